// round 7
// baseline (speedup 1.0000x reference)
#include <cuda_runtime.h>
#include <math.h>
#include <stdint.h>

#define D_MODEL 1024
#define N_HEADS 16
#define D_HEAD  64
#define D_FF    4096
#define BATCH   2
#define SEQ     2048
#define NTOK    (BATCH*SEQ)
#define D3      (3*D_MODEL)

// ---------------- scratch (no cudaMalloc allowed) ----------------
__device__ float g_h   [NTOK*D_MODEL];
__device__ float g_qkv [NTOK*D3];
__device__ float g_c   [NTOK*N_HEADS];
__device__ float g_ctx [NTOK*D_MODEL];
__device__ float g_x1  [NTOK*D_MODEL];
__device__ float g_h2  [NTOK*D_MODEL];
__device__ float g_ff  [NTOK*D_FF];
__device__ float g_wqkv[D_MODEL*D3];
__device__ float g_bqkv[D3];
__device__ float g_wo  [D_MODEL*D_MODEL];
__device__ float g_w1  [D_MODEL*D_FF];
__device__ float g_w2  [D_FF*D_MODEL];

__device__ __forceinline__ uint32_t f2tf32(float x) {
    uint32_t r;
    asm("cvt.rna.tf32.f32 %0, %1;" : "=r"(r) : "f"(x));
    return r;
}
__device__ __forceinline__ float ftf32(float x) {
    return __uint_as_float(f2tf32(x));
}
__device__ __forceinline__ void cp16(uint32_t dst, const void* src) {
    asm volatile("cp.async.cg.shared.global [%0], [%1], 16;" :: "r"(dst), "l"(src));
}
#define CP_COMMIT() asm volatile("cp.async.commit_group;")
#define CP_WAIT(n)  asm volatile("cp.async.wait_group %0;" :: "n"(n))

__device__ __forceinline__ void mma_tf32(float* c, const uint32_t* a,
                                         uint32_t b0, uint32_t b1) {
    asm volatile(
        "mma.sync.aligned.m16n8k8.row.col.f32.tf32.tf32.f32 "
        "{%0,%1,%2,%3}, {%4,%5,%6,%7}, {%8,%9}, {%0,%1,%2,%3};"
        : "+f"(c[0]), "+f"(c[1]), "+f"(c[2]), "+f"(c[3])
        : "r"(a[0]), "r"(a[1]), "r"(a[2]), "r"(a[3]), "r"(b0), "r"(b1));
}

__device__ __forceinline__ float gelu_exact(float x) {
    return 0.5f * x * (1.0f + erff(x * 0.70710678118654752f));
}

// ---------------- pack+round QKV weights: dst[k][s*1024+n] = tf32(ws[k][n]) ----------------
__global__ __launch_bounds__(256) void pack_qkv_kernel(
    const float* __restrict__ wq, const float* __restrict__ wk,
    const float* __restrict__ wv, float* __restrict__ dst)
{
    const float* srcs[3] = {wq, wk, wv};
    int total = 3 * D_MODEL * (D_MODEL / 4);        // float4 units
    for (int i = blockIdx.x * 256 + threadIdx.x; i < total; i += gridDim.x * 256) {
        int s   = i / (D_MODEL * (D_MODEL / 4));
        int rem = i - s * (D_MODEL * (D_MODEL / 4));
        int k   = rem >> 8;            // D_MODEL/4 = 256
        int n4  = rem & 255;
        float4 v = ((const float4*)srcs[s])[k * 256 + n4];
        v.x = ftf32(v.x); v.y = ftf32(v.y);
        v.z = ftf32(v.z); v.w = ftf32(v.w);
        ((float4*)dst)[k * (D3/4) + s * 256 + n4] = v;
    }
}

__global__ void pack_bias_kernel(
    const float* __restrict__ bq, const float* __restrict__ bk,
    const float* __restrict__ bv, float* __restrict__ dst)
{
    int tid = threadIdx.x;      // 768 threads
    int s = tid >> 8, n4 = tid & 255;
    const float* srcs[3] = {bq, bk, bv};
    ((float4*)dst)[s * 256 + n4] = ((const float4*)srcs[s])[n4];
}

// ---------------- tf32 rounding pass (grid-stride, ILP-4) ----------------
__global__ __launch_bounds__(256) void round_tf32_kernel(
    const float* __restrict__ src, float* __restrict__ dst, int n4)
{
    int stride = gridDim.x * 256;
    for (int i = blockIdx.x * 256 + threadIdx.x; i < n4; i += 4 * stride) {
        float4 v[4];
        int idx[4];
        #pragma unroll
        for (int u = 0; u < 4; u++) {
            idx[u] = i + u * stride;
            if (idx[u] < n4) v[u] = ((const float4*)src)[idx[u]];
        }
        #pragma unroll
        for (int u = 0; u < 4; u++) {
            if (idx[u] < n4) {
                v[u].x = ftf32(v[u].x); v[u].y = ftf32(v[u].y);
                v[u].z = ftf32(v[u].z); v[u].w = ftf32(v[u].w);
                ((float4*)dst)[idx[u]] = v[u];
            }
        }
    }
}

// ---------------- LayerNorm (tf32-rounded output) ----------------
__global__ __launch_bounds__(256) void ln_kernel(
    const float* __restrict__ x, const float* __restrict__ g,
    const float* __restrict__ b, float* __restrict__ out)
{
    int row = blockIdx.x;
    int tid = threadIdx.x;
    const float4* xr = (const float4*)(x + (size_t)row * D_MODEL);
    float4 v = xr[tid];
    float s  = v.x + v.y + v.z + v.w;
    float s2 = v.x*v.x + v.y*v.y + v.z*v.z + v.w*v.w;

    __shared__ float red[18];
    #pragma unroll
    for (int off = 16; off > 0; off >>= 1) {
        s  += __shfl_xor_sync(0xffffffffu, s,  off);
        s2 += __shfl_xor_sync(0xffffffffu, s2, off);
    }
    int w = tid >> 5, lane = tid & 31;
    if (lane == 0) { red[w] = s; red[8 + w] = s2; }
    __syncthreads();
    if (tid == 0) {
        float a = 0.f, c2 = 0.f;
        #pragma unroll
        for (int i = 0; i < 8; i++) { a += red[i]; c2 += red[8 + i]; }
        red[16] = a; red[17] = c2;
    }
    __syncthreads();
    float mu  = red[16] * (1.0f / D_MODEL);
    float var = red[17] * (1.0f / D_MODEL) - mu * mu;
    float inv = rsqrtf(var + 1e-5f);

    float4 gg = ((const float4*)g)[tid];
    float4 bb = ((const float4*)b)[tid];
    float4 o;
    o.x = ftf32((v.x - mu) * inv * gg.x + bb.x);
    o.y = ftf32((v.y - mu) * inv * gg.y + bb.y);
    o.z = ftf32((v.z - mu) * inv * gg.z + bb.z);
    o.w = ftf32((v.w - mu) * inv * gg.w + bb.w);
    ((float4*)(out + (size_t)row * D_MODEL))[tid] = o;
}

// ---------------- TF32 tensor-core GEMM, cp.async double-buffered ----------------
#define BM 128
#define BN 128
#define BK 32
#define AST 36
#define BST 136
#define ASZ (BM*AST)
#define BSZ (BK*BST)
#define GEMM_SMEM ((2*ASZ + 2*BSZ) * 4)

__global__ __launch_bounds__(256, 2) void gemm_tc(
    const float* __restrict__ A, const float* __restrict__ W,
    const float* __restrict__ bias, const float* __restrict__ resid,
    float* __restrict__ C, int M, int N, int K, int act, int rnd)
{
    extern __shared__ uint32_t dsm[];
    uint32_t* As = dsm;
    uint32_t* Bs = dsm + 2*ASZ;

    int tid  = threadIdx.x;
    int wid  = tid >> 5, lane = tid & 31;
    int warp_m = wid >> 2;
    int warp_n = wid & 3;
    int gid = lane >> 2, tig = lane & 3;
    int mb = blockIdx.y * BM, nb = blockIdx.x * BN;

    float acc[4][4][4];
    #pragma unroll
    for (int mt = 0; mt < 4; mt++)
        #pragma unroll
        for (int nt = 0; nt < 4; nt++)
            #pragma unroll
            for (int r = 0; r < 4; r++) acc[mt][nt][r] = 0.f;

    const float* a_gp[4];
    uint32_t a_dst[4];
    #pragma unroll
    for (int i = 0; i < 4; i++) {
        int idx = tid + i * 256;
        int m = idx >> 3;
        int kg = ((idx & 7) + 8 - (m & 7)) & 7;
        a_gp[i] = A + (size_t)(mb + m) * K + kg * 4;
        a_dst[i] = (uint32_t)__cvta_generic_to_shared(&As[m * AST + kg * 4]);
    }
    const float* b_gp[4];
    uint32_t b_dst[4];
    #pragma unroll
    for (int i = 0; i < 4; i++) {
        int idx = tid + i * 256;
        int k = idx >> 5, ng = idx & 31;
        b_gp[i] = W + (size_t)k * N + nb + ng * 4;
        b_dst[i] = (uint32_t)__cvta_generic_to_shared(&Bs[k * BST + ng * 4]);
    }

    int lm_row = ((lane >> 3) & 1) * 8 + (lane & 7);
    int lm_khalf = (lane >> 4);
    uint32_t lm_base[4];
    #pragma unroll
    for (int mt = 0; mt < 4; mt++) {
        int row = warp_m * 64 + mt * 16 + lm_row;
        lm_base[mt] = (uint32_t)__cvta_generic_to_shared(
            &As[row * AST + lm_khalf * 4]);
    }
    int bf_base = tig * BST + warp_n * 32 + gid;

    #pragma unroll
    for (int i = 0; i < 4; i++) cp16(a_dst[i], a_gp[i]);
    #pragma unroll
    for (int i = 0; i < 4; i++) cp16(b_dst[i], b_gp[i]);
    CP_COMMIT();

    int buf = 0;
    for (int k0 = 0; k0 < K; k0 += BK) {
        CP_WAIT(0);
        __syncthreads();
        if (k0 + BK < K) {
            int nbo = (buf ^ 1);
            #pragma unroll
            for (int i = 0; i < 4; i++)
                cp16(a_dst[i] + nbo * ASZ * 4, a_gp[i] + k0 + BK);
            #pragma unroll
            for (int i = 0; i < 4; i++)
                cp16(b_dst[i] + nbo * BSZ * 4, b_gp[i] + (size_t)(k0 + BK) * N);
            CP_COMMIT();
        }

        const uint32_t* Bb = Bs + buf * BSZ;
        uint32_t abuf_ofs = buf * ASZ * 4;
        #pragma unroll
        for (int ks = 0; ks < 4; ks++) {
            uint32_t af[4][4];
            #pragma unroll
            for (int mt = 0; mt < 4; mt++) {
                uint32_t saddr = lm_base[mt] + abuf_ofs + ks * 32;
                asm volatile(
                    "ldmatrix.sync.aligned.m8n8.x4.shared.b16 {%0,%1,%2,%3}, [%4];"
                    : "=r"(af[mt][0]), "=r"(af[mt][1]),
                      "=r"(af[mt][2]), "=r"(af[mt][3])
                    : "r"(saddr));
            }
            uint32_t bf[4][2];
            #pragma unroll
            for (int nt = 0; nt < 4; nt++) {
                bf[nt][0] = Bb[bf_base + ks * 8 * BST + nt * 8];
                bf[nt][1] = Bb[bf_base + (ks * 8 + 4) * BST + nt * 8];
            }
            #pragma unroll
            for (int mt = 0; mt < 4; mt++)
                #pragma unroll
                for (int nt = 0; nt < 4; nt++)
                    mma_tf32(acc[mt][nt], af[mt], bf[nt][0], bf[nt][1]);
        }
        buf ^= 1;
    }

    #pragma unroll
    for (int mt = 0; mt < 4; mt++) {
        int r0 = mb + warp_m * 64 + mt * 16 + gid;
        int r1 = r0 + 8;
        #pragma unroll
        for (int nt = 0; nt < 4; nt++) {
            int cc = nb + warp_n * 32 + nt * 8 + tig * 2;
            float b0 = bias[cc], b1 = bias[cc + 1];
            float v00 = acc[mt][nt][0] + b0, v01 = acc[mt][nt][1] + b1;
            float v10 = acc[mt][nt][2] + b0, v11 = acc[mt][nt][3] + b1;
            if (act == 1) {
                v00 = gelu_exact(v00); v01 = gelu_exact(v01);
                v10 = gelu_exact(v10); v11 = gelu_exact(v11);
            }
            size_t p0 = (size_t)r0 * N + cc;
            size_t p1 = (size_t)r1 * N + cc;
            if (resid) {
                float2 q0 = *(const float2*)(resid + p0);
                float2 q1 = *(const float2*)(resid + p1);
                v00 += q0.x; v01 += q0.y; v10 += q1.x; v11 += q1.y;
            }
            if (rnd) {
                v00 = ftf32(v00); v01 = ftf32(v01);
                v10 = ftf32(v10); v11 = ftf32(v11);
            }
            *(float2*)(C + p0) = make_float2(v00, v01);
            *(float2*)(C + p1) = make_float2(v10, v11);
        }
    }
}

// ---------------- forget gate ----------------
__global__ __launch_bounds__(256) void fgate_kernel(
    const float* __restrict__ h, const float* __restrict__ wf,
    const float* __restrict__ bf, float* __restrict__ logf)
{
    int t   = blockIdx.x;
    int tid = threadIdx.x;
    int hd  = tid >> 4;
    int ln  = tid & 15;
    const float* hr = h + (size_t)t * D_MODEL;
    float s = 0.f;
    #pragma unroll 8
    for (int k = ln; k < D_MODEL; k += 16)
        s = fmaf(hr[k], wf[(size_t)k * N_HEADS + hd], s);
    #pragma unroll
    for (int off = 8; off > 0; off >>= 1)
        s += __shfl_xor_sync(0xffffffffu, s, off);
    if (ln == 0) {
        float z = s + bf[hd];
        float ls = (z >= 0.f) ? -log1pf(expf(-z)) : (z - log1pf(expf(z)));
        logf[(size_t)t * N_HEADS + hd] = ls;
    }
}

// ---------------- cumsum per (b,h) ----------------
__global__ __launch_bounds__(256) void cumsum_kernel(float* __restrict__ c)
{
    int bh = blockIdx.x;
    int b  = bh >> 4, h = bh & 15;
    int tid = threadIdx.x;
    const int CHUNK = SEQ / 256;
    float vals[CHUNK];
    float run = 0.f;
    size_t base = (size_t)b * SEQ * N_HEADS + h;
    #pragma unroll
    for (int u = 0; u < CHUNK; u++) {
        run += c[base + (size_t)(tid * CHUNK + u) * N_HEADS];
        vals[u] = run;
    }
    __shared__ float tot[256];
    tot[tid] = run;
    __syncthreads();
    for (int off = 1; off < 256; off <<= 1) {
        float t = (tid >= off) ? tot[tid - off] : 0.f;
        __syncthreads();
        tot[tid] += t;
        __syncthreads();
    }
    float offs = tot[tid] - run;
    #pragma unroll
    for (int u = 0; u < CHUNK; u++)
        c[base + (size_t)(tid * CHUNK + u) * N_HEADS] = vals[u] + offs;
}

// ---------------- tensor-core flash attention: 128 q-rows, 8 warps ----------------
// QKV packed [tok][3072]; Q at +0, K at +1024, V at +2048 (all tf32-rounded).
// logits = (q.k)/8 - c_j  (c_i row-constant, dropped: softmax invariant)
#define KST 68
#define VST 72
#define PST 68
#define ATTN_SMEM ((64*KST + 64*VST + 128*PST + 64) * 4)

__global__ __launch_bounds__(256) void attn_tc(
    const float* __restrict__ QKV, const float* __restrict__ Cdec,
    float* __restrict__ Out)
{
    extern __shared__ float sm[];
    uint32_t* Ks = (uint32_t*)sm;            // [64][KST]
    uint32_t* Vs = Ks + 64 * KST;            // [64][VST]
    uint32_t* Ps = Vs + 64 * VST;            // [128][PST] (Q staging, then P)
    float*    cs = (float*)(Ps + 128 * PST); // [64]

    // descending work order: biggest q-tiles scheduled first
    int qtb = (int)gridDim.x - 1 - (int)blockIdx.x;
    int h = blockIdx.y, b = blockIdx.z;
    int tid = threadIdx.x, wid = tid >> 5, lane = tid & 31;
    int gid = lane >> 2, tig = lane & 3;
    size_t rowbase = (size_t)b * SEQ;
    int qbase = qtb * 128;
    int r0 = wid * 16 + gid;   // 0..127 (first of thread's two rows)

    // stage Q (128 rows x 64 cols) via cp.async into Ps
    const float* qg = QKV + (rowbase + qbase) * D3 + h * D_HEAD;
    #pragma unroll
    for (int i = 0; i < 8; i++) {
        int idx = tid + i * 256;
        int r = idx >> 4, c4 = idx & 15;
        cp16((uint32_t)__cvta_generic_to_shared(Ps + r * PST + c4 * 4),
             qg + (size_t)r * D3 + c4 * 4);
    }
    CP_COMMIT(); CP_WAIT(0);
    __syncthreads();

    uint32_t qf[8][4];
    #pragma unroll
    for (int ks = 0; ks < 8; ks++) {
        qf[ks][0] = Ps[(r0)     * PST + ks * 8 + tig];
        qf[ks][1] = Ps[(r0 + 8) * PST + ks * 8 + tig];
        qf[ks][2] = Ps[(r0)     * PST + ks * 8 + tig + 4];
        qf[ks][3] = Ps[(r0 + 8) * PST + ks * 8 + tig + 4];
    }

    float oacc[8][4];
    #pragma unroll
    for (int nt = 0; nt < 8; nt++)
        #pragma unroll
        for (int r = 0; r < 4; r++) oacc[nt][r] = 0.f;
    float mrow[2] = {-1e30f, -1e30f};
    float lrow[2] = {0.f, 0.f};

    const float* kg0 = QKV + rowbase * D3 + D_MODEL + h * D_HEAD;
    const float* vg0 = kg0 + D_MODEL;

    int ktmax = 2 * qtb + 1;
    for (int kt = 0; kt <= ktmax; kt++) {
        __syncthreads();     // prior Ks/Vs reads complete
        const float* kg = kg0 + (size_t)kt * 64 * D3;
        const float* vg = vg0 + (size_t)kt * 64 * D3;
        {
            int r_ = tid >> 4, c4 = tid & 15;
            #pragma unroll
            for (int i = 0; i < 4; i++) {
                int r = r_ + i * 16;
                cp16((uint32_t)__cvta_generic_to_shared(Ks + r * KST + c4 * 4),
                     kg + (size_t)r * D3 + c4 * 4);
                cp16((uint32_t)__cvta_generic_to_shared(Vs + r * VST + c4 * 4),
                     vg + (size_t)r * D3 + c4 * 4);
            }
        }
        CP_COMMIT();
        if (tid < 64)
            cs[tid] = Cdec[(rowbase + kt * 64 + tid) * N_HEADS + h];
        CP_WAIT(0);
        __syncthreads();

        // S = Q K^T
        float s[8][4];
        #pragma unroll
        for (int nt = 0; nt < 8; nt++)
            #pragma unroll
            for (int r = 0; r < 4; r++) s[nt][r] = 0.f;
        #pragma unroll
        for (int ks = 0; ks < 8; ks++) {
            #pragma unroll
            for (int nt = 0; nt < 8; nt++) {
                uint32_t b0 = Ks[(nt * 8 + gid) * KST + ks * 8 + tig];
                uint32_t b1 = Ks[(nt * 8 + gid) * KST + ks * 8 + tig + 4];
                mma_tf32(s[nt], qf[ks], b0, b1);
            }
        }

        // scale + decay + causal mask + online softmax
        int coff = kt * 64 - qbase;        // column offset rel. to q-tile base
        bool diag = (kt >= 2 * qtb);
        #pragma unroll
        for (int rr = 0; rr < 2; rr++) {
            int rloc = r0 + rr * 8;
            float mx = -1e30f;
            #pragma unroll
            for (int nt = 0; nt < 8; nt++) {
                #pragma unroll
                for (int q = 0; q < 2; q++) {
                    int col = nt * 8 + tig * 2 + q;
                    float val = s[nt][rr * 2 + q] * 0.125f - cs[col];
                    if (diag && (coff + col) > rloc) val = -1e30f;
                    s[nt][rr * 2 + q] = val;
                    mx = fmaxf(mx, val);
                }
            }
            mx = fmaxf(mx, __shfl_xor_sync(0xffffffffu, mx, 1));
            mx = fmaxf(mx, __shfl_xor_sync(0xffffffffu, mx, 2));
            float mnew = fmaxf(mrow[rr], mx);
            float sf = __expf(mrow[rr] - mnew);
            mrow[rr] = mnew;
            float rs = 0.f;
            #pragma unroll
            for (int nt = 0; nt < 8; nt++) {
                #pragma unroll
                for (int q = 0; q < 2; q++) {
                    float p = __expf(s[nt][rr * 2 + q] - mnew);
                    s[nt][rr * 2 + q] = p;
                    rs += p;
                }
            }
            rs += __shfl_xor_sync(0xffffffffu, rs, 1);
            rs += __shfl_xor_sync(0xffffffffu, rs, 2);
            lrow[rr] = lrow[rr] * sf + rs;
            #pragma unroll
            for (int nt = 0; nt < 8; nt++) {
                oacc[nt][rr * 2]     *= sf;
                oacc[nt][rr * 2 + 1] *= sf;
            }
        }

        // P -> smem (tf32), warp-private rows
        #pragma unroll
        for (int nt = 0; nt < 8; nt++) {
            uint2 p01 = make_uint2(f2tf32(s[nt][0]), f2tf32(s[nt][1]));
            *(uint2*)&Ps[(r0)     * PST + nt * 8 + tig * 2] = p01;
            uint2 p23 = make_uint2(f2tf32(s[nt][2]), f2tf32(s[nt][3]));
            *(uint2*)&Ps[(r0 + 8) * PST + nt * 8 + tig * 2] = p23;
        }
        __syncwarp();

        // O += P @ V
        #pragma unroll
        for (int ks = 0; ks < 8; ks++) {
            uint32_t af[4];
            af[0] = Ps[(r0)     * PST + ks * 8 + tig];
            af[1] = Ps[(r0 + 8) * PST + ks * 8 + tig];
            af[2] = Ps[(r0)     * PST + ks * 8 + tig + 4];
            af[3] = Ps[(r0 + 8) * PST + ks * 8 + tig + 4];
            #pragma unroll
            for (int nt = 0; nt < 8; nt++) {
                uint32_t b0 = Vs[(ks * 8 + tig)     * VST + nt * 8 + gid];
                uint32_t b1 = Vs[(ks * 8 + tig + 4) * VST + nt * 8 + gid];
                mma_tf32(oacc[nt], af, b0, b1);
            }
        }
    }

    float inv0 = 1.0f / lrow[0], inv1 = 1.0f / lrow[1];
    size_t row0 = rowbase + qbase + r0;
    #pragma unroll
    for (int nt = 0; nt < 8; nt++) {
        int col = h * D_HEAD + nt * 8 + tig * 2;
        *(float2*)(Out + row0 * D_MODEL + col) =
            make_float2(ftf32(oacc[nt][0] * inv0), ftf32(oacc[nt][1] * inv0));
        *(float2*)(Out + (row0 + 8) * D_MODEL + col) =
            make_float2(ftf32(oacc[nt][2] * inv1), ftf32(oacc[nt][3] * inv1));
    }
}

// ---------------- launcher ----------------
extern "C" void kernel_launch(void* const* d_in, const int* in_sizes, int n_in,
                              void* d_out, int out_size)
{
    const float* x    = (const float*)d_in[0];
    const float* ln1g = (const float*)d_in[1];
    const float* ln1b = (const float*)d_in[2];
    const float* wq   = (const float*)d_in[3];
    const float* bq   = (const float*)d_in[4];
    const float* wk   = (const float*)d_in[5];
    const float* bk   = (const float*)d_in[6];
    const float* wv   = (const float*)d_in[7];
    const float* bv   = (const float*)d_in[8];
    const float* wo   = (const float*)d_in[9];
    const float* bo   = (const float*)d_in[10];
    const float* wf   = (const float*)d_in[11];
    const float* bf   = (const float*)d_in[12];
    const float* ln2g = (const float*)d_in[13];
    const float* ln2b = (const float*)d_in[14];
    const float* w1   = (const float*)d_in[15];
    const float* b1   = (const float*)d_in[16];
    const float* w2   = (const float*)d_in[17];
    const float* b2   = (const float*)d_in[18];
    float* out = (float*)d_out;

    float *h, *qkv, *c, *ctx, *x1, *h2, *ff;
    float *rwqkv, *rbqkv, *rwo, *rw1, *rw2;
    cudaGetSymbolAddress((void**)&h,    g_h);
    cudaGetSymbolAddress((void**)&qkv,  g_qkv);
    cudaGetSymbolAddress((void**)&c,    g_c);
    cudaGetSymbolAddress((void**)&ctx,  g_ctx);
    cudaGetSymbolAddress((void**)&x1,   g_x1);
    cudaGetSymbolAddress((void**)&h2,   g_h2);
    cudaGetSymbolAddress((void**)&ff,   g_ff);
    cudaGetSymbolAddress((void**)&rwqkv,g_wqkv);
    cudaGetSymbolAddress((void**)&rbqkv,g_bqkv);
    cudaGetSymbolAddress((void**)&rwo,  g_wo);
    cudaGetSymbolAddress((void**)&rw1,  g_w1);
    cudaGetSymbolAddress((void**)&rw2,  g_w2);

    static int inited = 0;
    if (!inited) {
        cudaFuncSetAttribute(gemm_tc, cudaFuncAttributeMaxDynamicSharedMemorySize, GEMM_SMEM);
        cudaFuncSetAttribute(attn_tc, cudaFuncAttributeMaxDynamicSharedMemorySize, ATTN_SMEM);
        inited = 1;
    }

    // 0) pack+round weights (once per replay, memory-bound)
    pack_qkv_kernel<<<592, 256>>>(wq, wk, wv, rwqkv);
    pack_bias_kernel<<<1, 768>>>(bq, bk, bv, rbqkv);
    round_tf32_kernel<<<592, 256>>>(wo, rwo, D_MODEL*D_MODEL/4);
    round_tf32_kernel<<<592, 256>>>(w1, rw1, D_MODEL*D_FF/4);
    round_tf32_kernel<<<592, 256>>>(w2, rw2, D_FF*D_MODEL/4);

    // 1) LN1
    ln_kernel<<<NTOK, 256>>>(x, ln1g, ln1b, h);
    // 2) fused QKV projection
    gemm_tc<<<dim3(D3/BN, NTOK/BM), 256, GEMM_SMEM>>>(h, rwqkv, rbqkv, nullptr, qkv, NTOK, D3, D_MODEL, 0, 1);
    // 3) forget gate + cumulative log-decay
    fgate_kernel<<<NTOK, 256>>>(h, wf, bf, c);
    cumsum_kernel<<<BATCH * N_HEADS, 256>>>(c);
    // 4) attention (128-row q tiles, descending work order)
    attn_tc<<<dim3(SEQ/128, N_HEADS, BATCH), 256, ATTN_SMEM>>>(qkv, c, ctx);
    // 5) output proj + residual
    gemm_tc<<<dim3(D_MODEL/BN, NTOK/BM), 256, GEMM_SMEM>>>(ctx, rwo, bo, x, x1, NTOK, D_MODEL, D_MODEL, 0, 0);
    // 6) LN2
    ln_kernel<<<NTOK, 256>>>(x1, ln2g, ln2b, h2);
    // 7) FF up + GELU
    gemm_tc<<<dim3(D_FF/BN, NTOK/BM), 256, GEMM_SMEM>>>(h2, rw1, b1, nullptr, ff, NTOK, D_FF, D_MODEL, 1, 1);
    // 8) FF down + residual -> output
    gemm_tc<<<dim3(D_MODEL/BN, NTOK/BM), 256, GEMM_SMEM>>>(ff, rw2, b2, x1, out, NTOK, D_MODEL, D_FF, 0, 0);
}

// round 8
// speedup vs baseline: 1.4452x; 1.4452x over previous
#include <cuda_runtime.h>
#include <cuda_fp16.h>
#include <math.h>
#include <stdint.h>

#define D_MODEL 1024
#define N_HEADS 16
#define D_HEAD  64
#define D_FF    4096
#define BATCH   2
#define SEQ     2048
#define NTOK    (BATCH*SEQ)
#define D3      (3*D_MODEL)

// ---------------- scratch (no cudaMalloc allowed) ----------------
__device__ __half g_h   [NTOK*D_MODEL];
__device__ float  g_qkv [NTOK*D3];
__device__ float  g_c   [NTOK*N_HEADS];
__device__ __half g_ctx [NTOK*D_MODEL];
__device__ float  g_x1  [NTOK*D_MODEL];
__device__ __half g_h2  [NTOK*D_MODEL];
__device__ __half g_ff  [NTOK*D_FF];
// transposed fp16 weights, [N][K]
__device__ __half g_wqkvT[D3*D_MODEL];
__device__ float  g_bqkv [D3];
__device__ __half g_woT  [D_MODEL*D_MODEL];
__device__ __half g_w1T  [D_FF*D_MODEL];
__device__ __half g_w2T  [D_MODEL*D_FF];

__device__ __forceinline__ uint32_t f2tf32(float x) {
    uint32_t r;
    asm("cvt.rna.tf32.f32 %0, %1;" : "=r"(r) : "f"(x));
    return r;
}
__device__ __forceinline__ float ftf32(float x) {
    return __uint_as_float(f2tf32(x));
}
__device__ __forceinline__ void cp16(uint32_t dst, const void* src) {
    asm volatile("cp.async.cg.shared.global [%0], [%1], 16;" :: "r"(dst), "l"(src));
}
#define CP_COMMIT() asm volatile("cp.async.commit_group;")
#define CP_WAIT(n)  asm volatile("cp.async.wait_group %0;" :: "n"(n))

__device__ __forceinline__ void mma_tf32(float* c, const uint32_t* a,
                                         uint32_t b0, uint32_t b1) {
    asm volatile(
        "mma.sync.aligned.m16n8k8.row.col.f32.tf32.tf32.f32 "
        "{%0,%1,%2,%3}, {%4,%5,%6,%7}, {%8,%9}, {%0,%1,%2,%3};"
        : "+f"(c[0]), "+f"(c[1]), "+f"(c[2]), "+f"(c[3])
        : "r"(a[0]), "r"(a[1]), "r"(a[2]), "r"(a[3]), "r"(b0), "r"(b1));
}
__device__ __forceinline__ void mma_f16(float* c, const uint32_t* a,
                                        uint32_t b0, uint32_t b1) {
    asm volatile(
        "mma.sync.aligned.m16n8k16.row.col.f32.f16.f16.f32 "
        "{%0,%1,%2,%3}, {%4,%5,%6,%7}, {%8,%9}, {%0,%1,%2,%3};"
        : "+f"(c[0]), "+f"(c[1]), "+f"(c[2]), "+f"(c[3])
        : "r"(a[0]), "r"(a[1]), "r"(a[2]), "r"(a[3]), "r"(b0), "r"(b1));
}

__device__ __forceinline__ float gelu_exact(float x) {
    return 0.5f * x * (1.0f + erff(x * 0.70710678118654752f));
}

// ---------------- transpose + fp16: src[K][N] fp32 -> dst[N][K] fp16 ----------------
__global__ __launch_bounds__(256) void transp_half(
    const float* __restrict__ src, __half* __restrict__ dst, int K, int N)
{
    __shared__ float t[32][33];
    int kb = blockIdx.y * 32, nb = blockIdx.x * 32;
    int x = threadIdx.x & 31, y = threadIdx.x >> 5;   // 32 x 8
    #pragma unroll
    for (int i = 0; i < 32; i += 8)
        t[y + i][x] = src[(size_t)(kb + y + i) * N + nb + x];
    __syncthreads();
    #pragma unroll
    for (int i = 0; i < 32; i += 8)
        dst[(size_t)(nb + y + i) * K + kb + x] = __float2half_rn(t[x][y + i]);
}

__global__ void pack_bias_kernel(
    const float* __restrict__ bq, const float* __restrict__ bk,
    const float* __restrict__ bv, float* __restrict__ dst)
{
    int tid = threadIdx.x;      // 768 threads
    int s = tid >> 8, n4 = tid & 255;
    const float* srcs[3] = {bq, bk, bv};
    ((float4*)dst)[s * 256 + n4] = ((const float4*)srcs[s])[n4];
}

// ---------------- LayerNorm: fp32 in, fp16 out ----------------
__global__ __launch_bounds__(256) void ln_kernel(
    const float* __restrict__ x, const float* __restrict__ g,
    const float* __restrict__ b, __half* __restrict__ out)
{
    int row = blockIdx.x;
    int tid = threadIdx.x;
    const float4* xr = (const float4*)(x + (size_t)row * D_MODEL);
    float4 v = xr[tid];
    float s  = v.x + v.y + v.z + v.w;
    float s2 = v.x*v.x + v.y*v.y + v.z*v.z + v.w*v.w;

    __shared__ float red[18];
    #pragma unroll
    for (int off = 16; off > 0; off >>= 1) {
        s  += __shfl_xor_sync(0xffffffffu, s,  off);
        s2 += __shfl_xor_sync(0xffffffffu, s2, off);
    }
    int w = tid >> 5, lane = tid & 31;
    if (lane == 0) { red[w] = s; red[8 + w] = s2; }
    __syncthreads();
    if (tid == 0) {
        float a = 0.f, c2 = 0.f;
        #pragma unroll
        for (int i = 0; i < 8; i++) { a += red[i]; c2 += red[8 + i]; }
        red[16] = a; red[17] = c2;
    }
    __syncthreads();
    float mu  = red[16] * (1.0f / D_MODEL);
    float var = red[17] * (1.0f / D_MODEL) - mu * mu;
    float inv = rsqrtf(var + 1e-5f);

    float4 gg = ((const float4*)g)[tid];
    float4 bb = ((const float4*)b)[tid];
    __half2 o0 = __floats2half2_rn((v.x - mu) * inv * gg.x + bb.x,
                                   (v.y - mu) * inv * gg.y + bb.y);
    __half2 o1 = __floats2half2_rn((v.z - mu) * inv * gg.z + bb.z,
                                   (v.w - mu) * inv * gg.w + bb.w);
    __half2* op = (__half2*)(out + (size_t)row * D_MODEL) + tid * 2;
    op[0] = o0; op[1] = o1;
}

// ---------------- fp16 tensor-core GEMM, cp.async double-buffered ----------------
// A[M][K] fp16 row-major, Wt[N][K] fp16 (transposed weight). C = act(A@Wt^T + bias)(+resid).
// CTA 128x128, BK=64 halves, 8 warps 2x4, warp tile 64x32, mma m16n8k16.
#define AST2 72                     // halves per padded row
#define TILE2 (128*AST2)            // halves per tile
#define GEMM_SMEM (2*2*TILE2*2)     // A+B, double-buffered, 2B/half = 73728

__global__ __launch_bounds__(256, 2) void gemm_f16(
    const __half* __restrict__ A, const __half* __restrict__ Wt,
    const float* __restrict__ bias, const float* __restrict__ resid,
    void* __restrict__ Cv, int M, int N, int K, int act, int omode)
{
    extern __shared__ __half hsm[];
    __half* As = hsm;                   // 2 x [128][AST2]
    __half* Bs = hsm + 2 * TILE2;       // 2 x [128][AST2]

    int tid  = threadIdx.x;
    int wid  = tid >> 5, lane = tid & 31;
    int warp_m = wid >> 2;
    int warp_n = wid & 3;
    int gid = lane >> 2, tig = lane & 3;
    int mb = blockIdx.y * 128, nb = blockIdx.x * 128;

    float acc[4][4][4];
    #pragma unroll
    for (int mt = 0; mt < 4; mt++)
        #pragma unroll
        for (int nt = 0; nt < 4; nt++)
            #pragma unroll
            for (int r = 0; r < 4; r++) acc[mt][nt][r] = 0.f;

    // loads: 128 rows x 8 chunks of 16B per tile; 1024 slots / 256 thr = 4 each
    const __half* a_gp[4];
    const __half* b_gp[4];
    uint32_t a_dst[4], b_dst[4];
    #pragma unroll
    for (int i = 0; i < 4; i++) {
        int idx = tid + i * 256;
        int r = idx >> 3, g = idx & 7;
        a_gp[i] = A  + (size_t)(mb + r) * K + g * 8;
        b_gp[i] = Wt + (size_t)(nb + r) * K + g * 8;
        a_dst[i] = (uint32_t)__cvta_generic_to_shared(&As[r * AST2 + g * 8]);
        b_dst[i] = (uint32_t)__cvta_generic_to_shared(&Bs[r * AST2 + g * 8]);
    }

    // ldmatrix lane mapping (m16k16 A frag)
    int lm_row = ((lane >> 3) & 1) * 8 + (lane & 7);
    int lm_k8  = (lane >> 4);            // which 8-half k-group
    uint32_t lm_base[4];
    #pragma unroll
    for (int mt = 0; mt < 4; mt++) {
        int row = warp_m * 64 + mt * 16 + lm_row;
        lm_base[mt] = (uint32_t)__cvta_generic_to_shared(
            &As[row * AST2 + lm_k8 * 8]);
    }
    // B frag word base: word idx = n*36 + ks*8 + tig ; b1 at +4
    int n0 = warp_n * 32 + gid;

    #pragma unroll
    for (int i = 0; i < 4; i++) cp16(a_dst[i], a_gp[i]);
    #pragma unroll
    for (int i = 0; i < 4; i++) cp16(b_dst[i], b_gp[i]);
    CP_COMMIT();

    int nch = K >> 6;       // chunks of 64 halves
    int buf = 0;
    for (int c = 0; c < nch; c++) {
        CP_WAIT(0);
        __syncthreads();
        if (c + 1 < nch) {
            int nbo = buf ^ 1;
            int koff = (c + 1) * 64;
            #pragma unroll
            for (int i = 0; i < 4; i++)
                cp16(a_dst[i] + nbo * TILE2 * 2, a_gp[i] + koff);
            #pragma unroll
            for (int i = 0; i < 4; i++)
                cp16(b_dst[i] + nbo * TILE2 * 2, b_gp[i] + koff);
            CP_COMMIT();
        }

        const uint32_t* Bw = (const uint32_t*)(Bs + buf * TILE2);
        uint32_t abuf = buf * TILE2 * 2;
        #pragma unroll
        for (int ks = 0; ks < 4; ks++) {       // 4 x K=16
            uint32_t af[4][4];
            #pragma unroll
            for (int mt = 0; mt < 4; mt++) {
                uint32_t saddr = lm_base[mt] + abuf + ks * 32;   // 16 halves
                asm volatile(
                    "ldmatrix.sync.aligned.m8n8.x4.shared.b16 {%0,%1,%2,%3}, [%4];"
                    : "=r"(af[mt][0]), "=r"(af[mt][1]),
                      "=r"(af[mt][2]), "=r"(af[mt][3])
                    : "r"(saddr));
            }
            uint32_t bf[4][2];
            #pragma unroll
            for (int nt = 0; nt < 4; nt++) {
                int widx = (n0 + nt * 8) * 36 + ks * 8 + tig;
                bf[nt][0] = Bw[widx];
                bf[nt][1] = Bw[widx + 4];
            }
            #pragma unroll
            for (int mt = 0; mt < 4; mt++)
                #pragma unroll
                for (int nt = 0; nt < 4; nt++)
                    mma_f16(acc[mt][nt], af[mt], bf[nt][0], bf[nt][1]);
        }
        buf ^= 1;
    }

    // epilogue
    #pragma unroll
    for (int mt = 0; mt < 4; mt++) {
        int r0 = mb + warp_m * 64 + mt * 16 + gid;
        int r1 = r0 + 8;
        #pragma unroll
        for (int nt = 0; nt < 4; nt++) {
            int cc = nb + warp_n * 32 + nt * 8 + tig * 2;
            float b0 = bias[cc], b1 = bias[cc + 1];
            float v00 = acc[mt][nt][0] + b0, v01 = acc[mt][nt][1] + b1;
            float v10 = acc[mt][nt][2] + b0, v11 = acc[mt][nt][3] + b1;
            if (act == 1) {
                v00 = gelu_exact(v00); v01 = gelu_exact(v01);
                v10 = gelu_exact(v10); v11 = gelu_exact(v11);
            }
            size_t p0 = (size_t)r0 * N + cc;
            size_t p1 = (size_t)r1 * N + cc;
            if (resid) {
                float2 q0 = *(const float2*)(resid + p0);
                float2 q1 = *(const float2*)(resid + p1);
                v00 += q0.x; v01 += q0.y; v10 += q1.x; v11 += q1.y;
            }
            if (omode == 2) {          // fp16 out
                __half* Ch = (__half*)Cv;
                *(__half2*)(Ch + p0) = __floats2half2_rn(v00, v01);
                *(__half2*)(Ch + p1) = __floats2half2_rn(v10, v11);
            } else {
                if (omode == 1) {      // tf32-rounded fp32 (feeds attention)
                    v00 = ftf32(v00); v01 = ftf32(v01);
                    v10 = ftf32(v10); v11 = ftf32(v11);
                }
                float* Cf = (float*)Cv;
                *(float2*)(Cf + p0) = make_float2(v00, v01);
                *(float2*)(Cf + p1) = make_float2(v10, v11);
            }
        }
    }
}

// ---------------- forget gate (fp16 h input) ----------------
__global__ __launch_bounds__(256) void fgate_kernel(
    const __half* __restrict__ h, const float* __restrict__ wf,
    const float* __restrict__ bf, float* __restrict__ logf)
{
    int t   = blockIdx.x;
    int tid = threadIdx.x;
    int hd  = tid >> 4;
    int ln  = tid & 15;
    const __half* hr = h + (size_t)t * D_MODEL;
    float s = 0.f;
    #pragma unroll 8
    for (int k = ln; k < D_MODEL; k += 16)
        s = fmaf(__half2float(hr[k]), wf[(size_t)k * N_HEADS + hd], s);
    #pragma unroll
    for (int off = 8; off > 0; off >>= 1)
        s += __shfl_xor_sync(0xffffffffu, s, off);
    if (ln == 0) {
        float z = s + bf[hd];
        float ls = (z >= 0.f) ? -log1pf(expf(-z)) : (z - log1pf(expf(z)));
        logf[(size_t)t * N_HEADS + hd] = ls;
    }
}

// ---------------- cumsum per (b,h) ----------------
__global__ __launch_bounds__(256) void cumsum_kernel(float* __restrict__ c)
{
    int bh = blockIdx.x;
    int b  = bh >> 4, h = bh & 15;
    int tid = threadIdx.x;
    const int CHUNK = SEQ / 256;
    float vals[CHUNK];
    float run = 0.f;
    size_t base = (size_t)b * SEQ * N_HEADS + h;
    #pragma unroll
    for (int u = 0; u < CHUNK; u++) {
        run += c[base + (size_t)(tid * CHUNK + u) * N_HEADS];
        vals[u] = run;
    }
    __shared__ float tot[256];
    tot[tid] = run;
    __syncthreads();
    for (int off = 1; off < 256; off <<= 1) {
        float t = (tid >= off) ? tot[tid - off] : 0.f;
        __syncthreads();
        tot[tid] += t;
        __syncthreads();
    }
    float offs = tot[tid] - run;
    #pragma unroll
    for (int u = 0; u < CHUNK; u++)
        c[base + (size_t)(tid * CHUNK + u) * N_HEADS] = vals[u] + offs;
}

// ---------------- tf32 flash attention, double-buffered K/V (fp16 ctx out) ----------------
// QKV packed [tok][3072] fp32 tf32-rounded; Q at +0, K at +1024, V at +2048.
// logits = (q.k)/8 - c_j  (c_i row-constant, dropped: softmax invariant)
#define KST 68
#define VST 72
#define PST 68
#define KSZ (64*KST)
#define VSZ (64*VST)
#define ATTN_SMEM ((2*KSZ + 2*VSZ + 64*PST + 2*64) * 4)

__global__ __launch_bounds__(128) void attn_tc(
    const float* __restrict__ QKV, const float* __restrict__ Cdec,
    __half* __restrict__ Out)
{
    extern __shared__ float sm[];
    uint32_t* Ksb = (uint32_t*)sm;
    uint32_t* Vsb = Ksb + 2*KSZ;
    uint32_t* Ps  = Vsb + 2*VSZ;
    float*    csb = (float*)(Ps + 64*PST);

    int qt = blockIdx.x, h = blockIdx.y, b = blockIdx.z;
    int tid = threadIdx.x, wid = tid >> 5, lane = tid & 31;
    int gid = lane >> 2, tig = lane & 3;
    size_t rowbase = (size_t)b * SEQ;
    int qbase = qt * 64;
    int r0 = wid * 16 + gid;

    const float* qg = QKV + (rowbase + qbase) * D3 + h * D_HEAD;
    #pragma unroll
    for (int i = 0; i < 8; i++) {
        int idx = tid + i * 128;
        int r = idx >> 4, c4 = idx & 15;
        cp16((uint32_t)__cvta_generic_to_shared(Ps + r * PST + c4 * 4),
             qg + (size_t)r * D3 + c4 * 4);
    }
    CP_COMMIT();

    int ldr = tid >> 4, ldc4 = tid & 15;
    const float* kg0 = QKV + rowbase * D3 + D_MODEL + h * D_HEAD;
    const float* vg0 = kg0 + D_MODEL;
    {
        #pragma unroll
        for (int i = 0; i < 8; i++) {
            int r = ldr + i * 8;
            cp16((uint32_t)__cvta_generic_to_shared(Ksb + r * KST + ldc4 * 4),
                 kg0 + (size_t)r * D3 + ldc4 * 4);
            cp16((uint32_t)__cvta_generic_to_shared(Vsb + r * VST + ldc4 * 4),
                 vg0 + (size_t)r * D3 + ldc4 * 4);
        }
        if (tid < 64)
            csb[tid] = Cdec[(rowbase + tid) * N_HEADS + h];
    }
    CP_COMMIT();

    CP_WAIT(1);
    __syncthreads();

    uint32_t qf[8][4];
    #pragma unroll
    for (int ks = 0; ks < 8; ks++) {
        qf[ks][0] = Ps[(r0)     * PST + ks * 8 + tig];
        qf[ks][1] = Ps[(r0 + 8) * PST + ks * 8 + tig];
        qf[ks][2] = Ps[(r0)     * PST + ks * 8 + tig + 4];
        qf[ks][3] = Ps[(r0 + 8) * PST + ks * 8 + tig + 4];
    }

    float oacc[8][4];
    #pragma unroll
    for (int nt = 0; nt < 8; nt++)
        #pragma unroll
        for (int r = 0; r < 4; r++) oacc[nt][r] = 0.f;
    float mrow[2] = {-1e30f, -1e30f};
    float lrow[2] = {0.f, 0.f};

    int buf = 0;
    for (int kt = 0; kt <= qt; kt++) {
        CP_WAIT(0);
        __syncthreads();

        if (kt < qt) {
            int nb_ = buf ^ 1;
            const float* kg = kg0 + (size_t)(kt + 1) * 64 * D3;
            const float* vg = vg0 + (size_t)(kt + 1) * 64 * D3;
            uint32_t* Kd = Ksb + nb_ * KSZ;
            uint32_t* Vd = Vsb + nb_ * VSZ;
            #pragma unroll
            for (int i = 0; i < 8; i++) {
                int r = ldr + i * 8;
                cp16((uint32_t)__cvta_generic_to_shared(Kd + r * KST + ldc4 * 4),
                     kg + (size_t)r * D3 + ldc4 * 4);
                cp16((uint32_t)__cvta_generic_to_shared(Vd + r * VST + ldc4 * 4),
                     vg + (size_t)r * D3 + ldc4 * 4);
            }
            CP_COMMIT();
            if (tid < 64)
                csb[nb_ * 64 + tid] =
                    Cdec[(rowbase + (kt + 1) * 64 + tid) * N_HEADS + h];
        }

        const uint32_t* Ks = Ksb + buf * KSZ;
        const uint32_t* Vs = Vsb + buf * VSZ;
        const float*    cs = csb + buf * 64;

        float s[8][4];
        #pragma unroll
        for (int nt = 0; nt < 8; nt++)
            #pragma unroll
            for (int r = 0; r < 4; r++) s[nt][r] = 0.f;
        #pragma unroll
        for (int ks = 0; ks < 8; ks++) {
            #pragma unroll
            for (int nt = 0; nt < 8; nt++) {
                uint32_t b0 = Ks[(nt * 8 + gid) * KST + ks * 8 + tig];
                uint32_t b1 = Ks[(nt * 8 + gid) * KST + ks * 8 + tig + 4];
                mma_tf32(s[nt], qf[ks], b0, b1);
            }
        }

        #pragma unroll
        for (int rr = 0; rr < 2; rr++) {
            int rloc = r0 + rr * 8;
            float mx = -1e30f;
            #pragma unroll
            for (int nt = 0; nt < 8; nt++) {
                #pragma unroll
                for (int q = 0; q < 2; q++) {
                    int col = nt * 8 + tig * 2 + q;
                    float val = s[nt][rr * 2 + q] * 0.125f - cs[col];
                    if (kt == qt && col > rloc) val = -1e30f;
                    s[nt][rr * 2 + q] = val;
                    mx = fmaxf(mx, val);
                }
            }
            mx = fmaxf(mx, __shfl_xor_sync(0xffffffffu, mx, 1));
            mx = fmaxf(mx, __shfl_xor_sync(0xffffffffu, mx, 2));
            float mnew = fmaxf(mrow[rr], mx);
            float sf = __expf(mrow[rr] - mnew);
            mrow[rr] = mnew;
            float rs = 0.f;
            #pragma unroll
            for (int nt = 0; nt < 8; nt++) {
                #pragma unroll
                for (int q = 0; q < 2; q++) {
                    float p = __expf(s[nt][rr * 2 + q] - mnew);
                    s[nt][rr * 2 + q] = p;
                    rs += p;
                }
            }
            rs += __shfl_xor_sync(0xffffffffu, rs, 1);
            rs += __shfl_xor_sync(0xffffffffu, rs, 2);
            lrow[rr] = lrow[rr] * sf + rs;
            #pragma unroll
            for (int nt = 0; nt < 8; nt++) {
                oacc[nt][rr * 2]     *= sf;
                oacc[nt][rr * 2 + 1] *= sf;
            }
        }

        #pragma unroll
        for (int nt = 0; nt < 8; nt++) {
            uint2 p01 = make_uint2(f2tf32(s[nt][0]), f2tf32(s[nt][1]));
            *(uint2*)&Ps[(r0)     * PST + nt * 8 + tig * 2] = p01;
            uint2 p23 = make_uint2(f2tf32(s[nt][2]), f2tf32(s[nt][3]));
            *(uint2*)&Ps[(r0 + 8) * PST + nt * 8 + tig * 2] = p23;
        }
        __syncwarp();

        #pragma unroll
        for (int ks = 0; ks < 8; ks++) {
            uint32_t af[4];
            af[0] = Ps[(r0)     * PST + ks * 8 + tig];
            af[1] = Ps[(r0 + 8) * PST + ks * 8 + tig];
            af[2] = Ps[(r0)     * PST + ks * 8 + tig + 4];
            af[3] = Ps[(r0 + 8) * PST + ks * 8 + tig + 4];
            #pragma unroll
            for (int nt = 0; nt < 8; nt++) {
                uint32_t b0 = Vs[(ks * 8 + tig)     * VST + nt * 8 + gid];
                uint32_t b1 = Vs[(ks * 8 + tig + 4) * VST + nt * 8 + gid];
                mma_tf32(oacc[nt], af, b0, b1);
            }
        }
        buf ^= 1;
    }

    float inv0 = 1.0f / lrow[0], inv1 = 1.0f / lrow[1];
    size_t row0 = rowbase + qbase + r0;
    #pragma unroll
    for (int nt = 0; nt < 8; nt++) {
        int col = h * D_HEAD + nt * 8 + tig * 2;
        *(__half2*)(Out + row0 * D_MODEL + col) =
            __floats2half2_rn(oacc[nt][0] * inv0, oacc[nt][1] * inv0);
        *(__half2*)(Out + (row0 + 8) * D_MODEL + col) =
            __floats2half2_rn(oacc[nt][2] * inv1, oacc[nt][3] * inv1);
    }
}

// ---------------- launcher ----------------
extern "C" void kernel_launch(void* const* d_in, const int* in_sizes, int n_in,
                              void* d_out, int out_size)
{
    const float* x    = (const float*)d_in[0];
    const float* ln1g = (const float*)d_in[1];
    const float* ln1b = (const float*)d_in[2];
    const float* wq   = (const float*)d_in[3];
    const float* bq   = (const float*)d_in[4];
    const float* wk   = (const float*)d_in[5];
    const float* bk   = (const float*)d_in[6];
    const float* wv   = (const float*)d_in[7];
    const float* bv   = (const float*)d_in[8];
    const float* wo   = (const float*)d_in[9];
    const float* bo   = (const float*)d_in[10];
    const float* wf   = (const float*)d_in[11];
    const float* bf   = (const float*)d_in[12];
    const float* ln2g = (const float*)d_in[13];
    const float* ln2b = (const float*)d_in[14];
    const float* w1   = (const float*)d_in[15];
    const float* b1   = (const float*)d_in[16];
    const float* w2   = (const float*)d_in[17];
    const float* b2   = (const float*)d_in[18];
    float* out = (float*)d_out;

    __half *h, *ctx, *h2, *ff, *rwqkv, *rwo, *rw1, *rw2;
    float *qkv, *c, *x1, *rbqkv;
    cudaGetSymbolAddress((void**)&h,    g_h);
    cudaGetSymbolAddress((void**)&qkv,  g_qkv);
    cudaGetSymbolAddress((void**)&c,    g_c);
    cudaGetSymbolAddress((void**)&ctx,  g_ctx);
    cudaGetSymbolAddress((void**)&x1,   g_x1);
    cudaGetSymbolAddress((void**)&h2,   g_h2);
    cudaGetSymbolAddress((void**)&ff,   g_ff);
    cudaGetSymbolAddress((void**)&rwqkv,g_wqkvT);
    cudaGetSymbolAddress((void**)&rbqkv,g_bqkv);
    cudaGetSymbolAddress((void**)&rwo,  g_woT);
    cudaGetSymbolAddress((void**)&rw1,  g_w1T);
    cudaGetSymbolAddress((void**)&rw2,  g_w2T);

    static int inited = 0;
    if (!inited) {
        cudaFuncSetAttribute(gemm_f16, cudaFuncAttributeMaxDynamicSharedMemorySize, GEMM_SMEM);
        cudaFuncSetAttribute(attn_tc, cudaFuncAttributeMaxDynamicSharedMemorySize, ATTN_SMEM);
        inited = 1;
    }

    // 0) transpose + fp16 weights into [N][K]
    transp_half<<<dim3(32, 32),  256>>>(wq, rwqkv + 0*D_MODEL*D_MODEL, D_MODEL, D_MODEL);
    transp_half<<<dim3(32, 32),  256>>>(wk, rwqkv + 1*D_MODEL*D_MODEL, D_MODEL, D_MODEL);
    transp_half<<<dim3(32, 32),  256>>>(wv, rwqkv + 2*D_MODEL*D_MODEL, D_MODEL, D_MODEL);
    pack_bias_kernel<<<1, 768>>>(bq, bk, bv, rbqkv);
    transp_half<<<dim3(32, 32),  256>>>(wo, rwo, D_MODEL, D_MODEL);
    transp_half<<<dim3(128, 32), 256>>>(w1, rw1, D_MODEL, D_FF);
    transp_half<<<dim3(32, 128), 256>>>(w2, rw2, D_FF, D_MODEL);

    // 1) LN1 -> h fp16
    ln_kernel<<<NTOK, 256>>>(x, ln1g, ln1b, h);
    // 2) fused QKV projection (fp16 mma, tf32-rounded fp32 out)
    gemm_f16<<<dim3(D3/128, NTOK/128), 256, GEMM_SMEM>>>(h, rwqkv, rbqkv, nullptr, qkv, NTOK, D3, D_MODEL, 0, 1);
    // 3) forget gate + cumulative log-decay
    fgate_kernel<<<NTOK, 256>>>(h, wf, bf, c);
    cumsum_kernel<<<BATCH * N_HEADS, 256>>>(c);
    // 4) attention (tf32) -> ctx fp16
    attn_tc<<<dim3(SEQ/64, N_HEADS, BATCH), 128, ATTN_SMEM>>>(qkv, c, ctx);
    // 5) output proj + residual -> x1 fp32
    gemm_f16<<<dim3(D_MODEL/128, NTOK/128), 256, GEMM_SMEM>>>(ctx, rwo, bo, x, x1, NTOK, D_MODEL, D_MODEL, 0, 0);
    // 6) LN2 -> h2 fp16
    ln_kernel<<<NTOK, 256>>>(x1, ln2g, ln2b, h2);
    // 7) FF up + GELU -> ff fp16
    gemm_f16<<<dim3(D_FF/128, NTOK/128), 256, GEMM_SMEM>>>(h2, rw1, b1, nullptr, ff, NTOK, D_FF, D_MODEL, 1, 2);
    // 8) FF down + residual -> out fp32
    gemm_f16<<<dim3(D_MODEL/128, NTOK/128), 256, GEMM_SMEM>>>(ff, rw2, b2, x1, out, NTOK, D_MODEL, D_FF, 0, 0);
}

// round 9
// speedup vs baseline: 1.6781x; 1.1612x over previous
#include <cuda_runtime.h>
#include <cuda_fp16.h>
#include <math.h>
#include <stdint.h>

#define D_MODEL 1024
#define N_HEADS 16
#define D_HEAD  64
#define D_FF    4096
#define BATCH   2
#define SEQ     2048
#define NTOK    (BATCH*SEQ)
#define D3      (3*D_MODEL)

// ---------------- scratch (no cudaMalloc allowed) ----------------
__device__ __half g_h   [NTOK*D_MODEL];
__device__ __half g_qkv [NTOK*D3];
__device__ float  g_c   [NTOK*N_HEADS];
__device__ __half g_ctx [NTOK*D_MODEL];
__device__ float  g_x1  [NTOK*D_MODEL];
__device__ __half g_h2  [NTOK*D_MODEL];
__device__ __half g_ff  [NTOK*D_FF];
// transposed fp16 weights, [N][K]
__device__ __half g_wqkvT[D3*D_MODEL];
__device__ float  g_bqkv [D3];
__device__ __half g_woT  [D_MODEL*D_MODEL];
__device__ __half g_w1T  [D_FF*D_MODEL];
__device__ __half g_w2T  [D_MODEL*D_FF];

__device__ __forceinline__ void cp16(uint32_t dst, const void* src) {
    asm volatile("cp.async.cg.shared.global [%0], [%1], 16;" :: "r"(dst), "l"(src));
}
#define CP_COMMIT() asm volatile("cp.async.commit_group;")
#define CP_WAIT(n)  asm volatile("cp.async.wait_group %0;" :: "n"(n))

__device__ __forceinline__ void mma_f16(float* c, const uint32_t* a,
                                        uint32_t b0, uint32_t b1) {
    asm volatile(
        "mma.sync.aligned.m16n8k16.row.col.f32.f16.f16.f32 "
        "{%0,%1,%2,%3}, {%4,%5,%6,%7}, {%8,%9}, {%0,%1,%2,%3};"
        : "+f"(c[0]), "+f"(c[1]), "+f"(c[2]), "+f"(c[3])
        : "r"(a[0]), "r"(a[1]), "r"(a[2]), "r"(a[3]), "r"(b0), "r"(b1));
}
__device__ __forceinline__ void ldsm_x4(uint32_t* r, uint32_t addr) {
    asm volatile(
        "ldmatrix.sync.aligned.m8n8.x4.shared.b16 {%0,%1,%2,%3}, [%4];"
        : "=r"(r[0]), "=r"(r[1]), "=r"(r[2]), "=r"(r[3]) : "r"(addr));
}
__device__ __forceinline__ void ldsm_x4_t(uint32_t* r, uint32_t addr) {
    asm volatile(
        "ldmatrix.sync.aligned.m8n8.x4.trans.shared.b16 {%0,%1,%2,%3}, [%4];"
        : "=r"(r[0]), "=r"(r[1]), "=r"(r[2]), "=r"(r[3]) : "r"(addr));
}

__device__ __forceinline__ float gelu_exact(float x) {
    return 0.5f * x * (1.0f + erff(x * 0.70710678118654752f));
}

// ---------------- transpose + fp16: src[K][N] fp32 -> dst[N][K] fp16 ----------------
__global__ __launch_bounds__(256) void transp_half(
    const float* __restrict__ src, __half* __restrict__ dst, int K, int N)
{
    __shared__ float t[32][33];
    int kb = blockIdx.y * 32, nb = blockIdx.x * 32;
    int x = threadIdx.x & 31, y = threadIdx.x >> 5;   // 32 x 8
    #pragma unroll
    for (int i = 0; i < 32; i += 8)
        t[y + i][x] = src[(size_t)(kb + y + i) * N + nb + x];
    __syncthreads();
    #pragma unroll
    for (int i = 0; i < 32; i += 8)
        dst[(size_t)(nb + y + i) * K + kb + x] = __float2half_rn(t[x][y + i]);
}

__global__ void pack_bias_kernel(
    const float* __restrict__ bq, const float* __restrict__ bk,
    const float* __restrict__ bv, float* __restrict__ dst)
{
    int tid = threadIdx.x;      // 768 threads
    int s = tid >> 8, n4 = tid & 255;
    const float* srcs[3] = {bq, bk, bv};
    ((float4*)dst)[s * 256 + n4] = ((const float4*)srcs[s])[n4];
}

// ---------------- LayerNorm: fp32 in, fp16 out ----------------
__global__ __launch_bounds__(256) void ln_kernel(
    const float* __restrict__ x, const float* __restrict__ g,
    const float* __restrict__ b, __half* __restrict__ out)
{
    int row = blockIdx.x;
    int tid = threadIdx.x;
    const float4* xr = (const float4*)(x + (size_t)row * D_MODEL);
    float4 v = xr[tid];
    float s  = v.x + v.y + v.z + v.w;
    float s2 = v.x*v.x + v.y*v.y + v.z*v.z + v.w*v.w;

    __shared__ float red[18];
    #pragma unroll
    for (int off = 16; off > 0; off >>= 1) {
        s  += __shfl_xor_sync(0xffffffffu, s,  off);
        s2 += __shfl_xor_sync(0xffffffffu, s2, off);
    }
    int w = tid >> 5, lane = tid & 31;
    if (lane == 0) { red[w] = s; red[8 + w] = s2; }
    __syncthreads();
    if (tid == 0) {
        float a = 0.f, c2 = 0.f;
        #pragma unroll
        for (int i = 0; i < 8; i++) { a += red[i]; c2 += red[8 + i]; }
        red[16] = a; red[17] = c2;
    }
    __syncthreads();
    float mu  = red[16] * (1.0f / D_MODEL);
    float var = red[17] * (1.0f / D_MODEL) - mu * mu;
    float inv = rsqrtf(var + 1e-5f);

    float4 gg = ((const float4*)g)[tid];
    float4 bb = ((const float4*)b)[tid];
    __half2 o0 = __floats2half2_rn((v.x - mu) * inv * gg.x + bb.x,
                                   (v.y - mu) * inv * gg.y + bb.y);
    __half2 o1 = __floats2half2_rn((v.z - mu) * inv * gg.z + bb.z,
                                   (v.w - mu) * inv * gg.w + bb.w);
    __half2* op = (__half2*)(out + (size_t)row * D_MODEL) + tid * 2;
    op[0] = o0; op[1] = o1;
}

// ---------------- fp16 tensor-core GEMM, cp.async double-buffered ----------------
#define AST2 72
#define TILE2 (128*AST2)
#define GEMM_SMEM (2*2*TILE2*2)

__global__ __launch_bounds__(256, 2) void gemm_f16(
    const __half* __restrict__ A, const __half* __restrict__ Wt,
    const float* __restrict__ bias, const float* __restrict__ resid,
    void* __restrict__ Cv, int M, int N, int K, int act, int omode)
{
    extern __shared__ __half hsm[];
    __half* As = hsm;
    __half* Bs = hsm + 2 * TILE2;

    int tid  = threadIdx.x;
    int wid  = tid >> 5, lane = tid & 31;
    int warp_m = wid >> 2;
    int warp_n = wid & 3;
    int gid = lane >> 2, tig = lane & 3;
    int mb = blockIdx.y * 128, nb = blockIdx.x * 128;

    float acc[4][4][4];
    #pragma unroll
    for (int mt = 0; mt < 4; mt++)
        #pragma unroll
        for (int nt = 0; nt < 4; nt++)
            #pragma unroll
            for (int r = 0; r < 4; r++) acc[mt][nt][r] = 0.f;

    const __half* a_gp[4];
    const __half* b_gp[4];
    uint32_t a_dst[4], b_dst[4];
    #pragma unroll
    for (int i = 0; i < 4; i++) {
        int idx = tid + i * 256;
        int r = idx >> 3, g = idx & 7;
        a_gp[i] = A  + (size_t)(mb + r) * K + g * 8;
        b_gp[i] = Wt + (size_t)(nb + r) * K + g * 8;
        a_dst[i] = (uint32_t)__cvta_generic_to_shared(&As[r * AST2 + g * 8]);
        b_dst[i] = (uint32_t)__cvta_generic_to_shared(&Bs[r * AST2 + g * 8]);
    }

    int lm_row = ((lane >> 3) & 1) * 8 + (lane & 7);
    int lm_k8  = (lane >> 4);
    uint32_t lm_base[4];
    #pragma unroll
    for (int mt = 0; mt < 4; mt++) {
        int row = warp_m * 64 + mt * 16 + lm_row;
        lm_base[mt] = (uint32_t)__cvta_generic_to_shared(
            &As[row * AST2 + lm_k8 * 8]);
    }
    int n0 = warp_n * 32 + gid;

    #pragma unroll
    for (int i = 0; i < 4; i++) cp16(a_dst[i], a_gp[i]);
    #pragma unroll
    for (int i = 0; i < 4; i++) cp16(b_dst[i], b_gp[i]);
    CP_COMMIT();

    int nch = K >> 6;
    int buf = 0;
    for (int c = 0; c < nch; c++) {
        CP_WAIT(0);
        __syncthreads();
        if (c + 1 < nch) {
            int nbo = buf ^ 1;
            int koff = (c + 1) * 64;
            #pragma unroll
            for (int i = 0; i < 4; i++)
                cp16(a_dst[i] + nbo * TILE2 * 2, a_gp[i] + koff);
            #pragma unroll
            for (int i = 0; i < 4; i++)
                cp16(b_dst[i] + nbo * TILE2 * 2, b_gp[i] + koff);
            CP_COMMIT();
        }

        const uint32_t* Bw = (const uint32_t*)(Bs + buf * TILE2);
        uint32_t abuf = buf * TILE2 * 2;
        #pragma unroll
        for (int ks = 0; ks < 4; ks++) {
            uint32_t af[4][4];
            #pragma unroll
            for (int mt = 0; mt < 4; mt++) {
                uint32_t saddr = lm_base[mt] + abuf + ks * 32;
                ldsm_x4(af[mt], saddr);
            }
            uint32_t bf[4][2];
            #pragma unroll
            for (int nt = 0; nt < 4; nt++) {
                int widx = (n0 + nt * 8) * 36 + ks * 8 + tig;
                bf[nt][0] = Bw[widx];
                bf[nt][1] = Bw[widx + 4];
            }
            #pragma unroll
            for (int mt = 0; mt < 4; mt++)
                #pragma unroll
                for (int nt = 0; nt < 4; nt++)
                    mma_f16(acc[mt][nt], af[mt], bf[nt][0], bf[nt][1]);
        }
        buf ^= 1;
    }

    #pragma unroll
    for (int mt = 0; mt < 4; mt++) {
        int r0 = mb + warp_m * 64 + mt * 16 + gid;
        int r1 = r0 + 8;
        #pragma unroll
        for (int nt = 0; nt < 4; nt++) {
            int cc = nb + warp_n * 32 + nt * 8 + tig * 2;
            float b0 = bias[cc], b1 = bias[cc + 1];
            float v00 = acc[mt][nt][0] + b0, v01 = acc[mt][nt][1] + b1;
            float v10 = acc[mt][nt][2] + b0, v11 = acc[mt][nt][3] + b1;
            if (act == 1) {
                v00 = gelu_exact(v00); v01 = gelu_exact(v01);
                v10 = gelu_exact(v10); v11 = gelu_exact(v11);
            }
            size_t p0 = (size_t)r0 * N + cc;
            size_t p1 = (size_t)r1 * N + cc;
            if (resid) {
                float2 q0 = *(const float2*)(resid + p0);
                float2 q1 = *(const float2*)(resid + p1);
                v00 += q0.x; v01 += q0.y; v10 += q1.x; v11 += q1.y;
            }
            if (omode == 2) {          // fp16 out
                __half* Ch = (__half*)Cv;
                *(__half2*)(Ch + p0) = __floats2half2_rn(v00, v01);
                *(__half2*)(Ch + p1) = __floats2half2_rn(v10, v11);
            } else {                   // fp32 out
                float* Cf = (float*)Cv;
                *(float2*)(Cf + p0) = make_float2(v00, v01);
                *(float2*)(Cf + p1) = make_float2(v10, v11);
            }
        }
    }
}

// ---------------- forget gate (fp16 h input) ----------------
__global__ __launch_bounds__(256) void fgate_kernel(
    const __half* __restrict__ h, const float* __restrict__ wf,
    const float* __restrict__ bf, float* __restrict__ logf)
{
    int t   = blockIdx.x;
    int tid = threadIdx.x;
    int hd  = tid >> 4;
    int ln  = tid & 15;
    const __half* hr = h + (size_t)t * D_MODEL;
    float s = 0.f;
    #pragma unroll 8
    for (int k = ln; k < D_MODEL; k += 16)
        s = fmaf(__half2float(hr[k]), wf[(size_t)k * N_HEADS + hd], s);
    #pragma unroll
    for (int off = 8; off > 0; off >>= 1)
        s += __shfl_xor_sync(0xffffffffu, s, off);
    if (ln == 0) {
        float z = s + bf[hd];
        float ls = (z >= 0.f) ? -log1pf(expf(-z)) : (z - log1pf(expf(z)));
        logf[(size_t)t * N_HEADS + hd] = ls;
    }
}

// ---------------- cumsum per (b,h) ----------------
__global__ __launch_bounds__(256) void cumsum_kernel(float* __restrict__ c)
{
    int bh = blockIdx.x;
    int b  = bh >> 4, h = bh & 15;
    int tid = threadIdx.x;
    const int CHUNK = SEQ / 256;
    float vals[CHUNK];
    float run = 0.f;
    size_t base = (size_t)b * SEQ * N_HEADS + h;
    #pragma unroll
    for (int u = 0; u < CHUNK; u++) {
        run += c[base + (size_t)(tid * CHUNK + u) * N_HEADS];
        vals[u] = run;
    }
    __shared__ float tot[256];
    tot[tid] = run;
    __syncthreads();
    for (int off = 1; off < 256; off <<= 1) {
        float t = (tid >= off) ? tot[tid - off] : 0.f;
        __syncthreads();
        tot[tid] += t;
        __syncthreads();
    }
    float offs = tot[tid] - run;
    #pragma unroll
    for (int u = 0; u < CHUNK; u++)
        c[base + (size_t)(tid * CHUNK + u) * N_HEADS] = vals[u] + offs;
}

// ---------------- fp16 tensor-core flash attention, double-buffered K/V ----------------
// QKV fp16 packed [tok][3072]; Q at +0, K at +1024, V at +2048.
// logits = (q.k)/8 - c_j  (c_i row-constant, dropped: softmax invariant)
// Tiles: Q/P [64][72] halves, K/V 2x[64][72] halves. mma m16n8k16.
#define HTILE (64*72)
#define ATTN_SMEM (5*HTILE*2 + 2*64*4)

__global__ __launch_bounds__(128) void attn_f16(
    const __half* __restrict__ QKV, const float* __restrict__ Cdec,
    __half* __restrict__ Out)
{
    extern __shared__ __half hsm[];
    __half* Ksb = hsm;                  // 2 x [64][72]
    __half* Vsb = hsm + 2 * HTILE;      // 2 x [64][72]
    __half* Ps  = hsm + 4 * HTILE;      // [64][72]  (Q staging, then P)
    float*  csb = (float*)(hsm + 5 * HTILE);   // 2 x [64]

    int qt = blockIdx.x, h = blockIdx.y, b = blockIdx.z;
    int tid = threadIdx.x, wid = tid >> 5, lane = tid & 31;
    int gid = lane >> 2, tig = lane & 3;
    size_t rowbase = (size_t)b * SEQ;
    int qbase = qt * 64;
    int r0 = wid * 16 + gid;

    uint32_t Ps_u = (uint32_t)__cvta_generic_to_shared(Ps);
    uint32_t Ks_u = (uint32_t)__cvta_generic_to_shared(Ksb);
    uint32_t Vs_u = (uint32_t)__cvta_generic_to_shared(Vsb);

    // stage Q (64 rows x 64 halves = 512 x 16B chunks / 128 thr = 4 each)
    const __half* qg = QKV + (rowbase + qbase) * D3 + h * D_HEAD;
    #pragma unroll
    for (int i = 0; i < 4; i++) {
        int idx = tid + i * 128;
        int r = idx >> 3, g = idx & 7;
        cp16(Ps_u + r * 144 + g * 16, qg + (size_t)r * D3 + g * 8);
    }
    CP_COMMIT();

    // K/V tile 0
    const __half* kg0 = QKV + rowbase * D3 + D_MODEL + h * D_HEAD;
    const __half* vg0 = kg0 + D_MODEL;
    #pragma unroll
    for (int i = 0; i < 4; i++) {
        int idx = tid + i * 128;
        int r = idx >> 3, g = idx & 7;
        cp16(Ks_u + r * 144 + g * 16, kg0 + (size_t)r * D3 + g * 8);
        cp16(Vs_u + r * 144 + g * 16, vg0 + (size_t)r * D3 + g * 8);
    }
    if (tid < 64)
        csb[tid] = Cdec[(rowbase + tid) * N_HEADS + h];
    CP_COMMIT();

    CP_WAIT(1);            // Q staged
    __syncthreads();

    // hoist Q fragments (4 k-steps of 16)
    int lm_row = ((lane >> 3) & 1) * 8 + (lane & 7);
    int lm_k8  = (lane >> 4);
    uint32_t qp_base = Ps_u + (wid * 16 + lm_row) * 144 + lm_k8 * 16;
    uint32_t qf[4][4];
    #pragma unroll
    for (int ks = 0; ks < 4; ks++) ldsm_x4(qf[ks], qp_base + ks * 32);

    // V trans-ldmatrix lane mapping
    int v_row = ((lane >> 3) & 1) * 8 + (lane & 7);
    int v_sel = (lane >> 4);

    float oacc[8][4];
    #pragma unroll
    for (int nt = 0; nt < 8; nt++)
        #pragma unroll
        for (int r = 0; r < 4; r++) oacc[nt][r] = 0.f;
    float mrow[2] = {-1e30f, -1e30f};
    float lrow[2] = {0.f, 0.f};

    int buf = 0;
    for (int kt = 0; kt <= qt; kt++) {
        CP_WAIT(0);
        __syncthreads();

        if (kt < qt) {     // prefetch tile kt+1
            int nb_ = buf ^ 1;
            const __half* kg = kg0 + (size_t)(kt + 1) * 64 * D3;
            const __half* vg = vg0 + (size_t)(kt + 1) * 64 * D3;
            uint32_t Kd = Ks_u + nb_ * HTILE * 2;
            uint32_t Vd = Vs_u + nb_ * HTILE * 2;
            #pragma unroll
            for (int i = 0; i < 4; i++) {
                int idx = tid + i * 128;
                int r = idx >> 3, g = idx & 7;
                cp16(Kd + r * 144 + g * 16, kg + (size_t)r * D3 + g * 8);
                cp16(Vd + r * 144 + g * 16, vg + (size_t)r * D3 + g * 8);
            }
            CP_COMMIT();
            if (tid < 64)
                csb[nb_ * 64 + tid] =
                    Cdec[(rowbase + (kt + 1) * 64 + tid) * N_HEADS + h];
        }

        const uint32_t* Kw = (const uint32_t*)(Ksb + buf * HTILE);
        uint32_t Vs_b = Vs_u + buf * HTILE * 2;
        const float* cs = csb + buf * 64;

        // S = Q K^T   (K B-frags: direct word reads from [key][dim])
        float s[8][4];
        #pragma unroll
        for (int nt = 0; nt < 8; nt++)
            #pragma unroll
            for (int r = 0; r < 4; r++) s[nt][r] = 0.f;
        #pragma unroll
        for (int ks = 0; ks < 4; ks++) {
            #pragma unroll
            for (int nt = 0; nt < 8; nt++) {
                int widx = (nt * 8 + gid) * 36 + ks * 8 + tig;
                mma_f16(s[nt], qf[ks], Kw[widx], Kw[widx + 4]);
            }
        }

        // scale + decay + mask + online softmax
        #pragma unroll
        for (int rr = 0; rr < 2; rr++) {
            int rloc = r0 + rr * 8;
            float mx = -1e30f;
            #pragma unroll
            for (int nt = 0; nt < 8; nt++) {
                #pragma unroll
                for (int q = 0; q < 2; q++) {
                    int col = nt * 8 + tig * 2 + q;
                    float val = s[nt][rr * 2 + q] * 0.125f - cs[col];
                    if (kt == qt && col > rloc) val = -1e30f;
                    s[nt][rr * 2 + q] = val;
                    mx = fmaxf(mx, val);
                }
            }
            mx = fmaxf(mx, __shfl_xor_sync(0xffffffffu, mx, 1));
            mx = fmaxf(mx, __shfl_xor_sync(0xffffffffu, mx, 2));
            float mnew = fmaxf(mrow[rr], mx);
            float sf = __expf(mrow[rr] - mnew);
            mrow[rr] = mnew;
            float rs = 0.f;
            #pragma unroll
            for (int nt = 0; nt < 8; nt++) {
                #pragma unroll
                for (int q = 0; q < 2; q++) {
                    float p = __expf(s[nt][rr * 2 + q] - mnew);
                    s[nt][rr * 2 + q] = p;
                    rs += p;
                }
            }
            rs += __shfl_xor_sync(0xffffffffu, rs, 1);
            rs += __shfl_xor_sync(0xffffffffu, rs, 2);
            lrow[rr] = lrow[rr] * sf + rs;
            #pragma unroll
            for (int nt = 0; nt < 8; nt++) {
                oacc[nt][rr * 2]     *= sf;
                oacc[nt][rr * 2 + 1] *= sf;
            }
        }

        // P -> smem fp16, warp-private rows
        uint32_t* Pw = (uint32_t*)Ps;
        #pragma unroll
        for (int nt = 0; nt < 8; nt++) {
            Pw[(r0)     * 36 + nt * 4 + tig] =
                __half2_raw(__floats2half2_rn(s[nt][0], s[nt][1])).x |
                ((uint32_t)__half2_raw(__floats2half2_rn(s[nt][0], s[nt][1])).y << 16);
            Pw[(r0 + 8) * 36 + nt * 4 + tig] =
                __half2_raw(__floats2half2_rn(s[nt][2], s[nt][3])).x |
                ((uint32_t)__half2_raw(__floats2half2_rn(s[nt][2], s[nt][3])).y << 16);
        }
        __syncwarp();

        // O += P @ V   (P A-frags via ldmatrix, V B-frags via ldmatrix.trans)
        #pragma unroll
        for (int ks = 0; ks < 4; ks++) {
            uint32_t pf[4];
            ldsm_x4(pf, qp_base + ks * 32);
            #pragma unroll
            for (int j = 0; j < 4; j++) {
                uint32_t vf[4];
                ldsm_x4_t(vf, Vs_b + (ks * 16 + v_row) * 144 + (2 * j + v_sel) * 16);
                mma_f16(oacc[2 * j],     pf, vf[0], vf[1]);
                mma_f16(oacc[2 * j + 1], pf, vf[2], vf[3]);
            }
        }
        buf ^= 1;
    }

    float inv0 = 1.0f / lrow[0], inv1 = 1.0f / lrow[1];
    size_t row0 = rowbase + qbase + r0;
    #pragma unroll
    for (int nt = 0; nt < 8; nt++) {
        int col = h * D_HEAD + nt * 8 + tig * 2;
        *(__half2*)(Out + row0 * D_MODEL + col) =
            __floats2half2_rn(oacc[nt][0] * inv0, oacc[nt][1] * inv0);
        *(__half2*)(Out + (row0 + 8) * D_MODEL + col) =
            __floats2half2_rn(oacc[nt][2] * inv1, oacc[nt][3] * inv1);
    }
}

// ---------------- launcher ----------------
extern "C" void kernel_launch(void* const* d_in, const int* in_sizes, int n_in,
                              void* d_out, int out_size)
{
    const float* x    = (const float*)d_in[0];
    const float* ln1g = (const float*)d_in[1];
    const float* ln1b = (const float*)d_in[2];
    const float* wq   = (const float*)d_in[3];
    const float* bq   = (const float*)d_in[4];
    const float* wk   = (const float*)d_in[5];
    const float* bk   = (const float*)d_in[6];
    const float* wv   = (const float*)d_in[7];
    const float* bv   = (const float*)d_in[8];
    const float* wo   = (const float*)d_in[9];
    const float* bo   = (const float*)d_in[10];
    const float* wf   = (const float*)d_in[11];
    const float* bf   = (const float*)d_in[12];
    const float* ln2g = (const float*)d_in[13];
    const float* ln2b = (const float*)d_in[14];
    const float* w1   = (const float*)d_in[15];
    const float* b1   = (const float*)d_in[16];
    const float* w2   = (const float*)d_in[17];
    const float* b2   = (const float*)d_in[18];
    float* out = (float*)d_out;

    __half *h, *qkv, *ctx, *h2, *ff, *rwqkv, *rwo, *rw1, *rw2;
    float *c, *x1, *rbqkv;
    cudaGetSymbolAddress((void**)&h,    g_h);
    cudaGetSymbolAddress((void**)&qkv,  g_qkv);
    cudaGetSymbolAddress((void**)&c,    g_c);
    cudaGetSymbolAddress((void**)&ctx,  g_ctx);
    cudaGetSymbolAddress((void**)&x1,   g_x1);
    cudaGetSymbolAddress((void**)&h2,   g_h2);
    cudaGetSymbolAddress((void**)&ff,   g_ff);
    cudaGetSymbolAddress((void**)&rwqkv,g_wqkvT);
    cudaGetSymbolAddress((void**)&rbqkv,g_bqkv);
    cudaGetSymbolAddress((void**)&rwo,  g_woT);
    cudaGetSymbolAddress((void**)&rw1,  g_w1T);
    cudaGetSymbolAddress((void**)&rw2,  g_w2T);

    static int inited = 0;
    if (!inited) {
        cudaFuncSetAttribute(gemm_f16, cudaFuncAttributeMaxDynamicSharedMemorySize, GEMM_SMEM);
        cudaFuncSetAttribute(attn_f16, cudaFuncAttributeMaxDynamicSharedMemorySize, ATTN_SMEM);
        inited = 1;
    }

    // 0) transpose + fp16 weights into [N][K]
    transp_half<<<dim3(32, 32),  256>>>(wq, rwqkv + 0*D_MODEL*D_MODEL, D_MODEL, D_MODEL);
    transp_half<<<dim3(32, 32),  256>>>(wk, rwqkv + 1*D_MODEL*D_MODEL, D_MODEL, D_MODEL);
    transp_half<<<dim3(32, 32),  256>>>(wv, rwqkv + 2*D_MODEL*D_MODEL, D_MODEL, D_MODEL);
    pack_bias_kernel<<<1, 768>>>(bq, bk, bv, rbqkv);
    transp_half<<<dim3(32, 32),  256>>>(wo, rwo, D_MODEL, D_MODEL);
    transp_half<<<dim3(128, 32), 256>>>(w1, rw1, D_MODEL, D_FF);
    transp_half<<<dim3(32, 128), 256>>>(w2, rw2, D_FF, D_MODEL);

    // 1) LN1 -> h fp16
    ln_kernel<<<NTOK, 256>>>(x, ln1g, ln1b, h);
    // 2) fused QKV projection -> fp16 packed
    gemm_f16<<<dim3(D3/128, NTOK/128), 256, GEMM_SMEM>>>(h, rwqkv, rbqkv, nullptr, qkv, NTOK, D3, D_MODEL, 0, 2);
    // 3) forget gate + cumulative log-decay
    fgate_kernel<<<NTOK, 256>>>(h, wf, bf, c);
    cumsum_kernel<<<BATCH * N_HEADS, 256>>>(c);
    // 4) attention (fp16 mma) -> ctx fp16
    attn_f16<<<dim3(SEQ/64, N_HEADS, BATCH), 128, ATTN_SMEM>>>(qkv, c, ctx);
    // 5) output proj + residual -> x1 fp32
    gemm_f16<<<dim3(D_MODEL/128, NTOK/128), 256, GEMM_SMEM>>>(ctx, rwo, bo, x, x1, NTOK, D_MODEL, D_MODEL, 0, 0);
    // 6) LN2 -> h2 fp16
    ln_kernel<<<NTOK, 256>>>(x1, ln2g, ln2b, h2);
    // 7) FF up + GELU -> ff fp16
    gemm_f16<<<dim3(D_FF/128, NTOK/128), 256, GEMM_SMEM>>>(h2, rw1, b1, nullptr, ff, NTOK, D_FF, D_MODEL, 1, 2);
    // 8) FF down + residual -> out fp32
    gemm_f16<<<dim3(D_MODEL/128, NTOK/128), 256, GEMM_SMEM>>>(ff, rw2, b2, x1, out, NTOK, D_MODEL, D_FF, 0, 0);
}

// round 10
// speedup vs baseline: 1.7736x; 1.0569x over previous
#include <cuda_runtime.h>
#include <cuda_fp16.h>
#include <math.h>
#include <stdint.h>

#define D_MODEL 1024
#define N_HEADS 16
#define D_HEAD  64
#define D_FF    4096
#define BATCH   2
#define SEQ     2048
#define NTOK    (BATCH*SEQ)
#define D3      (3*D_MODEL)

// ---------------- scratch (no cudaMalloc allowed) ----------------
__device__ __half g_h   [NTOK*D_MODEL];
__device__ __half g_qkv [NTOK*D3];
__device__ float  g_c   [NTOK*N_HEADS];
__device__ __half g_ctx [NTOK*D_MODEL];
__device__ float  g_x1  [NTOK*D_MODEL];
__device__ __half g_h2  [NTOK*D_MODEL];
__device__ __half g_ff  [NTOK*D_FF];
// transposed fp16 weights, [N][K]
__device__ __half g_wqkvT[D3*D_MODEL];
__device__ float  g_bqkv [D3];
__device__ __half g_woT  [D_MODEL*D_MODEL];
__device__ __half g_w1T  [D_FF*D_MODEL];
__device__ __half g_w2T  [D_MODEL*D_FF];

__device__ __forceinline__ void cp16(uint32_t dst, const void* src) {
    asm volatile("cp.async.cg.shared.global [%0], [%1], 16;" :: "r"(dst), "l"(src));
}
#define CP_COMMIT() asm volatile("cp.async.commit_group;")
#define CP_WAIT(n)  asm volatile("cp.async.wait_group %0;" :: "n"(n))

__device__ __forceinline__ void mma_f16(float* c, const uint32_t* a,
                                        uint32_t b0, uint32_t b1) {
    asm volatile(
        "mma.sync.aligned.m16n8k16.row.col.f32.f16.f16.f32 "
        "{%0,%1,%2,%3}, {%4,%5,%6,%7}, {%8,%9}, {%0,%1,%2,%3};"
        : "+f"(c[0]), "+f"(c[1]), "+f"(c[2]), "+f"(c[3])
        : "r"(a[0]), "r"(a[1]), "r"(a[2]), "r"(a[3]), "r"(b0), "r"(b1));
}
__device__ __forceinline__ void ldsm_x4(uint32_t* r, uint32_t addr) {
    asm volatile(
        "ldmatrix.sync.aligned.m8n8.x4.shared.b16 {%0,%1,%2,%3}, [%4];"
        : "=r"(r[0]), "=r"(r[1]), "=r"(r[2]), "=r"(r[3]) : "r"(addr));
}
__device__ __forceinline__ void ldsm_x4_t(uint32_t* r, uint32_t addr) {
    asm volatile(
        "ldmatrix.sync.aligned.m8n8.x4.trans.shared.b16 {%0,%1,%2,%3}, [%4];"
        : "=r"(r[0]), "=r"(r[1]), "=r"(r[2]), "=r"(r[3]) : "r"(addr));
}

__device__ __forceinline__ float gelu_exact(float x) {
    return 0.5f * x * (1.0f + erff(x * 0.70710678118654752f));
}

// ---------------- transpose + fp16: src[K][N] fp32 -> dst[N][K] fp16 ----------------
// blockIdx.z selects among up to 3 same-shape matrices (QKV pack).
__global__ __launch_bounds__(256) void transp_half3(
    const float* __restrict__ s0, const float* __restrict__ s1,
    const float* __restrict__ s2, __half* __restrict__ dst, int K, int N)
{
    __shared__ float t[32][33];
    const float* src = (blockIdx.z == 0) ? s0 : (blockIdx.z == 1) ? s1 : s2;
    __half* d = dst + (size_t)blockIdx.z * K * N;
    int kb = blockIdx.y * 32, nb = blockIdx.x * 32;
    int x = threadIdx.x & 31, y = threadIdx.x >> 5;   // 32 x 8
    #pragma unroll
    for (int i = 0; i < 32; i += 8)
        t[y + i][x] = src[(size_t)(kb + y + i) * N + nb + x];
    __syncthreads();
    #pragma unroll
    for (int i = 0; i < 32; i += 8)
        d[(size_t)(nb + y + i) * K + kb + x] = __float2half_rn(t[x][y + i]);
}

__global__ void pack_bias_kernel(
    const float* __restrict__ bq, const float* __restrict__ bk,
    const float* __restrict__ bv, float* __restrict__ dst)
{
    int tid = threadIdx.x;      // 768 threads
    int s = tid >> 8, n4 = tid & 255;
    const float* srcs[3] = {bq, bk, bv};
    ((float4*)dst)[s * 256 + n4] = ((const float4*)srcs[s])[n4];
}

// ---------------- LayerNorm: fp32 in, fp16 out ----------------
__global__ __launch_bounds__(256) void ln_kernel(
    const float* __restrict__ x, const float* __restrict__ g,
    const float* __restrict__ b, __half* __restrict__ out)
{
    int row = blockIdx.x;
    int tid = threadIdx.x;
    const float4* xr = (const float4*)(x + (size_t)row * D_MODEL);
    float4 v = xr[tid];
    float s  = v.x + v.y + v.z + v.w;
    float s2 = v.x*v.x + v.y*v.y + v.z*v.z + v.w*v.w;

    __shared__ float red[18];
    #pragma unroll
    for (int off = 16; off > 0; off >>= 1) {
        s  += __shfl_xor_sync(0xffffffffu, s,  off);
        s2 += __shfl_xor_sync(0xffffffffu, s2, off);
    }
    int w = tid >> 5, lane = tid & 31;
    if (lane == 0) { red[w] = s; red[8 + w] = s2; }
    __syncthreads();
    if (tid == 0) {
        float a = 0.f, c2 = 0.f;
        #pragma unroll
        for (int i = 0; i < 8; i++) { a += red[i]; c2 += red[8 + i]; }
        red[16] = a; red[17] = c2;
    }
    __syncthreads();
    float mu  = red[16] * (1.0f / D_MODEL);
    float var = red[17] * (1.0f / D_MODEL) - mu * mu;
    float inv = rsqrtf(var + 1e-5f);

    float4 gg = ((const float4*)g)[tid];
    float4 bb = ((const float4*)b)[tid];
    __half2 o0 = __floats2half2_rn((v.x - mu) * inv * gg.x + bb.x,
                                   (v.y - mu) * inv * gg.y + bb.y);
    __half2 o1 = __floats2half2_rn((v.z - mu) * inv * gg.z + bb.z,
                                   (v.w - mu) * inv * gg.w + bb.w);
    __half2* op = (__half2*)(out + (size_t)row * D_MODEL) + tid * 2;
    op[0] = o0; op[1] = o1;
}

// ---------------- fp16 tensor-core GEMM, cp.async double-buffered ----------------
#define AST2 72
#define TILE2 (128*AST2)
#define GEMM_SMEM (2*2*TILE2*2)

__global__ __launch_bounds__(256, 2) void gemm_f16(
    const __half* __restrict__ A, const __half* __restrict__ Wt,
    const float* __restrict__ bias, const float* __restrict__ resid,
    void* __restrict__ Cv, int M, int N, int K, int act, int omode)
{
    extern __shared__ __half hsm[];
    __half* As = hsm;
    __half* Bs = hsm + 2 * TILE2;

    int tid  = threadIdx.x;
    int wid  = tid >> 5, lane = tid & 31;
    int warp_m = wid >> 2;
    int warp_n = wid & 3;
    int gid = lane >> 2, tig = lane & 3;
    int mb = blockIdx.y * 128, nb = blockIdx.x * 128;

    float acc[4][4][4];
    #pragma unroll
    for (int mt = 0; mt < 4; mt++)
        #pragma unroll
        for (int nt = 0; nt < 4; nt++)
            #pragma unroll
            for (int r = 0; r < 4; r++) acc[mt][nt][r] = 0.f;

    const __half* a_gp[4];
    const __half* b_gp[4];
    uint32_t a_dst[4], b_dst[4];
    #pragma unroll
    for (int i = 0; i < 4; i++) {
        int idx = tid + i * 256;
        int r = idx >> 3, g = idx & 7;
        a_gp[i] = A  + (size_t)(mb + r) * K + g * 8;
        b_gp[i] = Wt + (size_t)(nb + r) * K + g * 8;
        a_dst[i] = (uint32_t)__cvta_generic_to_shared(&As[r * AST2 + g * 8]);
        b_dst[i] = (uint32_t)__cvta_generic_to_shared(&Bs[r * AST2 + g * 8]);
    }

    int lm_row = ((lane >> 3) & 1) * 8 + (lane & 7);
    int lm_k8  = (lane >> 4);
    uint32_t lm_base[4];
    #pragma unroll
    for (int mt = 0; mt < 4; mt++) {
        int row = warp_m * 64 + mt * 16 + lm_row;
        lm_base[mt] = (uint32_t)__cvta_generic_to_shared(
            &As[row * AST2 + lm_k8 * 8]);
    }
    int n0 = warp_n * 32 + gid;

    #pragma unroll
    for (int i = 0; i < 4; i++) cp16(a_dst[i], a_gp[i]);
    #pragma unroll
    for (int i = 0; i < 4; i++) cp16(b_dst[i], b_gp[i]);
    CP_COMMIT();

    int nch = K >> 6;
    int buf = 0;
    for (int c = 0; c < nch; c++) {
        CP_WAIT(0);
        __syncthreads();
        if (c + 1 < nch) {
            int nbo = buf ^ 1;
            int koff = (c + 1) * 64;
            #pragma unroll
            for (int i = 0; i < 4; i++)
                cp16(a_dst[i] + nbo * TILE2 * 2, a_gp[i] + koff);
            #pragma unroll
            for (int i = 0; i < 4; i++)
                cp16(b_dst[i] + nbo * TILE2 * 2, b_gp[i] + koff);
            CP_COMMIT();
        }

        const uint32_t* Bw = (const uint32_t*)(Bs + buf * TILE2);
        uint32_t abuf = buf * TILE2 * 2;
        #pragma unroll
        for (int ks = 0; ks < 4; ks++) {
            uint32_t af[4][4];
            #pragma unroll
            for (int mt = 0; mt < 4; mt++) {
                uint32_t saddr = lm_base[mt] + abuf + ks * 32;
                ldsm_x4(af[mt], saddr);
            }
            uint32_t bf[4][2];
            #pragma unroll
            for (int nt = 0; nt < 4; nt++) {
                int widx = (n0 + nt * 8) * 36 + ks * 8 + tig;
                bf[nt][0] = Bw[widx];
                bf[nt][1] = Bw[widx + 4];
            }
            #pragma unroll
            for (int mt = 0; mt < 4; mt++)
                #pragma unroll
                for (int nt = 0; nt < 4; nt++)
                    mma_f16(acc[mt][nt], af[mt], bf[nt][0], bf[nt][1]);
        }
        buf ^= 1;
    }

    #pragma unroll
    for (int mt = 0; mt < 4; mt++) {
        int r0 = mb + warp_m * 64 + mt * 16 + gid;
        int r1 = r0 + 8;
        #pragma unroll
        for (int nt = 0; nt < 4; nt++) {
            int cc = nb + warp_n * 32 + nt * 8 + tig * 2;
            float b0 = bias[cc], b1 = bias[cc + 1];
            float v00 = acc[mt][nt][0] + b0, v01 = acc[mt][nt][1] + b1;
            float v10 = acc[mt][nt][2] + b0, v11 = acc[mt][nt][3] + b1;
            if (act == 1) {
                v00 = gelu_exact(v00); v01 = gelu_exact(v01);
                v10 = gelu_exact(v10); v11 = gelu_exact(v11);
            }
            size_t p0 = (size_t)r0 * N + cc;
            size_t p1 = (size_t)r1 * N + cc;
            if (resid) {
                float2 q0 = *(const float2*)(resid + p0);
                float2 q1 = *(const float2*)(resid + p1);
                v00 += q0.x; v01 += q0.y; v10 += q1.x; v11 += q1.y;
            }
            if (omode == 2) {
                __half* Ch = (__half*)Cv;
                *(__half2*)(Ch + p0) = __floats2half2_rn(v00, v01);
                *(__half2*)(Ch + p1) = __floats2half2_rn(v10, v11);
            } else {
                float* Cf = (float*)Cv;
                *(float2*)(Cf + p0) = make_float2(v00, v01);
                *(float2*)(Cf + p1) = make_float2(v10, v11);
            }
        }
    }
}

// ---------------- forget gate (fp16 h input) ----------------
__global__ __launch_bounds__(256) void fgate_kernel(
    const __half* __restrict__ h, const float* __restrict__ wf,
    const float* __restrict__ bf, float* __restrict__ logf)
{
    int t   = blockIdx.x;
    int tid = threadIdx.x;
    int hd  = tid >> 4;
    int ln  = tid & 15;
    const __half* hr = h + (size_t)t * D_MODEL;
    float s = 0.f;
    #pragma unroll 8
    for (int k = ln; k < D_MODEL; k += 16)
        s = fmaf(__half2float(hr[k]), wf[(size_t)k * N_HEADS + hd], s);
    #pragma unroll
    for (int off = 8; off > 0; off >>= 1)
        s += __shfl_xor_sync(0xffffffffu, s, off);
    if (ln == 0) {
        float z = s + bf[hd];
        float ls = (z >= 0.f) ? -log1pf(expf(-z)) : (z - log1pf(expf(z)));
        logf[(size_t)t * N_HEADS + hd] = ls;
    }
}

// ---------------- cumsum per (b,h) ----------------
__global__ __launch_bounds__(256) void cumsum_kernel(float* __restrict__ c)
{
    int bh = blockIdx.x;
    int b  = bh >> 4, h = bh & 15;
    int tid = threadIdx.x;
    const int CHUNK = SEQ / 256;
    float vals[CHUNK];
    float run = 0.f;
    size_t base = (size_t)b * SEQ * N_HEADS + h;
    #pragma unroll
    for (int u = 0; u < CHUNK; u++) {
        run += c[base + (size_t)(tid * CHUNK + u) * N_HEADS];
        vals[u] = run;
    }
    __shared__ float tot[256];
    tot[tid] = run;
    __syncthreads();
    for (int off = 1; off < 256; off <<= 1) {
        float t = (tid >= off) ? tot[tid - off] : 0.f;
        __syncthreads();
        tot[tid] += t;
        __syncthreads();
    }
    float offs = tot[tid] - run;
    #pragma unroll
    for (int u = 0; u < CHUNK; u++)
        c[base + (size_t)(tid * CHUNK + u) * N_HEADS] = vals[u] + offs;
}

// ---------------- fp16 tensor-core flash attention, double-buffered K/V ----------------
#define HTILE (64*72)
#define ATTN_SMEM (5*HTILE*2 + 2*64*4)

__global__ __launch_bounds__(128) void attn_f16(
    const __half* __restrict__ QKV, const float* __restrict__ Cdec,
    __half* __restrict__ Out)
{
    extern __shared__ __half hsm[];
    __half* Ksb = hsm;
    __half* Vsb = hsm + 2 * HTILE;
    __half* Ps  = hsm + 4 * HTILE;
    float*  csb = (float*)(hsm + 5 * HTILE);

    int qt = blockIdx.x, h = blockIdx.y, b = blockIdx.z;
    int tid = threadIdx.x, wid = tid >> 5, lane = tid & 31;
    int gid = lane >> 2, tig = lane & 3;
    size_t rowbase = (size_t)b * SEQ;
    int qbase = qt * 64;
    int r0 = wid * 16 + gid;

    uint32_t Ps_u = (uint32_t)__cvta_generic_to_shared(Ps);
    uint32_t Ks_u = (uint32_t)__cvta_generic_to_shared(Ksb);
    uint32_t Vs_u = (uint32_t)__cvta_generic_to_shared(Vsb);

    const __half* qg = QKV + (rowbase + qbase) * D3 + h * D_HEAD;
    #pragma unroll
    for (int i = 0; i < 4; i++) {
        int idx = tid + i * 128;
        int r = idx >> 3, g = idx & 7;
        cp16(Ps_u + r * 144 + g * 16, qg + (size_t)r * D3 + g * 8);
    }
    CP_COMMIT();

    const __half* kg0 = QKV + rowbase * D3 + D_MODEL + h * D_HEAD;
    const __half* vg0 = kg0 + D_MODEL;
    #pragma unroll
    for (int i = 0; i < 4; i++) {
        int idx = tid + i * 128;
        int r = idx >> 3, g = idx & 7;
        cp16(Ks_u + r * 144 + g * 16, kg0 + (size_t)r * D3 + g * 8);
        cp16(Vs_u + r * 144 + g * 16, vg0 + (size_t)r * D3 + g * 8);
    }
    if (tid < 64)
        csb[tid] = Cdec[(rowbase + tid) * N_HEADS + h];
    CP_COMMIT();

    CP_WAIT(1);
    __syncthreads();

    int lm_row = ((lane >> 3) & 1) * 8 + (lane & 7);
    int lm_k8  = (lane >> 4);
    uint32_t qp_base = Ps_u + (wid * 16 + lm_row) * 144 + lm_k8 * 16;
    uint32_t qf[4][4];
    #pragma unroll
    for (int ks = 0; ks < 4; ks++) ldsm_x4(qf[ks], qp_base + ks * 32);

    int v_row = ((lane >> 3) & 1) * 8 + (lane & 7);
    int v_sel = (lane >> 4);

    float oacc[8][4];
    #pragma unroll
    for (int nt = 0; nt < 8; nt++)
        #pragma unroll
        for (int r = 0; r < 4; r++) oacc[nt][r] = 0.f;
    float mrow[2] = {-1e30f, -1e30f};
    float lrow[2] = {0.f, 0.f};

    int buf = 0;
    for (int kt = 0; kt <= qt; kt++) {
        CP_WAIT(0);
        __syncthreads();

        if (kt < qt) {
            int nb_ = buf ^ 1;
            const __half* kg = kg0 + (size_t)(kt + 1) * 64 * D3;
            const __half* vg = vg0 + (size_t)(kt + 1) * 64 * D3;
            uint32_t Kd = Ks_u + nb_ * HTILE * 2;
            uint32_t Vd = Vs_u + nb_ * HTILE * 2;
            #pragma unroll
            for (int i = 0; i < 4; i++) {
                int idx = tid + i * 128;
                int r = idx >> 3, g = idx & 7;
                cp16(Kd + r * 144 + g * 16, kg + (size_t)r * D3 + g * 8);
                cp16(Vd + r * 144 + g * 16, vg + (size_t)r * D3 + g * 8);
            }
            CP_COMMIT();
            if (tid < 64)
                csb[nb_ * 64 + tid] =
                    Cdec[(rowbase + (kt + 1) * 64 + tid) * N_HEADS + h];
        }

        const uint32_t* Kw = (const uint32_t*)(Ksb + buf * HTILE);
        uint32_t Vs_b = Vs_u + buf * HTILE * 2;
        const float* cs = csb + buf * 64;

        float s[8][4];
        #pragma unroll
        for (int nt = 0; nt < 8; nt++)
            #pragma unroll
            for (int r = 0; r < 4; r++) s[nt][r] = 0.f;
        #pragma unroll
        for (int ks = 0; ks < 4; ks++) {
            #pragma unroll
            for (int nt = 0; nt < 8; nt++) {
                int widx = (nt * 8 + gid) * 36 + ks * 8 + tig;
                mma_f16(s[nt], qf[ks], Kw[widx], Kw[widx + 4]);
            }
        }

        #pragma unroll
        for (int rr = 0; rr < 2; rr++) {
            int rloc = r0 + rr * 8;
            float mx = -1e30f;
            #pragma unroll
            for (int nt = 0; nt < 8; nt++) {
                #pragma unroll
                for (int q = 0; q < 2; q++) {
                    int col = nt * 8 + tig * 2 + q;
                    float val = s[nt][rr * 2 + q] * 0.125f - cs[col];
                    if (kt == qt && col > rloc) val = -1e30f;
                    s[nt][rr * 2 + q] = val;
                    mx = fmaxf(mx, val);
                }
            }
            mx = fmaxf(mx, __shfl_xor_sync(0xffffffffu, mx, 1));
            mx = fmaxf(mx, __shfl_xor_sync(0xffffffffu, mx, 2));
            float mnew = fmaxf(mrow[rr], mx);
            float sf = __expf(mrow[rr] - mnew);
            mrow[rr] = mnew;
            float rs = 0.f;
            #pragma unroll
            for (int nt = 0; nt < 8; nt++) {
                #pragma unroll
                for (int q = 0; q < 2; q++) {
                    float p = __expf(s[nt][rr * 2 + q] - mnew);
                    s[nt][rr * 2 + q] = p;
                    rs += p;
                }
            }
            rs += __shfl_xor_sync(0xffffffffu, rs, 1);
            rs += __shfl_xor_sync(0xffffffffu, rs, 2);
            lrow[rr] = lrow[rr] * sf + rs;
            #pragma unroll
            for (int nt = 0; nt < 8; nt++) {
                oacc[nt][rr * 2]     *= sf;
                oacc[nt][rr * 2 + 1] *= sf;
            }
        }

        uint32_t* Pw = (uint32_t*)Ps;
        #pragma unroll
        for (int nt = 0; nt < 8; nt++) {
            __half2 h01 = __floats2half2_rn(s[nt][0], s[nt][1]);
            __half2 h23 = __floats2half2_rn(s[nt][2], s[nt][3]);
            Pw[(r0)     * 36 + nt * 4 + tig] = *(uint32_t*)&h01;
            Pw[(r0 + 8) * 36 + nt * 4 + tig] = *(uint32_t*)&h23;
        }
        __syncwarp();

        #pragma unroll
        for (int ks = 0; ks < 4; ks++) {
            uint32_t pf[4];
            ldsm_x4(pf, qp_base + ks * 32);
            #pragma unroll
            for (int j = 0; j < 4; j++) {
                uint32_t vf[4];
                ldsm_x4_t(vf, Vs_b + (ks * 16 + v_row) * 144 + (2 * j + v_sel) * 16);
                mma_f16(oacc[2 * j],     pf, vf[0], vf[1]);
                mma_f16(oacc[2 * j + 1], pf, vf[2], vf[3]);
            }
        }
        buf ^= 1;
    }

    float inv0 = 1.0f / lrow[0], inv1 = 1.0f / lrow[1];
    size_t row0 = rowbase + qbase + r0;
    #pragma unroll
    for (int nt = 0; nt < 8; nt++) {
        int col = h * D_HEAD + nt * 8 + tig * 2;
        *(__half2*)(Out + row0 * D_MODEL + col) =
            __floats2half2_rn(oacc[nt][0] * inv0, oacc[nt][1] * inv0);
        *(__half2*)(Out + (row0 + 8) * D_MODEL + col) =
            __floats2half2_rn(oacc[nt][2] * inv1, oacc[nt][3] * inv1);
    }
}

// ---------------- launcher with capture fork-join ----------------
extern "C" void kernel_launch(void* const* d_in, const int* in_sizes, int n_in,
                              void* d_out, int out_size)
{
    const float* x    = (const float*)d_in[0];
    const float* ln1g = (const float*)d_in[1];
    const float* ln1b = (const float*)d_in[2];
    const float* wq   = (const float*)d_in[3];
    const float* bq   = (const float*)d_in[4];
    const float* wk   = (const float*)d_in[5];
    const float* bk   = (const float*)d_in[6];
    const float* wv   = (const float*)d_in[7];
    const float* bv   = (const float*)d_in[8];
    const float* wo   = (const float*)d_in[9];
    const float* bo   = (const float*)d_in[10];
    const float* wf   = (const float*)d_in[11];
    const float* bf   = (const float*)d_in[12];
    const float* ln2g = (const float*)d_in[13];
    const float* ln2b = (const float*)d_in[14];
    const float* w1   = (const float*)d_in[15];
    const float* b1   = (const float*)d_in[16];
    const float* w2   = (const float*)d_in[17];
    const float* b2   = (const float*)d_in[18];
    float* out = (float*)d_out;

    __half *h, *qkv, *ctx, *h2, *ff, *rwqkv, *rwo, *rw1, *rw2;
    float *c, *x1, *rbqkv;
    cudaGetSymbolAddress((void**)&h,    g_h);
    cudaGetSymbolAddress((void**)&qkv,  g_qkv);
    cudaGetSymbolAddress((void**)&c,    g_c);
    cudaGetSymbolAddress((void**)&ctx,  g_ctx);
    cudaGetSymbolAddress((void**)&x1,   g_x1);
    cudaGetSymbolAddress((void**)&h2,   g_h2);
    cudaGetSymbolAddress((void**)&ff,   g_ff);
    cudaGetSymbolAddress((void**)&rwqkv,g_wqkvT);
    cudaGetSymbolAddress((void**)&rbqkv,g_bqkv);
    cudaGetSymbolAddress((void**)&rwo,  g_woT);
    cudaGetSymbolAddress((void**)&rw1,  g_w1T);
    cudaGetSymbolAddress((void**)&rw2,  g_w2T);

    static cudaStream_t s2 = nullptr, s3 = nullptr;
    static cudaEvent_t evFork, evQkvW, evLn1, evGate, evBigW;
    static int inited = 0;
    if (!inited) {
        cudaFuncSetAttribute(gemm_f16, cudaFuncAttributeMaxDynamicSharedMemorySize, GEMM_SMEM);
        cudaFuncSetAttribute(attn_f16, cudaFuncAttributeMaxDynamicSharedMemorySize, ATTN_SMEM);
        cudaStreamCreateWithFlags(&s2, cudaStreamNonBlocking);
        cudaStreamCreateWithFlags(&s3, cudaStreamNonBlocking);
        cudaEventCreateWithFlags(&evFork,  cudaEventDisableTiming);
        cudaEventCreateWithFlags(&evQkvW,  cudaEventDisableTiming);
        cudaEventCreateWithFlags(&evLn1,   cudaEventDisableTiming);
        cudaEventCreateWithFlags(&evGate,  cudaEventDisableTiming);
        cudaEventCreateWithFlags(&evBigW,  cudaEventDisableTiming);
        inited = 1;
    }

    // fork side streams from the (possibly captured) main stream
    cudaEventRecord(evFork, 0);
    cudaStreamWaitEvent(s2, evFork, 0);
    cudaStreamWaitEvent(s3, evFork, 0);

    // s2: QKV weight pack (transpose x3 + bias)
    transp_half3<<<dim3(32, 32, 3), 256, 0, s2>>>(wq, wk, wv, rwqkv, D_MODEL, D_MODEL);
    pack_bias_kernel<<<1, 768, 0, s2>>>(bq, bk, bv, rbqkv);
    cudaEventRecord(evQkvW, s2);

    // s3: wo/w1/w2 packs (needed only from step 5 onward)
    transp_half3<<<dim3(32, 32),  256, 0, s3>>>(wo, wo, wo, rwo, D_MODEL, D_MODEL);
    transp_half3<<<dim3(128, 32), 256, 0, s3>>>(w1, w1, w1, rw1, D_MODEL, D_FF);
    transp_half3<<<dim3(32, 128), 256, 0, s3>>>(w2, w2, w2, rw2, D_FF, D_MODEL);
    cudaEventRecord(evBigW, s3);

    // main: LN1 (concurrent with weight packs)
    ln_kernel<<<NTOK, 256>>>(x, ln1g, ln1b, h);
    cudaEventRecord(evLn1, 0);

    // s2: forget gate + cumsum (needs h; concurrent with QKV gemm)
    cudaStreamWaitEvent(s2, evLn1, 0);
    fgate_kernel<<<NTOK, 256, 0, s2>>>(h, wf, bf, c);
    cumsum_kernel<<<BATCH * N_HEADS, 256, 0, s2>>>(c);
    cudaEventRecord(evGate, s2);

    // main: QKV gemm (needs QKV weights)
    cudaStreamWaitEvent(0, evQkvW, 0);
    gemm_f16<<<dim3(D3/128, NTOK/128), 256, GEMM_SMEM>>>(h, rwqkv, rbqkv, nullptr, qkv, NTOK, D3, D_MODEL, 0, 2);

    // main: attention (needs qkv + gate)
    cudaStreamWaitEvent(0, evGate, 0);
    attn_f16<<<dim3(SEQ/64, N_HEADS, BATCH), 128, ATTN_SMEM>>>(qkv, c, ctx);

    // main: output proj + residual (needs wo pack)
    cudaStreamWaitEvent(0, evBigW, 0);
    gemm_f16<<<dim3(D_MODEL/128, NTOK/128), 256, GEMM_SMEM>>>(ctx, rwo, bo, x, x1, NTOK, D_MODEL, D_MODEL, 0, 0);
    // LN2
    ln_kernel<<<NTOK, 256>>>(x1, ln2g, ln2b, h2);
    // FF up + GELU
    gemm_f16<<<dim3(D_FF/128, NTOK/128), 256, GEMM_SMEM>>>(h2, rw1, b1, nullptr, ff, NTOK, D_FF, D_MODEL, 1, 2);
    // FF down + residual -> out
    gemm_f16<<<dim3(D_MODEL/128, NTOK/128), 256, GEMM_SMEM>>>(ff, rw2, b2, x1, out, NTOK, D_MODEL, D_FF, 0, 0);
}

// round 11
// speedup vs baseline: 1.7869x; 1.0075x over previous
#include <cuda_runtime.h>
#include <cuda_fp16.h>
#include <math.h>
#include <stdint.h>

#define D_MODEL 1024
#define N_HEADS 16
#define D_HEAD  64
#define D_FF    4096
#define BATCH   2
#define SEQ     2048
#define NTOK    (BATCH*SEQ)
#define D3      (3*D_MODEL)

// ---------------- scratch (no cudaMalloc allowed) ----------------
__device__ __half g_h   [NTOK*D_MODEL];
__device__ __half g_qkv [NTOK*D3];
__device__ float  g_c   [NTOK*N_HEADS];
__device__ __half g_ctx [NTOK*D_MODEL];
__device__ float  g_x1  [NTOK*D_MODEL];
__device__ __half g_h2  [NTOK*D_MODEL];
__device__ __half g_ff  [NTOK*D_FF];
// transposed fp16 weights, [N][K]
__device__ __half g_wqkvT[D3*D_MODEL];
__device__ float  g_bqkv [D3];
__device__ __half g_woT  [D_MODEL*D_MODEL];
__device__ __half g_w1T  [D_FF*D_MODEL];
__device__ __half g_w2T  [D_MODEL*D_FF];

__device__ __forceinline__ void cp16(uint32_t dst, const void* src) {
    asm volatile("cp.async.cg.shared.global [%0], [%1], 16;" :: "r"(dst), "l"(src));
}
#define CP_COMMIT() asm volatile("cp.async.commit_group;")
#define CP_WAIT(n)  asm volatile("cp.async.wait_group %0;" :: "n"(n))

__device__ __forceinline__ void mma_f16(float* c, const uint32_t* a,
                                        uint32_t b0, uint32_t b1) {
    asm volatile(
        "mma.sync.aligned.m16n8k16.row.col.f32.f16.f16.f32 "
        "{%0,%1,%2,%3}, {%4,%5,%6,%7}, {%8,%9}, {%0,%1,%2,%3};"
        : "+f"(c[0]), "+f"(c[1]), "+f"(c[2]), "+f"(c[3])
        : "r"(a[0]), "r"(a[1]), "r"(a[2]), "r"(a[3]), "r"(b0), "r"(b1));
}
__device__ __forceinline__ void ldsm_x4(uint32_t* r, uint32_t addr) {
    asm volatile(
        "ldmatrix.sync.aligned.m8n8.x4.shared.b16 {%0,%1,%2,%3}, [%4];"
        : "=r"(r[0]), "=r"(r[1]), "=r"(r[2]), "=r"(r[3]) : "r"(addr));
}
__device__ __forceinline__ void ldsm_x4_t(uint32_t* r, uint32_t addr) {
    asm volatile(
        "ldmatrix.sync.aligned.m8n8.x4.trans.shared.b16 {%0,%1,%2,%3}, [%4];"
        : "=r"(r[0]), "=r"(r[1]), "=r"(r[2]), "=r"(r[3]) : "r"(addr));
}

__device__ __forceinline__ float gelu_exact(float x) {
    return 0.5f * x * (1.0f + erff(x * 0.70710678118654752f));
}

// ---------------- transpose + fp16: src[K][N] fp32 -> dst[N][K] fp16 ----------------
__global__ __launch_bounds__(256) void transp_half3(
    const float* __restrict__ s0, const float* __restrict__ s1,
    const float* __restrict__ s2, __half* __restrict__ dst, int K, int N)
{
    __shared__ float t[32][33];
    const float* src = (blockIdx.z == 0) ? s0 : (blockIdx.z == 1) ? s1 : s2;
    __half* d = dst + (size_t)blockIdx.z * K * N;
    int kb = blockIdx.y * 32, nb = blockIdx.x * 32;
    int x = threadIdx.x & 31, y = threadIdx.x >> 5;
    #pragma unroll
    for (int i = 0; i < 32; i += 8)
        t[y + i][x] = src[(size_t)(kb + y + i) * N + nb + x];
    __syncthreads();
    #pragma unroll
    for (int i = 0; i < 32; i += 8)
        d[(size_t)(nb + y + i) * K + kb + x] = __float2half_rn(t[x][y + i]);
}

__global__ void pack_bias_kernel(
    const float* __restrict__ bq, const float* __restrict__ bk,
    const float* __restrict__ bv, float* __restrict__ dst)
{
    int tid = threadIdx.x;
    int s = tid >> 8, n4 = tid & 255;
    const float* srcs[3] = {bq, bk, bv};
    ((float4*)dst)[s * 256 + n4] = ((const float4*)srcs[s])[n4];
}

// ---------------- LayerNorm: fp32 in, fp16 out ----------------
__global__ __launch_bounds__(256) void ln_kernel(
    const float* __restrict__ x, const float* __restrict__ g,
    const float* __restrict__ b, __half* __restrict__ out)
{
    int row = blockIdx.x;
    int tid = threadIdx.x;
    const float4* xr = (const float4*)(x + (size_t)row * D_MODEL);
    float4 v = xr[tid];
    float s  = v.x + v.y + v.z + v.w;
    float s2 = v.x*v.x + v.y*v.y + v.z*v.z + v.w*v.w;

    __shared__ float red[18];
    #pragma unroll
    for (int off = 16; off > 0; off >>= 1) {
        s  += __shfl_xor_sync(0xffffffffu, s,  off);
        s2 += __shfl_xor_sync(0xffffffffu, s2, off);
    }
    int w = tid >> 5, lane = tid & 31;
    if (lane == 0) { red[w] = s; red[8 + w] = s2; }
    __syncthreads();
    if (tid == 0) {
        float a = 0.f, c2 = 0.f;
        #pragma unroll
        for (int i = 0; i < 8; i++) { a += red[i]; c2 += red[8 + i]; }
        red[16] = a; red[17] = c2;
    }
    __syncthreads();
    float mu  = red[16] * (1.0f / D_MODEL);
    float var = red[17] * (1.0f / D_MODEL) - mu * mu;
    float inv = rsqrtf(var + 1e-5f);

    float4 gg = ((const float4*)g)[tid];
    float4 bb = ((const float4*)b)[tid];
    __half2 o0 = __floats2half2_rn((v.x - mu) * inv * gg.x + bb.x,
                                   (v.y - mu) * inv * gg.y + bb.y);
    __half2 o1 = __floats2half2_rn((v.z - mu) * inv * gg.z + bb.z,
                                   (v.w - mu) * inv * gg.w + bb.w);
    __half2* op = (__half2*)(out + (size_t)row * D_MODEL) + tid * 2;
    op[0] = o0; op[1] = o1;
}

// ---------------- fp16 tensor-core GEMM, cp.async double-buffered ----------------
#define AST2 72
#define TILE2 (128*AST2)
#define GEMM_SMEM (2*2*TILE2*2)

__global__ __launch_bounds__(256, 2) void gemm_f16(
    const __half* __restrict__ A, const __half* __restrict__ Wt,
    const float* __restrict__ bias, const float* __restrict__ resid,
    void* __restrict__ Cv, int M, int N, int K, int act, int omode)
{
    extern __shared__ __half hsm[];
    __half* As = hsm;
    __half* Bs = hsm + 2 * TILE2;

    int tid  = threadIdx.x;
    int wid  = tid >> 5, lane = tid & 31;
    int warp_m = wid >> 2;
    int warp_n = wid & 3;
    int gid = lane >> 2, tig = lane & 3;
    int mb = blockIdx.y * 128, nb = blockIdx.x * 128;

    float acc[4][4][4];
    #pragma unroll
    for (int mt = 0; mt < 4; mt++)
        #pragma unroll
        for (int nt = 0; nt < 4; nt++)
            #pragma unroll
            for (int r = 0; r < 4; r++) acc[mt][nt][r] = 0.f;

    const __half* a_gp[4];
    const __half* b_gp[4];
    uint32_t a_dst[4], b_dst[4];
    #pragma unroll
    for (int i = 0; i < 4; i++) {
        int idx = tid + i * 256;
        int r = idx >> 3, g = idx & 7;
        a_gp[i] = A  + (size_t)(mb + r) * K + g * 8;
        b_gp[i] = Wt + (size_t)(nb + r) * K + g * 8;
        a_dst[i] = (uint32_t)__cvta_generic_to_shared(&As[r * AST2 + g * 8]);
        b_dst[i] = (uint32_t)__cvta_generic_to_shared(&Bs[r * AST2 + g * 8]);
    }

    int lm_row = ((lane >> 3) & 1) * 8 + (lane & 7);
    int lm_k8  = (lane >> 4);
    uint32_t lm_base[4];
    #pragma unroll
    for (int mt = 0; mt < 4; mt++) {
        int row = warp_m * 64 + mt * 16 + lm_row;
        lm_base[mt] = (uint32_t)__cvta_generic_to_shared(
            &As[row * AST2 + lm_k8 * 8]);
    }
    int n0 = warp_n * 32 + gid;

    #pragma unroll
    for (int i = 0; i < 4; i++) cp16(a_dst[i], a_gp[i]);
    #pragma unroll
    for (int i = 0; i < 4; i++) cp16(b_dst[i], b_gp[i]);
    CP_COMMIT();

    int nch = K >> 6;
    int buf = 0;
    for (int c = 0; c < nch; c++) {
        CP_WAIT(0);
        __syncthreads();
        if (c + 1 < nch) {
            int nbo = buf ^ 1;
            int koff = (c + 1) * 64;
            #pragma unroll
            for (int i = 0; i < 4; i++)
                cp16(a_dst[i] + nbo * TILE2 * 2, a_gp[i] + koff);
            #pragma unroll
            for (int i = 0; i < 4; i++)
                cp16(b_dst[i] + nbo * TILE2 * 2, b_gp[i] + koff);
            CP_COMMIT();
        }

        const uint32_t* Bw = (const uint32_t*)(Bs + buf * TILE2);
        uint32_t abuf = buf * TILE2 * 2;
        #pragma unroll
        for (int ks = 0; ks < 4; ks++) {
            uint32_t af[4][4];
            #pragma unroll
            for (int mt = 0; mt < 4; mt++) {
                uint32_t saddr = lm_base[mt] + abuf + ks * 32;
                ldsm_x4(af[mt], saddr);
            }
            uint32_t bf[4][2];
            #pragma unroll
            for (int nt = 0; nt < 4; nt++) {
                int widx = (n0 + nt * 8) * 36 + ks * 8 + tig;
                bf[nt][0] = Bw[widx];
                bf[nt][1] = Bw[widx + 4];
            }
            #pragma unroll
            for (int mt = 0; mt < 4; mt++)
                #pragma unroll
                for (int nt = 0; nt < 4; nt++)
                    mma_f16(acc[mt][nt], af[mt], bf[nt][0], bf[nt][1]);
        }
        buf ^= 1;
    }

    #pragma unroll
    for (int mt = 0; mt < 4; mt++) {
        int r0 = mb + warp_m * 64 + mt * 16 + gid;
        int r1 = r0 + 8;
        #pragma unroll
        for (int nt = 0; nt < 4; nt++) {
            int cc = nb + warp_n * 32 + nt * 8 + tig * 2;
            float b0 = bias[cc], b1 = bias[cc + 1];
            float v00 = acc[mt][nt][0] + b0, v01 = acc[mt][nt][1] + b1;
            float v10 = acc[mt][nt][2] + b0, v11 = acc[mt][nt][3] + b1;
            if (act == 1) {
                v00 = gelu_exact(v00); v01 = gelu_exact(v01);
                v10 = gelu_exact(v10); v11 = gelu_exact(v11);
            }
            size_t p0 = (size_t)r0 * N + cc;
            size_t p1 = (size_t)r1 * N + cc;
            if (resid) {
                float2 q0 = *(const float2*)(resid + p0);
                float2 q1 = *(const float2*)(resid + p1);
                v00 += q0.x; v01 += q0.y; v10 += q1.x; v11 += q1.y;
            }
            if (omode == 2) {
                __half* Ch = (__half*)Cv;
                *(__half2*)(Ch + p0) = __floats2half2_rn(v00, v01);
                *(__half2*)(Ch + p1) = __floats2half2_rn(v10, v11);
            } else {
                float* Cf = (float*)Cv;
                *(float2*)(Cf + p0) = make_float2(v00, v01);
                *(float2*)(Cf + p1) = make_float2(v10, v11);
            }
        }
    }
}

// ---------------- forget gate (fp16 h input) ----------------
__global__ __launch_bounds__(256) void fgate_kernel(
    const __half* __restrict__ h, const float* __restrict__ wf,
    const float* __restrict__ bf, float* __restrict__ logf)
{
    int t   = blockIdx.x;
    int tid = threadIdx.x;
    int hd  = tid >> 4;
    int ln  = tid & 15;
    const __half* hr = h + (size_t)t * D_MODEL;
    float s = 0.f;
    #pragma unroll 8
    for (int k = ln; k < D_MODEL; k += 16)
        s = fmaf(__half2float(hr[k]), wf[(size_t)k * N_HEADS + hd], s);
    #pragma unroll
    for (int off = 8; off > 0; off >>= 1)
        s += __shfl_xor_sync(0xffffffffu, s, off);
    if (ln == 0) {
        float z = s + bf[hd];
        float ls = (z >= 0.f) ? -log1pf(expf(-z)) : (z - log1pf(expf(z)));
        logf[(size_t)t * N_HEADS + hd] = ls;
    }
}

// ---------------- cumsum per (b,h) ----------------
__global__ __launch_bounds__(256) void cumsum_kernel(float* __restrict__ c)
{
    int bh = blockIdx.x;
    int b  = bh >> 4, h = bh & 15;
    int tid = threadIdx.x;
    const int CHUNK = SEQ / 256;
    float vals[CHUNK];
    float run = 0.f;
    size_t base = (size_t)b * SEQ * N_HEADS + h;
    #pragma unroll
    for (int u = 0; u < CHUNK; u++) {
        run += c[base + (size_t)(tid * CHUNK + u) * N_HEADS];
        vals[u] = run;
    }
    __shared__ float tot[256];
    tot[tid] = run;
    __syncthreads();
    for (int off = 1; off < 256; off <<= 1) {
        float t = (tid >= off) ? tot[tid - off] : 0.f;
        __syncthreads();
        tot[tid] += t;
        __syncthreads();
    }
    float offs = tot[tid] - run;
    #pragma unroll
    for (int u = 0; u < CHUNK; u++)
        c[base + (size_t)(tid * CHUNK + u) * N_HEADS] = vals[u] + offs;
}

// ---------------- fp16 flash attention, paired causal tiles ----------------
// CTA p processes q-tiles {p, NT-1-p}: constant 33 k-tile iterations per CTA.
#define HTILE (64*72)
#define ATTN_SMEM (5*HTILE*2 + 2*64*4)

__global__ __launch_bounds__(128) void attn_f16(
    const __half* __restrict__ QKV, const float* __restrict__ Cdec,
    __half* __restrict__ Out)
{
    extern __shared__ __half hsm[];
    __half* Ksb = hsm;
    __half* Vsb = hsm + 2 * HTILE;
    __half* Ps  = hsm + 4 * HTILE;
    float*  csb = (float*)(hsm + 5 * HTILE);

    int h = blockIdx.y, b = blockIdx.z;
    int tid = threadIdx.x, wid = tid >> 5, lane = tid & 31;
    int gid = lane >> 2, tig = lane & 3;
    size_t rowbase = (size_t)b * SEQ;
    int r0 = wid * 16 + gid;

    uint32_t Ps_u = (uint32_t)__cvta_generic_to_shared(Ps);
    uint32_t Ks_u = (uint32_t)__cvta_generic_to_shared(Ksb);
    uint32_t Vs_u = (uint32_t)__cvta_generic_to_shared(Vsb);

    const __half* kg0 = QKV + rowbase * D3 + D_MODEL + h * D_HEAD;
    const __half* vg0 = kg0 + D_MODEL;

    int lm_row = ((lane >> 3) & 1) * 8 + (lane & 7);
    int lm_k8  = (lane >> 4);
    uint32_t qp_base = Ps_u + (wid * 16 + lm_row) * 144 + lm_k8 * 16;
    int v_row = lm_row;
    int v_sel = lm_k8;

    const int NT = SEQ / 64;       // 32
    int qts[2] = { (int)blockIdx.x, NT - 1 - (int)blockIdx.x };

    for (int p = 0; p < 2; p++) {
        int qt = qts[p];
        int qbase = qt * 64;
        __syncthreads();           // smem reuse across pair

        // stage Q
        const __half* qg = QKV + (rowbase + qbase) * D3 + h * D_HEAD;
        #pragma unroll
        for (int i = 0; i < 4; i++) {
            int idx = tid + i * 128;
            int r = idx >> 3, g = idx & 7;
            cp16(Ps_u + r * 144 + g * 16, qg + (size_t)r * D3 + g * 8);
        }
        CP_COMMIT();

        // K/V tile 0
        #pragma unroll
        for (int i = 0; i < 4; i++) {
            int idx = tid + i * 128;
            int r = idx >> 3, g = idx & 7;
            cp16(Ks_u + r * 144 + g * 16, kg0 + (size_t)r * D3 + g * 8);
            cp16(Vs_u + r * 144 + g * 16, vg0 + (size_t)r * D3 + g * 8);
        }
        if (tid < 64)
            csb[tid] = Cdec[(rowbase + tid) * N_HEADS + h];
        CP_COMMIT();

        CP_WAIT(1);
        __syncthreads();

        uint32_t qf[4][4];
        #pragma unroll
        for (int ks = 0; ks < 4; ks++) ldsm_x4(qf[ks], qp_base + ks * 32);

        float oacc[8][4];
        #pragma unroll
        for (int nt = 0; nt < 8; nt++)
            #pragma unroll
            for (int r = 0; r < 4; r++) oacc[nt][r] = 0.f;
        float mrow[2] = {-1e30f, -1e30f};
        float lrow[2] = {0.f, 0.f};

        int buf = 0;
        for (int kt = 0; kt <= qt; kt++) {
            CP_WAIT(0);
            __syncthreads();

            if (kt < qt) {
                int nb_ = buf ^ 1;
                const __half* kg = kg0 + (size_t)(kt + 1) * 64 * D3;
                const __half* vg = vg0 + (size_t)(kt + 1) * 64 * D3;
                uint32_t Kd = Ks_u + nb_ * HTILE * 2;
                uint32_t Vd = Vs_u + nb_ * HTILE * 2;
                #pragma unroll
                for (int i = 0; i < 4; i++) {
                    int idx = tid + i * 128;
                    int r = idx >> 3, g = idx & 7;
                    cp16(Kd + r * 144 + g * 16, kg + (size_t)r * D3 + g * 8);
                    cp16(Vd + r * 144 + g * 16, vg + (size_t)r * D3 + g * 8);
                }
                CP_COMMIT();
                if (tid < 64)
                    csb[nb_ * 64 + tid] =
                        Cdec[(rowbase + (kt + 1) * 64 + tid) * N_HEADS + h];
            }

            const uint32_t* Kw = (const uint32_t*)(Ksb + buf * HTILE);
            uint32_t Vs_b = Vs_u + buf * HTILE * 2;
            const float* cs = csb + buf * 64;

            float s[8][4];
            #pragma unroll
            for (int nt = 0; nt < 8; nt++)
                #pragma unroll
                for (int r = 0; r < 4; r++) s[nt][r] = 0.f;
            #pragma unroll
            for (int ks = 0; ks < 4; ks++) {
                #pragma unroll
                for (int nt = 0; nt < 8; nt++) {
                    int widx = (nt * 8 + gid) * 36 + ks * 8 + tig;
                    mma_f16(s[nt], qf[ks], Kw[widx], Kw[widx + 4]);
                }
            }

            #pragma unroll
            for (int rr = 0; rr < 2; rr++) {
                int rloc = r0 + rr * 8;
                float mx = -1e30f;
                #pragma unroll
                for (int nt = 0; nt < 8; nt++) {
                    #pragma unroll
                    for (int q = 0; q < 2; q++) {
                        int col = nt * 8 + tig * 2 + q;
                        float val = s[nt][rr * 2 + q] * 0.125f - cs[col];
                        if (kt == qt && col > rloc) val = -1e30f;
                        s[nt][rr * 2 + q] = val;
                        mx = fmaxf(mx, val);
                    }
                }
                mx = fmaxf(mx, __shfl_xor_sync(0xffffffffu, mx, 1));
                mx = fmaxf(mx, __shfl_xor_sync(0xffffffffu, mx, 2));
                float mnew = fmaxf(mrow[rr], mx);
                float sf = __expf(mrow[rr] - mnew);
                mrow[rr] = mnew;
                float rs = 0.f;
                #pragma unroll
                for (int nt = 0; nt < 8; nt++) {
                    #pragma unroll
                    for (int q = 0; q < 2; q++) {
                        float pv = __expf(s[nt][rr * 2 + q] - mnew);
                        s[nt][rr * 2 + q] = pv;
                        rs += pv;
                    }
                }
                rs += __shfl_xor_sync(0xffffffffu, rs, 1);
                rs += __shfl_xor_sync(0xffffffffu, rs, 2);
                lrow[rr] = lrow[rr] * sf + rs;
                #pragma unroll
                for (int nt = 0; nt < 8; nt++) {
                    oacc[nt][rr * 2]     *= sf;
                    oacc[nt][rr * 2 + 1] *= sf;
                }
            }

            uint32_t* Pw = (uint32_t*)Ps;
            #pragma unroll
            for (int nt = 0; nt < 8; nt++) {
                __half2 h01 = __floats2half2_rn(s[nt][0], s[nt][1]);
                __half2 h23 = __floats2half2_rn(s[nt][2], s[nt][3]);
                Pw[(r0)     * 36 + nt * 4 + tig] = *(uint32_t*)&h01;
                Pw[(r0 + 8) * 36 + nt * 4 + tig] = *(uint32_t*)&h23;
            }
            __syncwarp();

            #pragma unroll
            for (int ks = 0; ks < 4; ks++) {
                uint32_t pf[4];
                ldsm_x4(pf, qp_base + ks * 32);
                #pragma unroll
                for (int j = 0; j < 4; j++) {
                    uint32_t vf[4];
                    ldsm_x4_t(vf, Vs_b + (ks * 16 + v_row) * 144 + (2 * j + v_sel) * 16);
                    mma_f16(oacc[2 * j],     pf, vf[0], vf[1]);
                    mma_f16(oacc[2 * j + 1], pf, vf[2], vf[3]);
                }
            }
            buf ^= 1;
        }

        float inv0 = 1.0f / lrow[0], inv1 = 1.0f / lrow[1];
        size_t row0 = rowbase + qbase + r0;
        #pragma unroll
        for (int nt = 0; nt < 8; nt++) {
            int col = h * D_HEAD + nt * 8 + tig * 2;
            *(__half2*)(Out + row0 * D_MODEL + col) =
                __floats2half2_rn(oacc[nt][0] * inv0, oacc[nt][1] * inv0);
            *(__half2*)(Out + (row0 + 8) * D_MODEL + col) =
                __floats2half2_rn(oacc[nt][2] * inv1, oacc[nt][3] * inv1);
        }
    }
}

// ---------------- launcher with capture fork-join ----------------
extern "C" void kernel_launch(void* const* d_in, const int* in_sizes, int n_in,
                              void* d_out, int out_size)
{
    const float* x    = (const float*)d_in[0];
    const float* ln1g = (const float*)d_in[1];
    const float* ln1b = (const float*)d_in[2];
    const float* wq   = (const float*)d_in[3];
    const float* bq   = (const float*)d_in[4];
    const float* wk   = (const float*)d_in[5];
    const float* bk   = (const float*)d_in[6];
    const float* wv   = (const float*)d_in[7];
    const float* bv   = (const float*)d_in[8];
    const float* wo   = (const float*)d_in[9];
    const float* bo   = (const float*)d_in[10];
    const float* wf   = (const float*)d_in[11];
    const float* bf   = (const float*)d_in[12];
    const float* ln2g = (const float*)d_in[13];
    const float* ln2b = (const float*)d_in[14];
    const float* w1   = (const float*)d_in[15];
    const float* b1   = (const float*)d_in[16];
    const float* w2   = (const float*)d_in[17];
    const float* b2   = (const float*)d_in[18];
    float* out = (float*)d_out;

    __half *h, *qkv, *ctx, *h2, *ff, *rwqkv, *rwo, *rw1, *rw2;
    float *c, *x1, *rbqkv;
    cudaGetSymbolAddress((void**)&h,    g_h);
    cudaGetSymbolAddress((void**)&qkv,  g_qkv);
    cudaGetSymbolAddress((void**)&c,    g_c);
    cudaGetSymbolAddress((void**)&ctx,  g_ctx);
    cudaGetSymbolAddress((void**)&x1,   g_x1);
    cudaGetSymbolAddress((void**)&h2,   g_h2);
    cudaGetSymbolAddress((void**)&ff,   g_ff);
    cudaGetSymbolAddress((void**)&rwqkv,g_wqkvT);
    cudaGetSymbolAddress((void**)&rbqkv,g_bqkv);
    cudaGetSymbolAddress((void**)&rwo,  g_woT);
    cudaGetSymbolAddress((void**)&rw1,  g_w1T);
    cudaGetSymbolAddress((void**)&rw2,  g_w2T);

    static cudaStream_t s2 = nullptr, s3 = nullptr;
    static cudaEvent_t evFork, evQkvW, evLn1, evGate, evBigW;
    static int inited = 0;
    if (!inited) {
        cudaFuncSetAttribute(gemm_f16, cudaFuncAttributeMaxDynamicSharedMemorySize, GEMM_SMEM);
        cudaFuncSetAttribute(attn_f16, cudaFuncAttributeMaxDynamicSharedMemorySize, ATTN_SMEM);
        cudaStreamCreateWithFlags(&s2, cudaStreamNonBlocking);
        cudaStreamCreateWithFlags(&s3, cudaStreamNonBlocking);
        cudaEventCreateWithFlags(&evFork,  cudaEventDisableTiming);
        cudaEventCreateWithFlags(&evQkvW,  cudaEventDisableTiming);
        cudaEventCreateWithFlags(&evLn1,   cudaEventDisableTiming);
        cudaEventCreateWithFlags(&evGate,  cudaEventDisableTiming);
        cudaEventCreateWithFlags(&evBigW,  cudaEventDisableTiming);
        inited = 1;
    }

    cudaEventRecord(evFork, 0);
    cudaStreamWaitEvent(s2, evFork, 0);
    cudaStreamWaitEvent(s3, evFork, 0);

    // s2: QKV weight pack
    transp_half3<<<dim3(32, 32, 3), 256, 0, s2>>>(wq, wk, wv, rwqkv, D_MODEL, D_MODEL);
    pack_bias_kernel<<<1, 768, 0, s2>>>(bq, bk, bv, rbqkv);
    cudaEventRecord(evQkvW, s2);

    // s3: wo/w1/w2 packs
    transp_half3<<<dim3(32, 32),  256, 0, s3>>>(wo, wo, wo, rwo, D_MODEL, D_MODEL);
    transp_half3<<<dim3(128, 32), 256, 0, s3>>>(w1, w1, w1, rw1, D_MODEL, D_FF);
    transp_half3<<<dim3(32, 128), 256, 0, s3>>>(w2, w2, w2, rw2, D_FF, D_MODEL);
    cudaEventRecord(evBigW, s3);

    // main: LN1
    ln_kernel<<<NTOK, 256>>>(x, ln1g, ln1b, h);
    cudaEventRecord(evLn1, 0);

    // s2: forget gate + cumsum (concurrent with QKV gemm)
    cudaStreamWaitEvent(s2, evLn1, 0);
    fgate_kernel<<<NTOK, 256, 0, s2>>>(h, wf, bf, c);
    cumsum_kernel<<<BATCH * N_HEADS, 256, 0, s2>>>(c);
    cudaEventRecord(evGate, s2);

    // main: QKV gemm
    cudaStreamWaitEvent(0, evQkvW, 0);
    gemm_f16<<<dim3(D3/128, NTOK/128), 256, GEMM_SMEM>>>(h, rwqkv, rbqkv, nullptr, qkv, NTOK, D3, D_MODEL, 0, 2);

    // main: attention (paired causal tiles)
    cudaStreamWaitEvent(0, evGate, 0);
    attn_f16<<<dim3(SEQ/128, N_HEADS, BATCH), 128, ATTN_SMEM>>>(qkv, c, ctx);

    // main: output proj + residual
    cudaStreamWaitEvent(0, evBigW, 0);
    gemm_f16<<<dim3(D_MODEL/128, NTOK/128), 256, GEMM_SMEM>>>(ctx, rwo, bo, x, x1, NTOK, D_MODEL, D_MODEL, 0, 0);
    // LN2
    ln_kernel<<<NTOK, 256>>>(x1, ln2g, ln2b, h2);
    // FF up + GELU
    gemm_f16<<<dim3(D_FF/128, NTOK/128), 256, GEMM_SMEM>>>(h2, rw1, b1, nullptr, ff, NTOK, D_FF, D_MODEL, 1, 2);
    // FF down + residual -> out
    gemm_f16<<<dim3(D_MODEL/128, NTOK/128), 256, GEMM_SMEM>>>(ff, rw2, b2, x1, out, NTOK, D_MODEL, D_FF, 0, 0);
}

// round 12
// speedup vs baseline: 1.8077x; 1.0116x over previous
#include <cuda_runtime.h>
#include <cuda_fp16.h>
#include <math.h>
#include <stdint.h>

#define D_MODEL 1024
#define N_HEADS 16
#define D_HEAD  64
#define D_FF    4096
#define BATCH   2
#define SEQ     2048
#define NTOK    (BATCH*SEQ)
#define D3      (3*D_MODEL)

// ---------------- scratch (no cudaMalloc allowed) ----------------
__device__ __half g_h   [NTOK*D_MODEL];
__device__ __half g_qkv [NTOK*D3];
__device__ float  g_c   [NTOK*N_HEADS];
__device__ __half g_ctx [NTOK*D_MODEL];
__device__ float  g_x1  [NTOK*D_MODEL];
__device__ __half g_h2  [NTOK*D_MODEL];
__device__ __half g_ff  [NTOK*D_FF];
// transposed fp16 weights, [N][K]
__device__ __half g_wqkvT[D3*D_MODEL];
__device__ float  g_bqkv [D3];
__device__ __half g_woT  [D_MODEL*D_MODEL];
__device__ __half g_w1T  [D_FF*D_MODEL];
__device__ __half g_w2T  [D_MODEL*D_FF];

__device__ __forceinline__ void cp16(uint32_t dst, const void* src) {
    asm volatile("cp.async.cg.shared.global [%0], [%1], 16;" :: "r"(dst), "l"(src));
}
#define CP_COMMIT() asm volatile("cp.async.commit_group;")
#define CP_WAIT(n)  asm volatile("cp.async.wait_group %0;" :: "n"(n))

__device__ __forceinline__ void mma_f16(float* c, const uint32_t* a,
                                        uint32_t b0, uint32_t b1) {
    asm volatile(
        "mma.sync.aligned.m16n8k16.row.col.f32.f16.f16.f32 "
        "{%0,%1,%2,%3}, {%4,%5,%6,%7}, {%8,%9}, {%0,%1,%2,%3};"
        : "+f"(c[0]), "+f"(c[1]), "+f"(c[2]), "+f"(c[3])
        : "r"(a[0]), "r"(a[1]), "r"(a[2]), "r"(a[3]), "r"(b0), "r"(b1));
}
__device__ __forceinline__ void ldsm_x4(uint32_t* r, uint32_t addr) {
    asm volatile(
        "ldmatrix.sync.aligned.m8n8.x4.shared.b16 {%0,%1,%2,%3}, [%4];"
        : "=r"(r[0]), "=r"(r[1]), "=r"(r[2]), "=r"(r[3]) : "r"(addr));
}
__device__ __forceinline__ void ldsm_x4_t(uint32_t* r, uint32_t addr) {
    asm volatile(
        "ldmatrix.sync.aligned.m8n8.x4.trans.shared.b16 {%0,%1,%2,%3}, [%4];"
        : "=r"(r[0]), "=r"(r[1]), "=r"(r[2]), "=r"(r[3]) : "r"(addr));
}
__device__ __forceinline__ uint32_t pack_h2(float a, float b) {
    __half2 h = __floats2half2_rn(a, b);
    return *(uint32_t*)&h;
}

__device__ __forceinline__ float gelu_exact(float x) {
    return 0.5f * x * (1.0f + erff(x * 0.70710678118654752f));
}

// ---------------- transpose + fp16: src[K][N] fp32 -> dst[N][K] fp16 ----------------
__global__ __launch_bounds__(256) void transp_half3(
    const float* __restrict__ s0, const float* __restrict__ s1,
    const float* __restrict__ s2, __half* __restrict__ dst, int K, int N)
{
    __shared__ float t[32][33];
    const float* src = (blockIdx.z == 0) ? s0 : (blockIdx.z == 1) ? s1 : s2;
    __half* d = dst + (size_t)blockIdx.z * K * N;
    int kb = blockIdx.y * 32, nb = blockIdx.x * 32;
    int x = threadIdx.x & 31, y = threadIdx.x >> 5;
    #pragma unroll
    for (int i = 0; i < 32; i += 8)
        t[y + i][x] = src[(size_t)(kb + y + i) * N + nb + x];
    __syncthreads();
    #pragma unroll
    for (int i = 0; i < 32; i += 8)
        d[(size_t)(nb + y + i) * K + kb + x] = __float2half_rn(t[x][y + i]);
}

__global__ void pack_bias_kernel(
    const float* __restrict__ bq, const float* __restrict__ bk,
    const float* __restrict__ bv, float* __restrict__ dst)
{
    int tid = threadIdx.x;
    int s = tid >> 8, n4 = tid & 255;
    const float* srcs[3] = {bq, bk, bv};
    ((float4*)dst)[s * 256 + n4] = ((const float4*)srcs[s])[n4];
}

// ---------------- LayerNorm: fp32 in, fp16 out ----------------
__global__ __launch_bounds__(256) void ln_kernel(
    const float* __restrict__ x, const float* __restrict__ g,
    const float* __restrict__ b, __half* __restrict__ out)
{
    int row = blockIdx.x;
    int tid = threadIdx.x;
    const float4* xr = (const float4*)(x + (size_t)row * D_MODEL);
    float4 v = xr[tid];
    float s  = v.x + v.y + v.z + v.w;
    float s2 = v.x*v.x + v.y*v.y + v.z*v.z + v.w*v.w;

    __shared__ float red[18];
    #pragma unroll
    for (int off = 16; off > 0; off >>= 1) {
        s  += __shfl_xor_sync(0xffffffffu, s,  off);
        s2 += __shfl_xor_sync(0xffffffffu, s2, off);
    }
    int w = tid >> 5, lane = tid & 31;
    if (lane == 0) { red[w] = s; red[8 + w] = s2; }
    __syncthreads();
    if (tid == 0) {
        float a = 0.f, c2 = 0.f;
        #pragma unroll
        for (int i = 0; i < 8; i++) { a += red[i]; c2 += red[8 + i]; }
        red[16] = a; red[17] = c2;
    }
    __syncthreads();
    float mu  = red[16] * (1.0f / D_MODEL);
    float var = red[17] * (1.0f / D_MODEL) - mu * mu;
    float inv = rsqrtf(var + 1e-5f);

    float4 gg = ((const float4*)g)[tid];
    float4 bb = ((const float4*)b)[tid];
    __half2 o0 = __floats2half2_rn((v.x - mu) * inv * gg.x + bb.x,
                                   (v.y - mu) * inv * gg.y + bb.y);
    __half2 o1 = __floats2half2_rn((v.z - mu) * inv * gg.z + bb.z,
                                   (v.w - mu) * inv * gg.w + bb.w);
    __half2* op = (__half2*)(out + (size_t)row * D_MODEL) + tid * 2;
    op[0] = o0; op[1] = o1;
}

// ---------------- fp16 tensor-core GEMM, cp.async double-buffered ----------------
#define AST2 72
#define TILE2 (128*AST2)
#define GEMM_SMEM (2*2*TILE2*2)

__global__ __launch_bounds__(256, 2) void gemm_f16(
    const __half* __restrict__ A, const __half* __restrict__ Wt,
    const float* __restrict__ bias, const float* __restrict__ resid,
    void* __restrict__ Cv, int M, int N, int K, int act, int omode)
{
    extern __shared__ __half hsm[];
    __half* As = hsm;
    __half* Bs = hsm + 2 * TILE2;

    int tid  = threadIdx.x;
    int wid  = tid >> 5, lane = tid & 31;
    int warp_m = wid >> 2;
    int warp_n = wid & 3;
    int gid = lane >> 2, tig = lane & 3;
    int mb = blockIdx.y * 128, nb = blockIdx.x * 128;

    float acc[4][4][4];
    #pragma unroll
    for (int mt = 0; mt < 4; mt++)
        #pragma unroll
        for (int nt = 0; nt < 4; nt++)
            #pragma unroll
            for (int r = 0; r < 4; r++) acc[mt][nt][r] = 0.f;

    const __half* a_gp[4];
    const __half* b_gp[4];
    uint32_t a_dst[4], b_dst[4];
    #pragma unroll
    for (int i = 0; i < 4; i++) {
        int idx = tid + i * 256;
        int r = idx >> 3, g = idx & 7;
        a_gp[i] = A  + (size_t)(mb + r) * K + g * 8;
        b_gp[i] = Wt + (size_t)(nb + r) * K + g * 8;
        a_dst[i] = (uint32_t)__cvta_generic_to_shared(&As[r * AST2 + g * 8]);
        b_dst[i] = (uint32_t)__cvta_generic_to_shared(&Bs[r * AST2 + g * 8]);
    }

    int lm_row = ((lane >> 3) & 1) * 8 + (lane & 7);
    int lm_k8  = (lane >> 4);
    uint32_t lm_base[4];
    #pragma unroll
    for (int mt = 0; mt < 4; mt++) {
        int row = warp_m * 64 + mt * 16 + lm_row;
        lm_base[mt] = (uint32_t)__cvta_generic_to_shared(
            &As[row * AST2 + lm_k8 * 8]);
    }
    int n0 = warp_n * 32 + gid;

    #pragma unroll
    for (int i = 0; i < 4; i++) cp16(a_dst[i], a_gp[i]);
    #pragma unroll
    for (int i = 0; i < 4; i++) cp16(b_dst[i], b_gp[i]);
    CP_COMMIT();

    int nch = K >> 6;
    int buf = 0;
    for (int c = 0; c < nch; c++) {
        CP_WAIT(0);
        __syncthreads();
        if (c + 1 < nch) {
            int nbo = buf ^ 1;
            int koff = (c + 1) * 64;
            #pragma unroll
            for (int i = 0; i < 4; i++)
                cp16(a_dst[i] + nbo * TILE2 * 2, a_gp[i] + koff);
            #pragma unroll
            for (int i = 0; i < 4; i++)
                cp16(b_dst[i] + nbo * TILE2 * 2, b_gp[i] + koff);
            CP_COMMIT();
        }

        const uint32_t* Bw = (const uint32_t*)(Bs + buf * TILE2);
        uint32_t abuf = buf * TILE2 * 2;
        #pragma unroll
        for (int ks = 0; ks < 4; ks++) {
            uint32_t af[4][4];
            #pragma unroll
            for (int mt = 0; mt < 4; mt++) {
                uint32_t saddr = lm_base[mt] + abuf + ks * 32;
                ldsm_x4(af[mt], saddr);
            }
            uint32_t bf[4][2];
            #pragma unroll
            for (int nt = 0; nt < 4; nt++) {
                int widx = (n0 + nt * 8) * 36 + ks * 8 + tig;
                bf[nt][0] = Bw[widx];
                bf[nt][1] = Bw[widx + 4];
            }
            #pragma unroll
            for (int mt = 0; mt < 4; mt++)
                #pragma unroll
                for (int nt = 0; nt < 4; nt++)
                    mma_f16(acc[mt][nt], af[mt], bf[nt][0], bf[nt][1]);
        }
        buf ^= 1;
    }

    #pragma unroll
    for (int mt = 0; mt < 4; mt++) {
        int r0 = mb + warp_m * 64 + mt * 16 + gid;
        int r1 = r0 + 8;
        #pragma unroll
        for (int nt = 0; nt < 4; nt++) {
            int cc = nb + warp_n * 32 + nt * 8 + tig * 2;
            float b0 = bias[cc], b1 = bias[cc + 1];
            float v00 = acc[mt][nt][0] + b0, v01 = acc[mt][nt][1] + b1;
            float v10 = acc[mt][nt][2] + b0, v11 = acc[mt][nt][3] + b1;
            if (act == 1) {
                v00 = gelu_exact(v00); v01 = gelu_exact(v01);
                v10 = gelu_exact(v10); v11 = gelu_exact(v11);
            }
            size_t p0 = (size_t)r0 * N + cc;
            size_t p1 = (size_t)r1 * N + cc;
            if (resid) {
                float2 q0 = *(const float2*)(resid + p0);
                float2 q1 = *(const float2*)(resid + p1);
                v00 += q0.x; v01 += q0.y; v10 += q1.x; v11 += q1.y;
            }
            if (omode == 2) {
                __half* Ch = (__half*)Cv;
                *(__half2*)(Ch + p0) = __floats2half2_rn(v00, v01);
                *(__half2*)(Ch + p1) = __floats2half2_rn(v10, v11);
            } else {
                float* Cf = (float*)Cv;
                *(float2*)(Cf + p0) = make_float2(v00, v01);
                *(float2*)(Cf + p1) = make_float2(v10, v11);
            }
        }
    }
}

// ---------------- forget gate (fp16 h input) ----------------
__global__ __launch_bounds__(256) void fgate_kernel(
    const __half* __restrict__ h, const float* __restrict__ wf,
    const float* __restrict__ bf, float* __restrict__ logf)
{
    int t   = blockIdx.x;
    int tid = threadIdx.x;
    int hd  = tid >> 4;
    int ln  = tid & 15;
    const __half* hr = h + (size_t)t * D_MODEL;
    float s = 0.f;
    #pragma unroll 8
    for (int k = ln; k < D_MODEL; k += 16)
        s = fmaf(__half2float(hr[k]), wf[(size_t)k * N_HEADS + hd], s);
    #pragma unroll
    for (int off = 8; off > 0; off >>= 1)
        s += __shfl_xor_sync(0xffffffffu, s, off);
    if (ln == 0) {
        float z = s + bf[hd];
        float ls = (z >= 0.f) ? -log1pf(expf(-z)) : (z - log1pf(expf(z)));
        logf[(size_t)t * N_HEADS + hd] = ls;
    }
}

// ---------------- cumsum per (b,h) ----------------
__global__ __launch_bounds__(256) void cumsum_kernel(float* __restrict__ c)
{
    int bh = blockIdx.x;
    int b  = bh >> 4, h = bh & 15;
    int tid = threadIdx.x;
    const int CHUNK = SEQ / 256;
    float vals[CHUNK];
    float run = 0.f;
    size_t base = (size_t)b * SEQ * N_HEADS + h;
    #pragma unroll
    for (int u = 0; u < CHUNK; u++) {
        run += c[base + (size_t)(tid * CHUNK + u) * N_HEADS];
        vals[u] = run;
    }
    __shared__ float tot[256];
    tot[tid] = run;
    __syncthreads();
    for (int off = 1; off < 256; off <<= 1) {
        float t = (tid >= off) ? tot[tid - off] : 0.f;
        __syncthreads();
        tot[tid] += t;
        __syncthreads();
    }
    float offs = tot[tid] - run;
    #pragma unroll
    for (int u = 0; u < CHUNK; u++)
        c[base + (size_t)(tid * CHUNK + u) * N_HEADS] = vals[u] + offs;
}

// ---------------- fp16 flash attention: paired tiles, register-resident P ----------------
#define HTILE (64*72)
#define ATTN_SMEM (5*HTILE*2 + 2*64*4)

__global__ __launch_bounds__(128) void attn_f16(
    const __half* __restrict__ QKV, const float* __restrict__ Cdec,
    __half* __restrict__ Out)
{
    extern __shared__ __half hsm[];
    __half* Ksb = hsm;
    __half* Vsb = hsm + 2 * HTILE;
    __half* Ps  = hsm + 4 * HTILE;      // Q staging only
    float*  csb = (float*)(hsm + 5 * HTILE);

    int h = blockIdx.y, b = blockIdx.z;
    int tid = threadIdx.x, wid = tid >> 5, lane = tid & 31;
    int gid = lane >> 2, tig = lane & 3;
    size_t rowbase = (size_t)b * SEQ;
    int r0 = wid * 16 + gid;

    uint32_t Ps_u = (uint32_t)__cvta_generic_to_shared(Ps);
    uint32_t Ks_u = (uint32_t)__cvta_generic_to_shared(Ksb);
    uint32_t Vs_u = (uint32_t)__cvta_generic_to_shared(Vsb);

    const __half* kg0 = QKV + rowbase * D3 + D_MODEL + h * D_HEAD;
    const __half* vg0 = kg0 + D_MODEL;

    int lm_row = ((lane >> 3) & 1) * 8 + (lane & 7);
    int lm_k8  = (lane >> 4);
    uint32_t qp_base = Ps_u + (wid * 16 + lm_row) * 144 + lm_k8 * 16;
    int v_row = lm_row;
    int v_sel = lm_k8;

    const __half2 qscale = __float2half2_rn(0.125f);
    const int NT = SEQ / 64;
    int qts[2] = { (int)blockIdx.x, NT - 1 - (int)blockIdx.x };

    for (int p = 0; p < 2; p++) {
        int qt = qts[p];
        int qbase = qt * 64;
        __syncthreads();           // smem reuse across pair

        // stage Q
        const __half* qg = QKV + (rowbase + qbase) * D3 + h * D_HEAD;
        #pragma unroll
        for (int i = 0; i < 4; i++) {
            int idx = tid + i * 128;
            int r = idx >> 3, g = idx & 7;
            cp16(Ps_u + r * 144 + g * 16, qg + (size_t)r * D3 + g * 8);
        }
        CP_COMMIT();

        // K/V tile 0
        #pragma unroll
        for (int i = 0; i < 4; i++) {
            int idx = tid + i * 128;
            int r = idx >> 3, g = idx & 7;
            cp16(Ks_u + r * 144 + g * 16, kg0 + (size_t)r * D3 + g * 8);
            cp16(Vs_u + r * 144 + g * 16, vg0 + (size_t)r * D3 + g * 8);
        }
        if (tid < 64)
            csb[tid] = Cdec[(rowbase + tid) * N_HEADS + h];
        CP_COMMIT();

        CP_WAIT(1);
        __syncthreads();

        // hoist Q fragments, pre-scale by 1/8 (exact power of 2)
        uint32_t qf[4][4];
        #pragma unroll
        for (int ks = 0; ks < 4; ks++) {
            ldsm_x4(qf[ks], qp_base + ks * 32);
            #pragma unroll
            for (int r = 0; r < 4; r++) {
                __half2 hv = *(__half2*)&qf[ks][r];
                hv = __hmul2(hv, qscale);
                qf[ks][r] = *(uint32_t*)&hv;
            }
        }

        float oacc[8][4];
        #pragma unroll
        for (int nt = 0; nt < 8; nt++)
            #pragma unroll
            for (int r = 0; r < 4; r++) oacc[nt][r] = 0.f;
        float mrow[2] = {-1e30f, -1e30f};
        float lrow[2] = {0.f, 0.f};

        int buf = 0;
        for (int kt = 0; kt <= qt; kt++) {
            CP_WAIT(0);
            __syncthreads();

            if (kt < qt) {
                int nb_ = buf ^ 1;
                const __half* kg = kg0 + (size_t)(kt + 1) * 64 * D3;
                const __half* vg = vg0 + (size_t)(kt + 1) * 64 * D3;
                uint32_t Kd = Ks_u + nb_ * HTILE * 2;
                uint32_t Vd = Vs_u + nb_ * HTILE * 2;
                #pragma unroll
                for (int i = 0; i < 4; i++) {
                    int idx = tid + i * 128;
                    int r = idx >> 3, g = idx & 7;
                    cp16(Kd + r * 144 + g * 16, kg + (size_t)r * D3 + g * 8);
                    cp16(Vd + r * 144 + g * 16, vg + (size_t)r * D3 + g * 8);
                }
                CP_COMMIT();
                if (tid < 64)
                    csb[nb_ * 64 + tid] =
                        Cdec[(rowbase + (kt + 1) * 64 + tid) * N_HEADS + h];
            }

            const uint32_t* Kw = (const uint32_t*)(Ksb + buf * HTILE);
            uint32_t Vs_b = Vs_u + buf * HTILE * 2;
            const float* cs = csb + buf * 64;

            // S = (Q/8) K^T
            float s[8][4];
            #pragma unroll
            for (int nt = 0; nt < 8; nt++)
                #pragma unroll
                for (int r = 0; r < 4; r++) s[nt][r] = 0.f;
            #pragma unroll
            for (int ks = 0; ks < 4; ks++) {
                #pragma unroll
                for (int nt = 0; nt < 8; nt++) {
                    int widx = (nt * 8 + gid) * 36 + ks * 8 + tig;
                    mma_f16(s[nt], qf[ks], Kw[widx], Kw[widx + 4]);
                }
            }

            // decay + mask + online softmax
            #pragma unroll
            for (int rr = 0; rr < 2; rr++) {
                int rloc = r0 + rr * 8;
                float mx = -1e30f;
                #pragma unroll
                for (int nt = 0; nt < 8; nt++) {
                    #pragma unroll
                    for (int q = 0; q < 2; q++) {
                        int col = nt * 8 + tig * 2 + q;
                        float val = s[nt][rr * 2 + q] - cs[col];
                        if (kt == qt && col > rloc) val = -1e30f;
                        s[nt][rr * 2 + q] = val;
                        mx = fmaxf(mx, val);
                    }
                }
                mx = fmaxf(mx, __shfl_xor_sync(0xffffffffu, mx, 1));
                mx = fmaxf(mx, __shfl_xor_sync(0xffffffffu, mx, 2));
                float mnew = fmaxf(mrow[rr], mx);
                float sf = __expf(mrow[rr] - mnew);
                mrow[rr] = mnew;
                float rs = 0.f;
                #pragma unroll
                for (int nt = 0; nt < 8; nt++) {
                    #pragma unroll
                    for (int q = 0; q < 2; q++) {
                        float pv = __expf(s[nt][rr * 2 + q] - mnew);
                        s[nt][rr * 2 + q] = pv;
                        rs += pv;
                    }
                }
                rs += __shfl_xor_sync(0xffffffffu, rs, 1);
                rs += __shfl_xor_sync(0xffffffffu, rs, 2);
                lrow[rr] = lrow[rr] * sf + rs;
                #pragma unroll
                for (int nt = 0; nt < 8; nt++) {
                    oacc[nt][rr * 2]     *= sf;
                    oacc[nt][rr * 2 + 1] *= sf;
                }
            }

            // O += P @ V : P A-fragments packed directly from S registers
            #pragma unroll
            for (int ks = 0; ks < 4; ks++) {
                uint32_t pf[4];
                pf[0] = pack_h2(s[2 * ks][0],     s[2 * ks][1]);
                pf[1] = pack_h2(s[2 * ks][2],     s[2 * ks][3]);
                pf[2] = pack_h2(s[2 * ks + 1][0], s[2 * ks + 1][1]);
                pf[3] = pack_h2(s[2 * ks + 1][2], s[2 * ks + 1][3]);
                #pragma unroll
                for (int j = 0; j < 4; j++) {
                    uint32_t vf[4];
                    ldsm_x4_t(vf, Vs_b + (ks * 16 + v_row) * 144 + (2 * j + v_sel) * 16);
                    mma_f16(oacc[2 * j],     pf, vf[0], vf[1]);
                    mma_f16(oacc[2 * j + 1], pf, vf[2], vf[3]);
                }
            }
            buf ^= 1;
        }

        float inv0 = 1.0f / lrow[0], inv1 = 1.0f / lrow[1];
        size_t row0 = rowbase + qbase + r0;
        #pragma unroll
        for (int nt = 0; nt < 8; nt++) {
            int col = h * D_HEAD + nt * 8 + tig * 2;
            *(__half2*)(Out + row0 * D_MODEL + col) =
                __floats2half2_rn(oacc[nt][0] * inv0, oacc[nt][1] * inv0);
            *(__half2*)(Out + (row0 + 8) * D_MODEL + col) =
                __floats2half2_rn(oacc[nt][2] * inv1, oacc[nt][3] * inv1);
        }
    }
}

// ---------------- launcher with capture fork-join ----------------
extern "C" void kernel_launch(void* const* d_in, const int* in_sizes, int n_in,
                              void* d_out, int out_size)
{
    const float* x    = (const float*)d_in[0];
    const float* ln1g = (const float*)d_in[1];
    const float* ln1b = (const float*)d_in[2];
    const float* wq   = (const float*)d_in[3];
    const float* bq   = (const float*)d_in[4];
    const float* wk   = (const float*)d_in[5];
    const float* bk   = (const float*)d_in[6];
    const float* wv   = (const float*)d_in[7];
    const float* bv   = (const float*)d_in[8];
    const float* wo   = (const float*)d_in[9];
    const float* bo   = (const float*)d_in[10];
    const float* wf   = (const float*)d_in[11];
    const float* bf   = (const float*)d_in[12];
    const float* ln2g = (const float*)d_in[13];
    const float* ln2b = (const float*)d_in[14];
    const float* w1   = (const float*)d_in[15];
    const float* b1   = (const float*)d_in[16];
    const float* w2   = (const float*)d_in[17];
    const float* b2   = (const float*)d_in[18];
    float* out = (float*)d_out;

    __half *h, *qkv, *ctx, *h2, *ff, *rwqkv, *rwo, *rw1, *rw2;
    float *c, *x1, *rbqkv;
    cudaGetSymbolAddress((void**)&h,    g_h);
    cudaGetSymbolAddress((void**)&qkv,  g_qkv);
    cudaGetSymbolAddress((void**)&c,    g_c);
    cudaGetSymbolAddress((void**)&ctx,  g_ctx);
    cudaGetSymbolAddress((void**)&x1,   g_x1);
    cudaGetSymbolAddress((void**)&h2,   g_h2);
    cudaGetSymbolAddress((void**)&ff,   g_ff);
    cudaGetSymbolAddress((void**)&rwqkv,g_wqkvT);
    cudaGetSymbolAddress((void**)&rbqkv,g_bqkv);
    cudaGetSymbolAddress((void**)&rwo,  g_woT);
    cudaGetSymbolAddress((void**)&rw1,  g_w1T);
    cudaGetSymbolAddress((void**)&rw2,  g_w2T);

    static cudaStream_t s2 = nullptr, s3 = nullptr;
    static cudaEvent_t evFork, evQkvW, evLn1, evGate, evBigW;
    static int inited = 0;
    if (!inited) {
        cudaFuncSetAttribute(gemm_f16, cudaFuncAttributeMaxDynamicSharedMemorySize, GEMM_SMEM);
        cudaFuncSetAttribute(attn_f16, cudaFuncAttributeMaxDynamicSharedMemorySize, ATTN_SMEM);
        cudaStreamCreateWithFlags(&s2, cudaStreamNonBlocking);
        cudaStreamCreateWithFlags(&s3, cudaStreamNonBlocking);
        cudaEventCreateWithFlags(&evFork,  cudaEventDisableTiming);
        cudaEventCreateWithFlags(&evQkvW,  cudaEventDisableTiming);
        cudaEventCreateWithFlags(&evLn1,   cudaEventDisableTiming);
        cudaEventCreateWithFlags(&evGate,  cudaEventDisableTiming);
        cudaEventCreateWithFlags(&evBigW,  cudaEventDisableTiming);
        inited = 1;
    }

    cudaEventRecord(evFork, 0);
    cudaStreamWaitEvent(s2, evFork, 0);
    cudaStreamWaitEvent(s3, evFork, 0);

    // s2: QKV weight pack
    transp_half3<<<dim3(32, 32, 3), 256, 0, s2>>>(wq, wk, wv, rwqkv, D_MODEL, D_MODEL);
    pack_bias_kernel<<<1, 768, 0, s2>>>(bq, bk, bv, rbqkv);
    cudaEventRecord(evQkvW, s2);

    // s3: wo/w1/w2 packs
    transp_half3<<<dim3(32, 32),  256, 0, s3>>>(wo, wo, wo, rwo, D_MODEL, D_MODEL);
    transp_half3<<<dim3(128, 32), 256, 0, s3>>>(w1, w1, w1, rw1, D_MODEL, D_FF);
    transp_half3<<<dim3(32, 128), 256, 0, s3>>>(w2, w2, w2, rw2, D_FF, D_MODEL);
    cudaEventRecord(evBigW, s3);

    // main: LN1
    ln_kernel<<<NTOK, 256>>>(x, ln1g, ln1b, h);
    cudaEventRecord(evLn1, 0);

    // s2: forget gate + cumsum (concurrent with QKV gemm)
    cudaStreamWaitEvent(s2, evLn1, 0);
    fgate_kernel<<<NTOK, 256, 0, s2>>>(h, wf, bf, c);
    cumsum_kernel<<<BATCH * N_HEADS, 256, 0, s2>>>(c);
    cudaEventRecord(evGate, s2);

    // main: QKV gemm
    cudaStreamWaitEvent(0, evQkvW, 0);
    gemm_f16<<<dim3(D3/128, NTOK/128), 256, GEMM_SMEM>>>(h, rwqkv, rbqkv, nullptr, qkv, NTOK, D3, D_MODEL, 0, 2);

    // main: attention (paired causal tiles, register-resident P)
    cudaStreamWaitEvent(0, evGate, 0);
    attn_f16<<<dim3(SEQ/128, N_HEADS, BATCH), 128, ATTN_SMEM>>>(qkv, c, ctx);

    // main: output proj + residual
    cudaStreamWaitEvent(0, evBigW, 0);
    gemm_f16<<<dim3(D_MODEL/128, NTOK/128), 256, GEMM_SMEM>>>(ctx, rwo, bo, x, x1, NTOK, D_MODEL, D_MODEL, 0, 0);
    // LN2
    ln_kernel<<<NTOK, 256>>>(x1, ln2g, ln2b, h2);
    // FF up + GELU
    gemm_f16<<<dim3(D_FF/128, NTOK/128), 256, GEMM_SMEM>>>(h2, rw1, b1, nullptr, ff, NTOK, D_FF, D_MODEL, 1, 2);
    // FF down + residual -> out
    gemm_f16<<<dim3(D_MODEL/128, NTOK/128), 256, GEMM_SMEM>>>(ff, rw2, b2, x1, out, NTOK, D_MODEL, D_FF, 0, 0);
}

// round 14
// speedup vs baseline: 1.9027x; 1.0526x over previous
#include <cuda_runtime.h>
#include <cuda_fp16.h>
#include <math.h>
#include <stdint.h>

#define D_MODEL 1024
#define N_HEADS 16
#define D_HEAD  64
#define D_FF    4096
#define BATCH   2
#define SEQ     2048
#define NTOK    (BATCH*SEQ)
#define D3      (3*D_MODEL)

// ---------------- scratch (no cudaMalloc allowed) ----------------
__device__ __half g_h   [NTOK*D_MODEL];
__device__ __half g_qkv [NTOK*D3];
__device__ float  g_c   [NTOK*N_HEADS];
__device__ __half g_ctx [NTOK*D_MODEL];
__device__ float  g_x1  [NTOK*D_MODEL];
__device__ __half g_h2  [NTOK*D_MODEL];
__device__ __half g_ff  [NTOK*D_FF];
// transposed fp16 weights, [N][K]
__device__ __half g_wqkvT[D3*D_MODEL];
__device__ float  g_bqkv [D3];
__device__ __half g_woT  [D_MODEL*D_MODEL];
__device__ __half g_w1T  [D_FF*D_MODEL];
__device__ __half g_w2T  [D_MODEL*D_FF];

__device__ __forceinline__ void cp16(uint32_t dst, const void* src) {
    asm volatile("cp.async.cg.shared.global [%0], [%1], 16;" :: "r"(dst), "l"(src));
}
#define CP_COMMIT() asm volatile("cp.async.commit_group;")
#define CP_WAIT(n)  asm volatile("cp.async.wait_group %0;" :: "n"(n))

__device__ __forceinline__ void mma_f16(float* c, const uint32_t* a,
                                        uint32_t b0, uint32_t b1) {
    asm volatile(
        "mma.sync.aligned.m16n8k16.row.col.f32.f16.f16.f32 "
        "{%0,%1,%2,%3}, {%4,%5,%6,%7}, {%8,%9}, {%0,%1,%2,%3};"
        : "+f"(c[0]), "+f"(c[1]), "+f"(c[2]), "+f"(c[3])
        : "r"(a[0]), "r"(a[1]), "r"(a[2]), "r"(a[3]), "r"(b0), "r"(b1));
}
__device__ __forceinline__ void ldsm_x4(uint32_t* r, uint32_t addr) {
    asm volatile(
        "ldmatrix.sync.aligned.m8n8.x4.shared.b16 {%0,%1,%2,%3}, [%4];"
        : "=r"(r[0]), "=r"(r[1]), "=r"(r[2]), "=r"(r[3]) : "r"(addr));
}
__device__ __forceinline__ void ldsm_x4_t(uint32_t* r, uint32_t addr) {
    asm volatile(
        "ldmatrix.sync.aligned.m8n8.x4.trans.shared.b16 {%0,%1,%2,%3}, [%4];"
        : "=r"(r[0]), "=r"(r[1]), "=r"(r[2]), "=r"(r[3]) : "r"(addr));
}
__device__ __forceinline__ uint32_t pack_h2(float a, float b) {
    __half2 h = __floats2half2_rn(a, b);
    return *(uint32_t*)&h;
}

__device__ __forceinline__ float gelu_exact(float x) {
    return 0.5f * x * (1.0f + erff(x * 0.70710678118654752f));
}

// ---------------- transpose + fp16: src[K][N] fp32 -> dst[N][K] fp16 ----------------
__global__ __launch_bounds__(256) void transp_half3(
    const float* __restrict__ s0, const float* __restrict__ s1,
    const float* __restrict__ s2, __half* __restrict__ dst, int K, int N)
{
    __shared__ float t[32][33];
    const float* src = (blockIdx.z == 0) ? s0 : (blockIdx.z == 1) ? s1 : s2;
    __half* d = dst + (size_t)blockIdx.z * K * N;
    int kb = blockIdx.y * 32, nb = blockIdx.x * 32;
    int x = threadIdx.x & 31, y = threadIdx.x >> 5;
    #pragma unroll
    for (int i = 0; i < 32; i += 8)
        t[y + i][x] = src[(size_t)(kb + y + i) * N + nb + x];
    __syncthreads();
    #pragma unroll
    for (int i = 0; i < 32; i += 8)
        d[(size_t)(nb + y + i) * K + kb + x] = __float2half_rn(t[x][y + i]);
}

__global__ void pack_bias_kernel(
    const float* __restrict__ bq, const float* __restrict__ bk,
    const float* __restrict__ bv, float* __restrict__ dst)
{
    int tid = threadIdx.x;
    int s = tid >> 8, n4 = tid & 255;
    const float* srcs[3] = {bq, bk, bv};
    ((float4*)dst)[s * 256 + n4] = ((const float4*)srcs[s])[n4];
}

// ---------------- LayerNorm: fp32 in, fp16 out ----------------
__global__ __launch_bounds__(256) void ln_kernel(
    const float* __restrict__ x, const float* __restrict__ g,
    const float* __restrict__ b, __half* __restrict__ out)
{
    int row = blockIdx.x;
    int tid = threadIdx.x;
    const float4* xr = (const float4*)(x + (size_t)row * D_MODEL);
    float4 v = xr[tid];
    float s  = v.x + v.y + v.z + v.w;
    float s2 = v.x*v.x + v.y*v.y + v.z*v.z + v.w*v.w;

    __shared__ float red[18];
    #pragma unroll
    for (int off = 16; off > 0; off >>= 1) {
        s  += __shfl_xor_sync(0xffffffffu, s,  off);
        s2 += __shfl_xor_sync(0xffffffffu, s2, off);
    }
    int w = tid >> 5, lane = tid & 31;
    if (lane == 0) { red[w] = s; red[8 + w] = s2; }
    __syncthreads();
    if (tid == 0) {
        float a = 0.f, c2 = 0.f;
        #pragma unroll
        for (int i = 0; i < 8; i++) { a += red[i]; c2 += red[8 + i]; }
        red[16] = a; red[17] = c2;
    }
    __syncthreads();
    float mu  = red[16] * (1.0f / D_MODEL);
    float var = red[17] * (1.0f / D_MODEL) - mu * mu;
    float inv = rsqrtf(var + 1e-5f);

    float4 gg = ((const float4*)g)[tid];
    float4 bb = ((const float4*)b)[tid];
    __half2 o0 = __floats2half2_rn((v.x - mu) * inv * gg.x + bb.x,
                                   (v.y - mu) * inv * gg.y + bb.y);
    __half2 o1 = __floats2half2_rn((v.z - mu) * inv * gg.z + bb.z,
                                   (v.w - mu) * inv * gg.w + bb.w);
    __half2* op = (__half2*)(out + (size_t)row * D_MODEL) + tid * 2;
    op[0] = o0; op[1] = o1;
}

// ---------------- fp16 tensor-core GEMM, cp.async double-buffered ----------------
#define AST2 72
#define TILE2 (128*AST2)
#define GEMM_SMEM (2*2*TILE2*2)

__global__ __launch_bounds__(256, 2) void gemm_f16(
    const __half* __restrict__ A, const __half* __restrict__ Wt,
    const float* __restrict__ bias, const float* __restrict__ resid,
    void* __restrict__ Cv, int M, int N, int K, int act, int omode)
{
    extern __shared__ __half hsm[];
    __half* As = hsm;
    __half* Bs = hsm + 2 * TILE2;

    int tid  = threadIdx.x;
    int wid  = tid >> 5, lane = tid & 31;
    int warp_m = wid >> 2;
    int warp_n = wid & 3;
    int gid = lane >> 2, tig = lane & 3;
    int mb = blockIdx.y * 128, nb = blockIdx.x * 128;

    float acc[4][4][4];
    #pragma unroll
    for (int mt = 0; mt < 4; mt++)
        #pragma unroll
        for (int nt = 0; nt < 4; nt++)
            #pragma unroll
            for (int r = 0; r < 4; r++) acc[mt][nt][r] = 0.f;

    const __half* a_gp[4];
    const __half* b_gp[4];
    uint32_t a_dst[4], b_dst[4];
    #pragma unroll
    for (int i = 0; i < 4; i++) {
        int idx = tid + i * 256;
        int r = idx >> 3, g = idx & 7;
        a_gp[i] = A  + (size_t)(mb + r) * K + g * 8;
        b_gp[i] = Wt + (size_t)(nb + r) * K + g * 8;
        a_dst[i] = (uint32_t)__cvta_generic_to_shared(&As[r * AST2 + g * 8]);
        b_dst[i] = (uint32_t)__cvta_generic_to_shared(&Bs[r * AST2 + g * 8]);
    }

    int lm_row = ((lane >> 3) & 1) * 8 + (lane & 7);
    int lm_k8  = (lane >> 4);
    uint32_t lm_base[4];
    #pragma unroll
    for (int mt = 0; mt < 4; mt++) {
        int row = warp_m * 64 + mt * 16 + lm_row;
        lm_base[mt] = (uint32_t)__cvta_generic_to_shared(
            &As[row * AST2 + lm_k8 * 8]);
    }
    int bl_row = (lane & 7) + ((lane >> 4) << 3);
    int bl_k16 = (lane >> 3) & 1;
    uint32_t bb_base = (uint32_t)__cvta_generic_to_shared(
        &Bs[(warp_n * 32 + bl_row) * AST2 + bl_k16 * 8]);

    #pragma unroll
    for (int i = 0; i < 4; i++) cp16(a_dst[i], a_gp[i]);
    #pragma unroll
    for (int i = 0; i < 4; i++) cp16(b_dst[i], b_gp[i]);
    CP_COMMIT();

    int nch = K >> 6;
    int buf = 0;
    for (int c = 0; c < nch; c++) {
        CP_WAIT(0);
        __syncthreads();
        if (c + 1 < nch) {
            int nbo = buf ^ 1;
            int koff = (c + 1) * 64;
            #pragma unroll
            for (int i = 0; i < 4; i++)
                cp16(a_dst[i] + nbo * TILE2 * 2, a_gp[i] + koff);
            #pragma unroll
            for (int i = 0; i < 4; i++)
                cp16(b_dst[i] + nbo * TILE2 * 2, b_gp[i] + koff);
            CP_COMMIT();
        }

        uint32_t abuf = buf * TILE2 * 2;
        #pragma unroll
        for (int ks = 0; ks < 4; ks++) {
            uint32_t af[4][4];
            #pragma unroll
            for (int mt = 0; mt < 4; mt++)
                ldsm_x4(af[mt], lm_base[mt] + abuf + ks * 32);
            uint32_t bf4[2][4];
            #pragma unroll
            for (int pr = 0; pr < 2; pr++)
                ldsm_x4(bf4[pr], bb_base + abuf + pr * 16 * 144 + ks * 32);
            #pragma unroll
            for (int mt = 0; mt < 4; mt++) {
                mma_f16(acc[mt][0], af[mt], bf4[0][0], bf4[0][1]);
                mma_f16(acc[mt][1], af[mt], bf4[0][2], bf4[0][3]);
                mma_f16(acc[mt][2], af[mt], bf4[1][0], bf4[1][1]);
                mma_f16(acc[mt][3], af[mt], bf4[1][2], bf4[1][3]);
            }
        }
        buf ^= 1;
    }

    #pragma unroll
    for (int mt = 0; mt < 4; mt++) {
        int r0 = mb + warp_m * 64 + mt * 16 + gid;
        int r1 = r0 + 8;
        #pragma unroll
        for (int nt = 0; nt < 4; nt++) {
            int cc = nb + warp_n * 32 + nt * 8 + tig * 2;
            float b0 = bias[cc], b1 = bias[cc + 1];
            float v00 = acc[mt][nt][0] + b0, v01 = acc[mt][nt][1] + b1;
            float v10 = acc[mt][nt][2] + b0, v11 = acc[mt][nt][3] + b1;
            if (act == 1) {
                v00 = gelu_exact(v00); v01 = gelu_exact(v01);
                v10 = gelu_exact(v10); v11 = gelu_exact(v11);
            }
            size_t p0 = (size_t)r0 * N + cc;
            size_t p1 = (size_t)r1 * N + cc;
            if (resid) {
                float2 q0 = *(const float2*)(resid + p0);
                float2 q1 = *(const float2*)(resid + p1);
                v00 += q0.x; v01 += q0.y; v10 += q1.x; v11 += q1.y;
            }
            if (omode == 2) {
                __half* Ch = (__half*)Cv;
                *(__half2*)(Ch + p0) = __floats2half2_rn(v00, v01);
                *(__half2*)(Ch + p1) = __floats2half2_rn(v10, v11);
            } else {
                float* Cf = (float*)Cv;
                *(float2*)(Cf + p0) = make_float2(v00, v01);
                *(float2*)(Cf + p1) = make_float2(v10, v11);
            }
        }
    }
}

// ---------------- forget gate (fp16 h input) ----------------
__global__ __launch_bounds__(256) void fgate_kernel(
    const __half* __restrict__ h, const float* __restrict__ wf,
    const float* __restrict__ bf, float* __restrict__ logf)
{
    int t   = blockIdx.x;
    int tid = threadIdx.x;
    int hd  = tid >> 4;
    int ln  = tid & 15;
    const __half* hr = h + (size_t)t * D_MODEL;
    float s = 0.f;
    #pragma unroll 8
    for (int k = ln; k < D_MODEL; k += 16)
        s = fmaf(__half2float(hr[k]), wf[(size_t)k * N_HEADS + hd], s);
    #pragma unroll
    for (int off = 8; off > 0; off >>= 1)
        s += __shfl_xor_sync(0xffffffffu, s, off);
    if (ln == 0) {
        float z = s + bf[hd];
        float ls = (z >= 0.f) ? -log1pf(expf(-z)) : (z - log1pf(expf(z)));
        logf[(size_t)t * N_HEADS + hd] = ls;
    }
}

// ---------------- cumsum over SEQ per head ----------------
__global__ __launch_bounds__(256) void cumsum_kernel(float* __restrict__ c)
{
    int h = blockIdx.x & 15;
    int tid = threadIdx.x;
    const int CHUNK = SEQ / 256;
    float vals[CHUNK];
    float run = 0.f;
    size_t base = h;
    #pragma unroll
    for (int u = 0; u < CHUNK; u++) {
        run += c[base + (size_t)(tid * CHUNK + u) * N_HEADS];
        vals[u] = run;
    }
    __shared__ float tot[256];
    tot[tid] = run;
    __syncthreads();
    for (int off = 1; off < 256; off <<= 1) {
        float t = (tid >= off) ? tot[tid - off] : 0.f;
        __syncthreads();
        tot[tid] += t;
        __syncthreads();
    }
    float offs = tot[tid] - run;
    #pragma unroll
    for (int u = 0; u < CHUNK; u++)
        c[base + (size_t)(tid * CHUNK + u) * N_HEADS] = vals[u] + offs;
}

// ---------------- fp16 flash attention: paired tiles, register P, ldmatrix K ----
#define HTILE (64*72)
#define ATTN_SMEM (5*HTILE*2 + 2*64*4)

__global__ __launch_bounds__(128) void attn_f16(
    const __half* __restrict__ QKV, const float* __restrict__ Cdec,
    __half* __restrict__ Out)
{
    extern __shared__ __half hsm[];
    __half* Ksb = hsm;
    __half* Vsb = hsm + 2 * HTILE;
    __half* Ps  = hsm + 4 * HTILE;
    float*  csb = (float*)(hsm + 5 * HTILE);

    int h = blockIdx.y;
    int tid = threadIdx.x, wid = tid >> 5, lane = tid & 31;
    int gid = lane >> 2, tig = lane & 3;
    int r0 = wid * 16 + gid;

    uint32_t Ps_u = (uint32_t)__cvta_generic_to_shared(Ps);
    uint32_t Ks_u = (uint32_t)__cvta_generic_to_shared(Ksb);
    uint32_t Vs_u = (uint32_t)__cvta_generic_to_shared(Vsb);

    const __half* kg0 = QKV + D_MODEL + h * D_HEAD;
    const __half* vg0 = kg0 + D_MODEL;

    int lm_row = ((lane >> 3) & 1) * 8 + (lane & 7);
    int lm_k8  = (lane >> 4);
    uint32_t qp_base = Ps_u + (wid * 16 + lm_row) * 144 + lm_k8 * 16;
    int v_row = lm_row;
    int v_sel = lm_k8;
    int bl_row = (lane & 7) + ((lane >> 4) << 3);
    int bl_k16 = (lane >> 3) & 1;
    uint32_t kb_base = Ks_u + bl_row * 144 + bl_k16 * 16;

    const __half2 qscale = __float2half2_rn(0.125f);
    const int NT = SEQ / 64;
    int qts[2] = { (int)blockIdx.x, NT - 1 - (int)blockIdx.x };

    for (int p = 0; p < 2; p++) {
        int qt = qts[p];
        int qbase = qt * 64;
        __syncthreads();

        const __half* qg = QKV + (size_t)qbase * D3 + h * D_HEAD;
        #pragma unroll
        for (int i = 0; i < 4; i++) {
            int idx = tid + i * 128;
            int r = idx >> 3, g = idx & 7;
            cp16(Ps_u + r * 144 + g * 16, qg + (size_t)r * D3 + g * 8);
        }
        CP_COMMIT();

        #pragma unroll
        for (int i = 0; i < 4; i++) {
            int idx = tid + i * 128;
            int r = idx >> 3, g = idx & 7;
            cp16(Ks_u + r * 144 + g * 16, kg0 + (size_t)r * D3 + g * 8);
            cp16(Vs_u + r * 144 + g * 16, vg0 + (size_t)r * D3 + g * 8);
        }
        if (tid < 64)
            csb[tid] = Cdec[(size_t)tid * N_HEADS + h];
        CP_COMMIT();

        CP_WAIT(1);
        __syncthreads();

        uint32_t qf[4][4];
        #pragma unroll
        for (int ks = 0; ks < 4; ks++) {
            ldsm_x4(qf[ks], qp_base + ks * 32);
            #pragma unroll
            for (int r = 0; r < 4; r++) {
                __half2 hv = *(__half2*)&qf[ks][r];
                hv = __hmul2(hv, qscale);
                qf[ks][r] = *(uint32_t*)&hv;
            }
        }

        float oacc[8][4];
        #pragma unroll
        for (int nt = 0; nt < 8; nt++)
            #pragma unroll
            for (int r = 0; r < 4; r++) oacc[nt][r] = 0.f;
        float mrow[2] = {-1e30f, -1e30f};
        float lrow[2] = {0.f, 0.f};

        int buf = 0;
        for (int kt = 0; kt <= qt; kt++) {
            CP_WAIT(0);
            __syncthreads();

            if (kt < qt) {
                int nb_ = buf ^ 1;
                const __half* kg = kg0 + (size_t)(kt + 1) * 64 * D3;
                const __half* vg = vg0 + (size_t)(kt + 1) * 64 * D3;
                uint32_t Kd = Ks_u + nb_ * HTILE * 2;
                uint32_t Vd = Vs_u + nb_ * HTILE * 2;
                #pragma unroll
                for (int i = 0; i < 4; i++) {
                    int idx = tid + i * 128;
                    int r = idx >> 3, g = idx & 7;
                    cp16(Kd + r * 144 + g * 16, kg + (size_t)r * D3 + g * 8);
                    cp16(Vd + r * 144 + g * 16, vg + (size_t)r * D3 + g * 8);
                }
                CP_COMMIT();
                if (tid < 64)
                    csb[nb_ * 64 + tid] =
                        Cdec[(size_t)((kt + 1) * 64 + tid) * N_HEADS + h];
            }

            uint32_t Kbuf = kb_base + buf * HTILE * 2;
            uint32_t Vs_b = Vs_u + buf * HTILE * 2;
            const float* cs = csb + buf * 64;

            float s[8][4];
            #pragma unroll
            for (int nt = 0; nt < 8; nt++)
                #pragma unroll
                for (int r = 0; r < 4; r++) s[nt][r] = 0.f;
            #pragma unroll
            for (int ks = 0; ks < 4; ks++) {
                #pragma unroll
                for (int pr = 0; pr < 4; pr++) {
                    uint32_t kf[4];
                    ldsm_x4(kf, Kbuf + pr * 16 * 144 + ks * 32);
                    mma_f16(s[2 * pr],     qf[ks], kf[0], kf[1]);
                    mma_f16(s[2 * pr + 1], qf[ks], kf[2], kf[3]);
                }
            }

            #pragma unroll
            for (int rr = 0; rr < 2; rr++) {
                int rloc = r0 + rr * 8;
                float mx = -1e30f;
                #pragma unroll
                for (int nt = 0; nt < 8; nt++) {
                    #pragma unroll
                    for (int q = 0; q < 2; q++) {
                        int col = nt * 8 + tig * 2 + q;
                        float val = s[nt][rr * 2 + q] - cs[col];
                        if (kt == qt && col > rloc) val = -1e30f;
                        s[nt][rr * 2 + q] = val;
                        mx = fmaxf(mx, val);
                    }
                }
                mx = fmaxf(mx, __shfl_xor_sync(0xffffffffu, mx, 1));
                mx = fmaxf(mx, __shfl_xor_sync(0xffffffffu, mx, 2));
                float mnew = fmaxf(mrow[rr], mx);
                float sf = __expf(mrow[rr] - mnew);
                mrow[rr] = mnew;
                float rs = 0.f;
                #pragma unroll
                for (int nt = 0; nt < 8; nt++) {
                    #pragma unroll
                    for (int q = 0; q < 2; q++) {
                        float pv = __expf(s[nt][rr * 2 + q] - mnew);
                        s[nt][rr * 2 + q] = pv;
                        rs += pv;
                    }
                }
                rs += __shfl_xor_sync(0xffffffffu, rs, 1);
                rs += __shfl_xor_sync(0xffffffffu, rs, 2);
                lrow[rr] = lrow[rr] * sf + rs;
                #pragma unroll
                for (int nt = 0; nt < 8; nt++) {
                    oacc[nt][rr * 2]     *= sf;
                    oacc[nt][rr * 2 + 1] *= sf;
                }
            }

            #pragma unroll
            for (int ks = 0; ks < 4; ks++) {
                uint32_t pf[4];
                pf[0] = pack_h2(s[2 * ks][0],     s[2 * ks][1]);
                pf[1] = pack_h2(s[2 * ks][2],     s[2 * ks][3]);
                pf[2] = pack_h2(s[2 * ks + 1][0], s[2 * ks + 1][1]);
                pf[3] = pack_h2(s[2 * ks + 1][2], s[2 * ks + 1][3]);
                #pragma unroll
                for (int j = 0; j < 4; j++) {
                    uint32_t vf[4];
                    ldsm_x4_t(vf, Vs_b + (ks * 16 + v_row) * 144 + (2 * j + v_sel) * 16);
                    mma_f16(oacc[2 * j],     pf, vf[0], vf[1]);
                    mma_f16(oacc[2 * j + 1], pf, vf[2], vf[3]);
                }
            }
            buf ^= 1;
        }

        float inv0 = 1.0f / lrow[0], inv1 = 1.0f / lrow[1];
        size_t row0 = (size_t)qbase + r0;
        #pragma unroll
        for (int nt = 0; nt < 8; nt++) {
            int col = h * D_HEAD + nt * 8 + tig * 2;
            *(__half2*)(Out + row0 * D_MODEL + col) =
                __floats2half2_rn(oacc[nt][0] * inv0, oacc[nt][1] * inv0);
            *(__half2*)(Out + (row0 + 8) * D_MODEL + col) =
                __floats2half2_rn(oacc[nt][2] * inv1, oacc[nt][3] * inv1);
        }
    }
}

// ---------------- launcher: dual-batch chains on 3 streams ----------------
extern "C" void kernel_launch(void* const* d_in, const int* in_sizes, int n_in,
                              void* d_out, int out_size)
{
    const float* x    = (const float*)d_in[0];
    const float* ln1g = (const float*)d_in[1];
    const float* ln1b = (const float*)d_in[2];
    const float* wq   = (const float*)d_in[3];
    const float* bq   = (const float*)d_in[4];
    const float* wk   = (const float*)d_in[5];
    const float* bk   = (const float*)d_in[6];
    const float* wv   = (const float*)d_in[7];
    const float* bv   = (const float*)d_in[8];
    const float* wo   = (const float*)d_in[9];
    const float* bo   = (const float*)d_in[10];
    const float* wf   = (const float*)d_in[11];
    const float* bf   = (const float*)d_in[12];
    const float* ln2g = (const float*)d_in[13];
    const float* ln2b = (const float*)d_in[14];
    const float* w1   = (const float*)d_in[15];
    const float* b1   = (const float*)d_in[16];
    const float* w2   = (const float*)d_in[17];
    const float* b2   = (const float*)d_in[18];
    float* out = (float*)d_out;

    __half *h, *qkv, *ctx, *h2, *ff, *rwqkv, *rwo, *rw1, *rw2;
    float *c, *x1, *rbqkv;
    cudaGetSymbolAddress((void**)&h,    g_h);
    cudaGetSymbolAddress((void**)&qkv,  g_qkv);
    cudaGetSymbolAddress((void**)&c,    g_c);
    cudaGetSymbolAddress((void**)&ctx,  g_ctx);
    cudaGetSymbolAddress((void**)&x1,   g_x1);
    cudaGetSymbolAddress((void**)&h2,   g_h2);
    cudaGetSymbolAddress((void**)&ff,   g_ff);
    cudaGetSymbolAddress((void**)&rwqkv,g_wqkvT);
    cudaGetSymbolAddress((void**)&rbqkv,g_bqkv);
    cudaGetSymbolAddress((void**)&rwo,  g_woT);
    cudaGetSymbolAddress((void**)&rw1,  g_w1T);
    cudaGetSymbolAddress((void**)&rw2,  g_w2T);

    static cudaStream_t s2 = nullptr, s3 = nullptr;
    static cudaEvent_t evFork, evQkvW, evBigW, evLn1A, evLn1B, evGateA, evGateB, evDoneB;
    static int inited = 0;
    if (!inited) {
        cudaFuncSetAttribute(gemm_f16, cudaFuncAttributeMaxDynamicSharedMemorySize, GEMM_SMEM);
        cudaFuncSetAttribute(attn_f16, cudaFuncAttributeMaxDynamicSharedMemorySize, ATTN_SMEM);
        cudaStreamCreateWithFlags(&s2, cudaStreamNonBlocking);
        cudaStreamCreateWithFlags(&s3, cudaStreamNonBlocking);
        cudaEventCreateWithFlags(&evFork,  cudaEventDisableTiming);
        cudaEventCreateWithFlags(&evQkvW,  cudaEventDisableTiming);
        cudaEventCreateWithFlags(&evBigW,  cudaEventDisableTiming);
        cudaEventCreateWithFlags(&evLn1A,  cudaEventDisableTiming);
        cudaEventCreateWithFlags(&evLn1B,  cudaEventDisableTiming);
        cudaEventCreateWithFlags(&evGateA, cudaEventDisableTiming);
        cudaEventCreateWithFlags(&evGateB, cudaEventDisableTiming);
        cudaEventCreateWithFlags(&evDoneB, cudaEventDisableTiming);
        inited = 1;
    }

    const int MB = SEQ;                   // rows per batch chain
    const size_t oD = (size_t)MB * D_MODEL;
    const size_t oQ = (size_t)MB * D3;
    const size_t oC = (size_t)MB * N_HEADS;
    const size_t oF = (size_t)MB * D_FF;

    cudaEventRecord(evFork, 0);
    cudaStreamWaitEvent(s2, evFork, 0);
    cudaStreamWaitEvent(s3, evFork, 0);

    // ---- s3: weight packs, then chain B (batch 1) end-to-end ----
    transp_half3<<<dim3(32, 32, 3), 256, 0, s3>>>(wq, wk, wv, rwqkv, D_MODEL, D_MODEL);
    pack_bias_kernel<<<1, 768, 0, s3>>>(bq, bk, bv, rbqkv);
    cudaEventRecord(evQkvW, s3);
    transp_half3<<<dim3(32, 32),  256, 0, s3>>>(wo, wo, wo, rwo, D_MODEL, D_MODEL);
    transp_half3<<<dim3(128, 32), 256, 0, s3>>>(w1, w1, w1, rw1, D_MODEL, D_FF);
    transp_half3<<<dim3(32, 128), 256, 0, s3>>>(w2, w2, w2, rw2, D_FF, D_MODEL);
    cudaEventRecord(evBigW, s3);

    ln_kernel<<<MB, 256, 0, s3>>>(x + oD, ln1g, ln1b, h + oD);
    cudaEventRecord(evLn1B, s3);

    // ---- main: chain A (batch 0) ----
    ln_kernel<<<MB, 256>>>(x, ln1g, ln1b, h);
    cudaEventRecord(evLn1A, 0);

    // ---- s2: gate chains (A, then B) ----
    cudaStreamWaitEvent(s2, evLn1A, 0);
    fgate_kernel<<<MB, 256, 0, s2>>>(h, wf, bf, c);
    cumsum_kernel<<<N_HEADS, 256, 0, s2>>>(c);
    cudaEventRecord(evGateA, s2);
    cudaStreamWaitEvent(s2, evLn1B, 0);
    fgate_kernel<<<MB, 256, 0, s2>>>(h + oD, wf, bf, c + oC);
    cumsum_kernel<<<N_HEADS, 256, 0, s2>>>(c + oC);
    cudaEventRecord(evGateB, s2);

    // ---- QKV ----
    cudaStreamWaitEvent(0, evQkvW, 0);
    gemm_f16<<<dim3(D3/128, MB/128), 256, GEMM_SMEM>>>(h, rwqkv, rbqkv, nullptr, qkv, MB, D3, D_MODEL, 0, 2);
    gemm_f16<<<dim3(D3/128, MB/128), 256, GEMM_SMEM, s3>>>(h + oD, rwqkv, rbqkv, nullptr, qkv + oQ, MB, D3, D_MODEL, 0, 2);

    // ---- attention ----
    cudaStreamWaitEvent(0, evGateA, 0);
    attn_f16<<<dim3(SEQ/128, N_HEADS, 1), 128, ATTN_SMEM>>>(qkv, c, ctx);
    cudaStreamWaitEvent(s3, evGateB, 0);
    attn_f16<<<dim3(SEQ/128, N_HEADS, 1), 128, ATTN_SMEM, s3>>>(qkv + oQ, c + oC, ctx + oD);

    // ---- Wo + residual ----
    cudaStreamWaitEvent(0, evBigW, 0);
    gemm_f16<<<dim3(D_MODEL/128, MB/128), 256, GEMM_SMEM>>>(ctx, rwo, bo, x, x1, MB, D_MODEL, D_MODEL, 0, 0);
    gemm_f16<<<dim3(D_MODEL/128, MB/128), 256, GEMM_SMEM, s3>>>(ctx + oD, rwo, bo, x + oD, x1 + oD, MB, D_MODEL, D_MODEL, 0, 0);

    // ---- LN2 ----
    ln_kernel<<<MB, 256>>>(x1, ln2g, ln2b, h2);
    ln_kernel<<<MB, 256, 0, s3>>>(x1 + oD, ln2g, ln2b, h2 + oD);

    // ---- FF up + GELU ----
    gemm_f16<<<dim3(D_FF/128, MB/128), 256, GEMM_SMEM>>>(h2, rw1, b1, nullptr, ff, MB, D_FF, D_MODEL, 1, 2);
    gemm_f16<<<dim3(D_FF/128, MB/128), 256, GEMM_SMEM, s3>>>(h2 + oD, rw1, b1, nullptr, ff + oF, MB, D_FF, D_MODEL, 1, 2);

    // ---- FF down + residual -> out ----
    gemm_f16<<<dim3(D_MODEL/128, MB/128), 256, GEMM_SMEM>>>(ff, rw2, b2, x1, out, MB, D_MODEL, D_FF, 0, 0);
    gemm_f16<<<dim3(D_MODEL/128, MB/128), 256, GEMM_SMEM, s3>>>(ff + oF, rw2, b2, x1 + oD, out + oD, MB, D_MODEL, D_FF, 0, 0);

    // join chain B back to main
    cudaEventRecord(evDoneB, s3);
    cudaStreamWaitEvent(0, evDoneB, 0);
}